// round 1
// baseline (speedup 1.0000x reference)
#include <cuda_runtime.h>
#include <cuda_bf16.h>
#include <math_constants.h>

// Problem constants
#define BB   2
#define TT   2048
#define DD   1024
#define HH   16
#define HD   64
#define MROWS (BB*TT)        // 4096
// GEMM tiling
#define GBM 64
#define GBN 64
#define GBK 16

// Scratch (device-global: allocation is forbidden in kernel_launch)
__device__ float g_q[MROWS * DD];     // 16 MB
__device__ float g_k[MROWS * DD];     // 16 MB
__device__ float g_v[MROWS * DD];     // 16 MB
__device__ float g_attn[MROWS * DD];  // 16 MB

// ---------------------------------------------------------------------------
// Tiled fp32 GEMM: C[M,N] = A[M,K] @ B[K,N], all row-major. M%64==N%64==K%16==0.
// 256 threads, each computes a 4x4 micro-tile.
// ---------------------------------------------------------------------------
__global__ __launch_bounds__(256)
void gemm64_kernel(const float* __restrict__ A, const float* __restrict__ B,
                   float* __restrict__ C, int M, int N, int K) {
    __shared__ float As[GBM][GBK + 1];   // [m][k], pad
    __shared__ float Bs[GBK][GBN + 4];   // [k][n], pad (row stride 68 floats = 272B, 16B-aligned)

    const int tid = threadIdx.x;
    const int tx = tid & 15;
    const int ty = tid >> 4;
    const int bm = blockIdx.y * GBM;
    const int bn = blockIdx.x * GBN;

    float acc[4][4];
    #pragma unroll
    for (int i = 0; i < 4; i++)
        #pragma unroll
        for (int j = 0; j < 4; j++) acc[i][j] = 0.f;

    const int ar = tid >> 2;          // 0..63
    const int ac = (tid & 3) * 4;     // 0,4,8,12
    const int br = tid >> 4;          // 0..15
    const int bc = (tid & 15) * 4;    // 0..60

    for (int k0 = 0; k0 < K; k0 += GBK) {
        float4 av = *(const float4*)&A[(size_t)(bm + ar) * K + k0 + ac];
        As[ar][ac + 0] = av.x; As[ar][ac + 1] = av.y;
        As[ar][ac + 2] = av.z; As[ar][ac + 3] = av.w;
        float4 bv = *(const float4*)&B[(size_t)(k0 + br) * N + bn + bc];
        *(float4*)&Bs[br][bc] = bv;
        __syncthreads();

        #pragma unroll
        for (int k = 0; k < GBK; k++) {
            float a[4], b[4];
            #pragma unroll
            for (int i = 0; i < 4; i++) a[i] = As[ty * 4 + i][k];
            #pragma unroll
            for (int j = 0; j < 4; j++) b[j] = Bs[k][tx * 4 + j];
            #pragma unroll
            for (int i = 0; i < 4; i++)
                #pragma unroll
                for (int j = 0; j < 4; j++) acc[i][j] += a[i] * b[j];
        }
        __syncthreads();
    }

    #pragma unroll
    for (int i = 0; i < 4; i++) {
        #pragma unroll
        for (int j = 0; j < 4; j++) {
            C[(size_t)(bm + ty * 4 + i) * N + bn + tx * 4 + j] = acc[i][j];
        }
    }
}

// ---------------------------------------------------------------------------
// Flash attention (causal), fp32. Layouts: Q/K/V/O are [B, T, H*HD] row-major.
// Grid: (T/64, B*H). Block: 256 threads (16x16, each owns 4x4).
// BQ = BKV = 64, HD = 64. Online softmax. Causal tiles beyond the diagonal
// are skipped entirely (kt runs 0..qb).
// ---------------------------------------------------------------------------
#define TSTR 65   // padded smem row stride

__global__ __launch_bounds__(256)
void flash_kernel(const float* __restrict__ Q, const float* __restrict__ K,
                  const float* __restrict__ V, float* __restrict__ O) {
    const int qb = blockIdx.x;         // query block 0..31
    const int bh = blockIdx.y;         // 0..31
    const int b = bh >> 4;
    const int h = bh & 15;
    const int tid = threadIdx.x;
    const int tx = tid & 15;
    const int ty = tid >> 4;
    const int r0 = ty * 4;
    const int c0 = tx * 4;

    extern __shared__ float sm[];
    float* Qs   = sm;                   // 64*65
    float* Ks   = Qs + 64 * TSTR;       // 64*65
    float* Vs   = Ks + 64 * TSTR;       // 64*65
    float* Ps   = Vs + 64 * TSTR;       // 64*65
    float* red  = Ps + 64 * TSTR;       // 64*16
    float* mrow = red + 64 * 16;        // 64
    float* lrow = mrow + 64;            // 64
    float* facr = lrow + 64;            // 64

    const size_t base_q  = ((size_t)(b * TT + qb * 64)) * DD + h * HD;
    const size_t base_kv = ((size_t)(b * TT)) * DD + h * HD;

    // Load Q tile [64 x 64]
    for (int idx = tid; idx < 64 * 16; idx += 256) {
        const int r = idx >> 4;
        const int c4 = (idx & 15) << 2;
        float4 v4 = *(const float4*)&Q[base_q + (size_t)r * DD + c4];
        Qs[r * TSTR + c4 + 0] = v4.x; Qs[r * TSTR + c4 + 1] = v4.y;
        Qs[r * TSTR + c4 + 2] = v4.z; Qs[r * TSTR + c4 + 3] = v4.w;
    }
    if (tid < 64) { mrow[tid] = -CUDART_INF_F; lrow[tid] = 0.f; }

    float acc[4][4];
    #pragma unroll
    for (int i = 0; i < 4; i++)
        #pragma unroll
        for (int j = 0; j < 4; j++) acc[i][j] = 0.f;

    const float scale = 0.125f;  // 1/sqrt(64)

    for (int kt = 0; kt <= qb; kt++) {
        // Load K, V tiles for this key block
        const size_t tb = base_kv + (size_t)kt * 64 * DD;
        for (int idx = tid; idx < 64 * 16; idx += 256) {
            const int r = idx >> 4;
            const int c4 = (idx & 15) << 2;
            float4 kv = *(const float4*)&K[tb + (size_t)r * DD + c4];
            Ks[r * TSTR + c4 + 0] = kv.x; Ks[r * TSTR + c4 + 1] = kv.y;
            Ks[r * TSTR + c4 + 2] = kv.z; Ks[r * TSTR + c4 + 3] = kv.w;
            float4 vv = *(const float4*)&V[tb + (size_t)r * DD + c4];
            Vs[r * TSTR + c4 + 0] = vv.x; Vs[r * TSTR + c4 + 1] = vv.y;
            Vs[r * TSTR + c4 + 2] = vv.z; Vs[r * TSTR + c4 + 3] = vv.w;
        }
        __syncthreads();

        // S = Q @ K^T (4x4 per thread), scaled + causal mask
        float s[4][4];
        #pragma unroll
        for (int i = 0; i < 4; i++)
            #pragma unroll
            for (int j = 0; j < 4; j++) s[i][j] = 0.f;

        #pragma unroll 8
        for (int kk = 0; kk < HD; kk++) {
            float a[4], bq[4];
            #pragma unroll
            for (int i = 0; i < 4; i++) a[i] = Qs[(r0 + i) * TSTR + kk];
            #pragma unroll
            for (int j = 0; j < 4; j++) bq[j] = Ks[(c0 + j) * TSTR + kk];
            #pragma unroll
            for (int i = 0; i < 4; i++)
                #pragma unroll
                for (int j = 0; j < 4; j++) s[i][j] += a[i] * bq[j];
        }

        const bool diag = (kt == qb);
        #pragma unroll
        for (int i = 0; i < 4; i++) {
            #pragma unroll
            for (int j = 0; j < 4; j++) {
                s[i][j] *= scale;
                if (diag && (c0 + j) > (r0 + i)) s[i][j] = -1e30f;
            }
        }

        // Partial row max
        #pragma unroll
        for (int i = 0; i < 4; i++) {
            float pm = s[i][0];
            #pragma unroll
            for (int j = 1; j < 4; j++) pm = fmaxf(pm, s[i][j]);
            red[(r0 + i) * 16 + tx] = pm;
        }
        __syncthreads();

        if (tid < 64) {
            float tm = red[tid * 16];
            #pragma unroll
            for (int t = 1; t < 16; t++) tm = fmaxf(tm, red[tid * 16 + t]);
            const float mo = mrow[tid];
            const float mn = fmaxf(mo, tm);
            mrow[tid] = mn;
            facr[tid] = __expf(mo - mn);   // 0 on first tile (mo = -inf)
        }
        __syncthreads();

        // P = exp(S - m_new), partial row sums
        #pragma unroll
        for (int i = 0; i < 4; i++) {
            const float mn = mrow[r0 + i];
            float rs = 0.f;
            #pragma unroll
            for (int j = 0; j < 4; j++) {
                const float p = __expf(s[i][j] - mn);
                Ps[(r0 + i) * TSTR + (c0 + j)] = p;
                rs += p;
            }
            red[(r0 + i) * 16 + tx] = rs;
        }
        __syncthreads();

        if (tid < 64) {
            float ssum = 0.f;
            #pragma unroll
            for (int t = 0; t < 16; t++) ssum += red[tid * 16 + t];
            lrow[tid] = facr[tid] * lrow[tid] + ssum;
        }

        // O = facr * O + P @ V  (Ps, Vs, facr all stable past the last sync)
        #pragma unroll
        for (int i = 0; i < 4; i++) {
            const float f = facr[r0 + i];
            #pragma unroll
            for (int j = 0; j < 4; j++) acc[i][j] *= f;
        }
        #pragma unroll 8
        for (int kk = 0; kk < 64; kk++) {
            float p[4], vv[4];
            #pragma unroll
            for (int i = 0; i < 4; i++) p[i] = Ps[(r0 + i) * TSTR + kk];
            #pragma unroll
            for (int j = 0; j < 4; j++) vv[j] = Vs[kk * TSTR + (c0 + j)];
            #pragma unroll
            for (int i = 0; i < 4; i++)
                #pragma unroll
                for (int j = 0; j < 4; j++) acc[i][j] += p[i] * vv[j];
        }
        __syncthreads();   // protects Ks/Vs/Ps/red for next iteration; also
                           // orders lrow writes before the epilogue reads
    }

    // Epilogue: normalize and store
    #pragma unroll
    for (int i = 0; i < 4; i++) {
        const float inv = 1.0f / lrow[r0 + i];
        #pragma unroll
        for (int j = 0; j < 4; j++) {
            O[base_q + (size_t)(r0 + i) * DD + (c0 + j)] = acc[i][j] * inv;
        }
    }
}

// ---------------------------------------------------------------------------
// Launch
// ---------------------------------------------------------------------------
extern "C" void kernel_launch(void* const* d_in, const int* in_sizes, int n_in,
                              void* d_out, int out_size) {
    const float* xq  = (const float*)d_in[0];  // inputs_q  [B,T,D]
    const float* xkv = (const float*)d_in[1];  // inputs_kv [B,T,D]
    // d_in[2] = mask (causal tril, known statically) — ignored
    const float* Wq = (const float*)d_in[3];
    const float* Wk = (const float*)d_in[4];
    const float* Wv = (const float*)d_in[5];
    const float* Wo = (const float*)d_in[6];
    float* out = (float*)d_out;

    float *q_p, *k_p, *v_p, *a_p;
    cudaGetSymbolAddress((void**)&q_p, g_q);
    cudaGetSymbolAddress((void**)&k_p, g_k);
    cudaGetSymbolAddress((void**)&v_p, g_v);
    cudaGetSymbolAddress((void**)&a_p, g_attn);

    const int smem_flash = (4 * 64 * TSTR + 64 * 16 + 3 * 64) * (int)sizeof(float); // 71424 B
    cudaFuncSetAttribute(flash_kernel, cudaFuncAttributeMaxDynamicSharedMemorySize,
                         smem_flash);

    dim3 gg(DD / GBN, MROWS / GBM);  // (16, 64)
    gemm64_kernel<<<gg, 256>>>(xq,  Wq, q_p, MROWS, DD, DD);
    gemm64_kernel<<<gg, 256>>>(xkv, Wk, k_p, MROWS, DD, DD);
    gemm64_kernel<<<gg, 256>>>(xkv, Wv, v_p, MROWS, DD, DD);

    flash_kernel<<<dim3(TT / 64, BB * HH), 256, smem_flash>>>(q_p, k_p, v_p, a_p);

    gemm64_kernel<<<gg, 256>>>(a_p, Wo, out, MROWS, DD, DD);
}

// round 3
// speedup vs baseline: 1.5614x; 1.5614x over previous
#include <cuda_runtime.h>
#include <cuda_bf16.h>
#include <math_constants.h>
#include <cstdint>

// Problem constants
#define BB   2
#define TT   2048
#define DD   1024
#define HH   16
#define HD   64
#define MROWS (BB*TT)        // 4096

// ---------------------------------------------------------------------------
// Scratch (device globals; allocation forbidden)
// ---------------------------------------------------------------------------
__device__ float g_q[MROWS * DD];
__device__ float g_k[MROWS * DD];
__device__ float g_v[MROWS * DD];
__device__ float g_attn[MROWS * DD];

__device__ __nv_bfloat16 g_xa_h[MROWS * DD];   // activation hi
__device__ __nv_bfloat16 g_xa_l[MROWS * DD];   // activation lo
__device__ __nv_bfloat16 g_xb_h[MROWS * DD];   // kv activation hi
__device__ __nv_bfloat16 g_xb_l[MROWS * DD];
__device__ __nv_bfloat16 g_wt_h[4 * DD * DD];  // transposed weights hi [n][k]
__device__ __nv_bfloat16 g_wt_l[4 * DD * DD];  // transposed weights lo

// ---------------------------------------------------------------------------
// Small PTX helpers
// ---------------------------------------------------------------------------
__device__ __forceinline__ uint32_t smem_to_u32(const void* p) {
    uint32_t a;
    asm("{ .reg .u64 t; cvta.to.shared.u64 t, %1; cvt.u32.u64 %0, t; }"
        : "=r"(a) : "l"(p));
    return a;
}
__device__ __forceinline__ void cp_async16(uint32_t sa, const void* g) {
    asm volatile("cp.async.cg.shared.global [%0], [%1], 16;" :: "r"(sa), "l"(g));
}
__device__ __forceinline__ void cp_commit() {
    asm volatile("cp.async.commit_group;");
}
template <int N>
__device__ __forceinline__ void cp_wait() {
    asm volatile("cp.async.wait_group %0;" :: "n"(N));
}
__device__ __forceinline__ void ldsm_x4(uint32_t addr, uint32_t& r0, uint32_t& r1,
                                        uint32_t& r2, uint32_t& r3) {
    asm volatile("ldmatrix.sync.aligned.m8n8.x4.shared.b16 {%0,%1,%2,%3}, [%4];"
                 : "=r"(r0), "=r"(r1), "=r"(r2), "=r"(r3) : "r"(addr));
}
__device__ __forceinline__ void mma16816(float* c, const uint32_t* a,
                                         uint32_t b0, uint32_t b1) {
    asm volatile(
        "mma.sync.aligned.m16n8k16.row.col.f32.bf16.bf16.f32 "
        "{%0,%1,%2,%3}, {%4,%5,%6,%7}, {%8,%9}, {%0,%1,%2,%3};"
        : "+f"(c[0]), "+f"(c[1]), "+f"(c[2]), "+f"(c[3])
        : "r"(a[0]), "r"(a[1]), "r"(a[2]), "r"(a[3]), "r"(b0), "r"(b1));
}

// ---------------------------------------------------------------------------
// Activation fp32 -> (hi, lo) bf16 split
// ---------------------------------------------------------------------------
__global__ __launch_bounds__(256)
void aconv_kernel(const float* __restrict__ X, __nv_bfloat16* __restrict__ Xh,
                  __nv_bfloat16* __restrict__ Xl, int n4) {
    int i = blockIdx.x * blockDim.x + threadIdx.x;
    if (i >= n4) return;
    float4 v = ((const float4*)X)[i];
    __nv_bfloat16 h0 = __float2bfloat16(v.x), h1 = __float2bfloat16(v.y);
    __nv_bfloat16 h2 = __float2bfloat16(v.z), h3 = __float2bfloat16(v.w);
    __nv_bfloat16 l0 = __float2bfloat16(v.x - __bfloat162float(h0));
    __nv_bfloat16 l1 = __float2bfloat16(v.y - __bfloat162float(h1));
    __nv_bfloat16 l2 = __float2bfloat16(v.z - __bfloat162float(h2));
    __nv_bfloat16 l3 = __float2bfloat16(v.w - __bfloat162float(h3));
    ((__nv_bfloat162*)Xh)[i * 2 + 0] = __nv_bfloat162(h0, h1);
    ((__nv_bfloat162*)Xh)[i * 2 + 1] = __nv_bfloat162(h2, h3);
    ((__nv_bfloat162*)Xl)[i * 2 + 0] = __nv_bfloat162(l0, l1);
    ((__nv_bfloat162*)Xl)[i * 2 + 1] = __nv_bfloat162(l2, l3);
}

// ---------------------------------------------------------------------------
// Weight transpose + split: W[k][n] fp32 -> Wt[n][k] hi/lo bf16 (1024x1024)
// ---------------------------------------------------------------------------
__global__ __launch_bounds__(256)
void wconv_kernel(const float* __restrict__ W, __nv_bfloat16* __restrict__ Th,
                  __nv_bfloat16* __restrict__ Tl) {
    __shared__ float t[32][33];
    const int tx = threadIdx.x, ty = threadIdx.y;
    const int k0 = blockIdx.y * 32, n0 = blockIdx.x * 32;
    #pragma unroll
    for (int i = 0; i < 4; i++)
        t[ty + 8 * i][tx] = W[(size_t)(k0 + ty + 8 * i) * DD + n0 + tx];
    __syncthreads();
    #pragma unroll
    for (int i = 0; i < 4; i++) {
        float x = t[tx][ty + 8 * i];
        __nv_bfloat16 h = __float2bfloat16(x);
        __nv_bfloat16 l = __float2bfloat16(x - __bfloat162float(h));
        size_t o = (size_t)(n0 + ty + 8 * i) * DD + k0 + tx;
        Th[o] = h; Tl[o] = l;
    }
}

// ---------------------------------------------------------------------------
// bf16x3 GEMM with mma.sync: C[M,N] = A[M,K] @ W[K,N]
//   A = (Ah,Al) row-major [M,K]; W = (Bh,Bl) transposed [N,K] ("col" for mma).
//   CTA tile 128x128, 8 warps (4x2) each 32x64, K-chunk 32, cp.async x2 stages.
// smem per stage: 4 matrices * 128 rows * 80B (stride 40 bf16) = 40960 B
// ---------------------------------------------------------------------------
#define KC        32
#define SROW      80                      // bytes per smem row (40 bf16, padded)
#define MAT_B     (128 * SROW)            // 10240 B per matrix tile
#define STAGE_B   (4 * MAT_B)             // 40960 B
#define GEMM_SMEM (2 * STAGE_B)           // 81920 B

__global__ __launch_bounds__(256, 1)
void gemm_mma_kernel(const __nv_bfloat16* __restrict__ Ah,
                     const __nv_bfloat16* __restrict__ Al,
                     const __nv_bfloat16* __restrict__ Bh,
                     const __nv_bfloat16* __restrict__ Bl,
                     float* __restrict__ C, int M, int N, int K) {
    extern __shared__ char smem[];
    const uint32_t sbase = smem_to_u32(smem);
    const int tid = threadIdx.x;
    const int lane = tid & 31;
    const int wid = tid >> 5;
    const int wm = wid >> 1;              // 0..3
    const int wn = wid & 1;               // 0..1
    const int bm = blockIdx.y * 128;
    const int bn = blockIdx.x * 128;

    float acc[2][8][4];
    #pragma unroll
    for (int i = 0; i < 2; i++)
        #pragma unroll
        for (int j = 0; j < 8; j++)
            #pragma unroll
            for (int q = 0; q < 4; q++) acc[i][j][q] = 0.f;

    const int nchunks = K / KC;           // 32

    // ---- loader: per chunk, 2048 x 16B transfers; t in [0,8): mat = t>>1
    const int lrow_half = (tid >> 2);     // 0..63
    const int lseg = tid & 3;             // 16B segment within 64B row

    auto load_chunk = [&](int c) {
        const int k0 = c * KC;
        const uint32_t st = sbase + (c & 1) * STAGE_B;
        #pragma unroll
        for (int t = 0; t < 8; t++) {
            const int mat = t >> 1;
            const int row = (t & 1) * 64 + lrow_half;
            const __nv_bfloat16* src = (mat == 0) ? Ah : (mat == 1) ? Al
                                      : (mat == 2) ? Bh : Bl;
            const int grow = ((mat < 2) ? bm : bn) + row;
            const void* g = src + (size_t)grow * K + k0 + lseg * 8;
            cp_async16(st + mat * MAT_B + row * SROW + lseg * 16, g);
        }
        cp_commit();
    };

    // fragment smem addresses (lane-dependent constants)
    const int a_row = wm * 32 + (lane & 15);         // + mt*16
    const int a_col = (lane >> 4) * 8;               // + kstep*16
    const int b_row = wn * 64 + ((lane >> 4) & 1) * 8 + (lane & 7);  // + p*16
    const int b_col = ((lane >> 3) & 1) * 8;         // + kstep*16

    load_chunk(0);

    for (int c = 0; c < nchunks; c++) {
        if (c + 1 < nchunks) { load_chunk(c + 1); cp_wait<1>(); }
        else cp_wait<0>();
        __syncthreads();

        const uint32_t st = sbase + (c & 1) * STAGE_B;
        #pragma unroll
        for (int kstep = 0; kstep < 2; kstep++) {
            uint32_t ah[2][4], al[2][4], bh[4][4], bl[4][4];
            #pragma unroll
            for (int mt = 0; mt < 2; mt++) {
                uint32_t ra = st + 0 * MAT_B +
                    (a_row + mt * 16) * SROW + (a_col + kstep * 16) * 2;
                ldsm_x4(ra, ah[mt][0], ah[mt][1], ah[mt][2], ah[mt][3]);
                uint32_t rl = st + 1 * MAT_B +
                    (a_row + mt * 16) * SROW + (a_col + kstep * 16) * 2;
                ldsm_x4(rl, al[mt][0], al[mt][1], al[mt][2], al[mt][3]);
            }
            #pragma unroll
            for (int p = 0; p < 4; p++) {
                uint32_t rb = st + 2 * MAT_B +
                    (b_row + p * 16) * SROW + (b_col + kstep * 16) * 2;
                ldsm_x4(rb, bh[p][0], bh[p][1], bh[p][2], bh[p][3]);
                uint32_t rl = st + 3 * MAT_B +
                    (b_row + p * 16) * SROW + (b_col + kstep * 16) * 2;
                ldsm_x4(rl, bl[p][0], bl[p][1], bl[p][2], bl[p][3]);
            }
            #pragma unroll
            for (int mt = 0; mt < 2; mt++) {
                #pragma unroll
                for (int p = 0; p < 4; p++) {
                    mma16816(acc[mt][2 * p + 0], ah[mt], bh[p][0], bh[p][1]);
                    mma16816(acc[mt][2 * p + 1], ah[mt], bh[p][2], bh[p][3]);
                    mma16816(acc[mt][2 * p + 0], ah[mt], bl[p][0], bl[p][1]);
                    mma16816(acc[mt][2 * p + 1], ah[mt], bl[p][2], bl[p][3]);
                    mma16816(acc[mt][2 * p + 0], al[mt], bh[p][0], bh[p][1]);
                    mma16816(acc[mt][2 * p + 1], al[mt], bh[p][2], bh[p][3]);
                }
            }
        }
        __syncthreads();
    }

    // Epilogue: thread t holds rows (t>>2, t>>2 + 8), cols (t&3)*2, per frag
    const int er = lane >> 2;
    const int ec = (lane & 3) * 2;
    #pragma unroll
    for (int mt = 0; mt < 2; mt++) {
        const int row0 = bm + wm * 32 + mt * 16 + er;
        #pragma unroll
        for (int nt = 0; nt < 8; nt++) {
            const int col = bn + wn * 64 + nt * 8 + ec;
            *(float2*)&C[(size_t)row0 * N + col] =
                make_float2(acc[mt][nt][0], acc[mt][nt][1]);
            *(float2*)&C[(size_t)(row0 + 8) * N + col] =
                make_float2(acc[mt][nt][2], acc[mt][nt][3]);
        }
    }
}

// ---------------------------------------------------------------------------
// Flash attention (causal), fp32 — known-good from Round 1
// ---------------------------------------------------------------------------
#define TSTR 65

__global__ __launch_bounds__(256)
void flash_kernel(const float* __restrict__ Q, const float* __restrict__ K,
                  const float* __restrict__ V, float* __restrict__ O) {
    const int qb = (int)gridDim.x - 1 - (int)blockIdx.x;  // heavy blocks first
    const int bh = blockIdx.y;
    const int b = bh >> 4;
    const int h = bh & 15;
    const int tid = threadIdx.x;
    const int tx = tid & 15;
    const int ty = tid >> 4;
    const int r0 = ty * 4;
    const int c0 = tx * 4;

    extern __shared__ float sm[];
    float* Qs   = sm;
    float* Ks   = Qs + 64 * TSTR;
    float* Vs   = Ks + 64 * TSTR;
    float* Ps   = Vs + 64 * TSTR;
    float* red  = Ps + 64 * TSTR;
    float* mrow = red + 64 * 16;
    float* lrow = mrow + 64;
    float* facr = lrow + 64;

    const size_t base_q  = ((size_t)(b * TT + qb * 64)) * DD + h * HD;
    const size_t base_kv = ((size_t)(b * TT)) * DD + h * HD;

    for (int idx = tid; idx < 64 * 16; idx += 256) {
        const int r = idx >> 4;
        const int c4 = (idx & 15) << 2;
        float4 v4 = *(const float4*)&Q[base_q + (size_t)r * DD + c4];
        Qs[r * TSTR + c4 + 0] = v4.x; Qs[r * TSTR + c4 + 1] = v4.y;
        Qs[r * TSTR + c4 + 2] = v4.z; Qs[r * TSTR + c4 + 3] = v4.w;
    }
    if (tid < 64) { mrow[tid] = -CUDART_INF_F; lrow[tid] = 0.f; }

    float acc[4][4];
    #pragma unroll
    for (int i = 0; i < 4; i++)
        #pragma unroll
        for (int j = 0; j < 4; j++) acc[i][j] = 0.f;

    const float scale = 0.125f;

    for (int kt = 0; kt <= qb; kt++) {
        const size_t tb = base_kv + (size_t)kt * 64 * DD;
        for (int idx = tid; idx < 64 * 16; idx += 256) {
            const int r = idx >> 4;
            const int c4 = (idx & 15) << 2;
            float4 kv = *(const float4*)&K[tb + (size_t)r * DD + c4];
            Ks[r * TSTR + c4 + 0] = kv.x; Ks[r * TSTR + c4 + 1] = kv.y;
            Ks[r * TSTR + c4 + 2] = kv.z; Ks[r * TSTR + c4 + 3] = kv.w;
            float4 vv = *(const float4*)&V[tb + (size_t)r * DD + c4];
            Vs[r * TSTR + c4 + 0] = vv.x; Vs[r * TSTR + c4 + 1] = vv.y;
            Vs[r * TSTR + c4 + 2] = vv.z; Vs[r * TSTR + c4 + 3] = vv.w;
        }
        __syncthreads();

        float s[4][4];
        #pragma unroll
        for (int i = 0; i < 4; i++)
            #pragma unroll
            for (int j = 0; j < 4; j++) s[i][j] = 0.f;

        #pragma unroll 8
        for (int kk = 0; kk < HD; kk++) {
            float a[4], bq[4];
            #pragma unroll
            for (int i = 0; i < 4; i++) a[i] = Qs[(r0 + i) * TSTR + kk];
            #pragma unroll
            for (int j = 0; j < 4; j++) bq[j] = Ks[(c0 + j) * TSTR + kk];
            #pragma unroll
            for (int i = 0; i < 4; i++)
                #pragma unroll
                for (int j = 0; j < 4; j++) s[i][j] += a[i] * bq[j];
        }

        const bool diag = (kt == qb);
        #pragma unroll
        for (int i = 0; i < 4; i++) {
            #pragma unroll
            for (int j = 0; j < 4; j++) {
                s[i][j] *= scale;
                if (diag && (c0 + j) > (r0 + i)) s[i][j] = -1e30f;
            }
        }

        #pragma unroll
        for (int i = 0; i < 4; i++) {
            float pm = s[i][0];
            #pragma unroll
            for (int j = 1; j < 4; j++) pm = fmaxf(pm, s[i][j]);
            red[(r0 + i) * 16 + tx] = pm;
        }
        __syncthreads();

        if (tid < 64) {
            float tm = red[tid * 16];
            #pragma unroll
            for (int t = 1; t < 16; t++) tm = fmaxf(tm, red[tid * 16 + t]);
            const float mo = mrow[tid];
            const float mn = fmaxf(mo, tm);
            mrow[tid] = mn;
            facr[tid] = __expf(mo - mn);
        }
        __syncthreads();

        #pragma unroll
        for (int i = 0; i < 4; i++) {
            const float mn = mrow[r0 + i];
            float rs = 0.f;
            #pragma unroll
            for (int j = 0; j < 4; j++) {
                const float p = __expf(s[i][j] - mn);
                Ps[(r0 + i) * TSTR + (c0 + j)] = p;
                rs += p;
            }
            red[(r0 + i) * 16 + tx] = rs;
        }
        __syncthreads();

        if (tid < 64) {
            float ssum = 0.f;
            #pragma unroll
            for (int t = 0; t < 16; t++) ssum += red[tid * 16 + t];
            lrow[tid] = facr[tid] * lrow[tid] + ssum;
        }

        #pragma unroll
        for (int i = 0; i < 4; i++) {
            const float f = facr[r0 + i];
            #pragma unroll
            for (int j = 0; j < 4; j++) acc[i][j] *= f;
        }
        #pragma unroll 8
        for (int kk = 0; kk < 64; kk++) {
            float p[4], vv[4];
            #pragma unroll
            for (int i = 0; i < 4; i++) p[i] = Ps[(r0 + i) * TSTR + kk];
            #pragma unroll
            for (int j = 0; j < 4; j++) vv[j] = Vs[kk * TSTR + (c0 + j)];
            #pragma unroll
            for (int i = 0; i < 4; i++)
                #pragma unroll
                for (int j = 0; j < 4; j++) acc[i][j] += p[i] * vv[j];
        }
        __syncthreads();
    }

    #pragma unroll
    for (int i = 0; i < 4; i++) {
        const float inv = 1.0f / lrow[r0 + i];
        #pragma unroll
        for (int j = 0; j < 4; j++) {
            O[base_q + (size_t)(r0 + i) * DD + (c0 + j)] = acc[i][j] * inv;
        }
    }
}

// ---------------------------------------------------------------------------
// Launch
// ---------------------------------------------------------------------------
extern "C" void kernel_launch(void* const* d_in, const int* in_sizes, int n_in,
                              void* d_out, int out_size) {
    const float* xq  = (const float*)d_in[0];
    const float* xkv = (const float*)d_in[1];
    const float* Wq = (const float*)d_in[3];
    const float* Wk = (const float*)d_in[4];
    const float* Wv = (const float*)d_in[5];
    const float* Wo = (const float*)d_in[6];
    float* out = (float*)d_out;

    float *q_p, *k_p, *v_p, *a_p;
    cudaGetSymbolAddress((void**)&q_p, g_q);
    cudaGetSymbolAddress((void**)&k_p, g_k);
    cudaGetSymbolAddress((void**)&v_p, g_v);
    cudaGetSymbolAddress((void**)&a_p, g_attn);
    __nv_bfloat16 *xah, *xal, *xbh, *xbl, *wth, *wtl;
    cudaGetSymbolAddress((void**)&xah, g_xa_h);
    cudaGetSymbolAddress((void**)&xal, g_xa_l);
    cudaGetSymbolAddress((void**)&xbh, g_xb_h);
    cudaGetSymbolAddress((void**)&xbl, g_xb_l);
    cudaGetSymbolAddress((void**)&wth, g_wt_h);
    cudaGetSymbolAddress((void**)&wtl, g_wt_l);

    const int smem_flash = (4 * 64 * TSTR + 64 * 16 + 3 * 64) * (int)sizeof(float);
    cudaFuncSetAttribute(flash_kernel, cudaFuncAttributeMaxDynamicSharedMemorySize,
                         smem_flash);
    cudaFuncSetAttribute(gemm_mma_kernel, cudaFuncAttributeMaxDynamicSharedMemorySize,
                         GEMM_SMEM);

    const int n4 = MROWS * DD / 4;
    aconv_kernel<<<(n4 + 255) / 256, 256>>>(xq,  xah, xal, n4);
    aconv_kernel<<<(n4 + 255) / 256, 256>>>(xkv, xbh, xbl, n4);

    dim3 wg(32, 32), wb(32, 8);
    wconv_kernel<<<wg, wb>>>(Wq, wth + 0 * DD * DD, wtl + 0 * DD * DD);
    wconv_kernel<<<wg, wb>>>(Wk, wth + 1 * DD * DD, wtl + 1 * DD * DD);
    wconv_kernel<<<wg, wb>>>(Wv, wth + 2 * DD * DD, wtl + 2 * DD * DD);
    wconv_kernel<<<wg, wb>>>(Wo, wth + 3 * DD * DD, wtl + 3 * DD * DD);

    dim3 gg(DD / 128, MROWS / 128);  // (8, 32)
    gemm_mma_kernel<<<gg, 256, GEMM_SMEM>>>(xah, xal, wth + 0 * DD * DD, wtl + 0 * DD * DD,
                                            q_p, MROWS, DD, DD);
    gemm_mma_kernel<<<gg, 256, GEMM_SMEM>>>(xbh, xbl, wth + 1 * DD * DD, wtl + 1 * DD * DD,
                                            k_p, MROWS, DD, DD);
    gemm_mma_kernel<<<gg, 256, GEMM_SMEM>>>(xbh, xbl, wth + 2 * DD * DD, wtl + 2 * DD * DD,
                                            v_p, MROWS, DD, DD);

    flash_kernel<<<dim3(TT / 64, BB * HH), 256, smem_flash>>>(q_p, k_p, v_p, a_p);

    aconv_kernel<<<(n4 + 255) / 256, 256>>>(a_p, xah, xal, n4);
    gemm_mma_kernel<<<gg, 256, GEMM_SMEM>>>(xah, xal, wth + 3 * DD * DD, wtl + 3 * DD * DD,
                                            out, MROWS, DD, DD);
}

// round 4
// speedup vs baseline: 2.8338x; 1.8150x over previous
#include <cuda_runtime.h>
#include <cuda_bf16.h>
#include <math_constants.h>
#include <cstdint>

// Problem constants
#define BB   2
#define TT   2048
#define DD   1024
#define HH   16
#define HD   64
#define MROWS (BB*TT)        // 4096

// ---------------------------------------------------------------------------
// Scratch (device globals; allocation forbidden)
// ---------------------------------------------------------------------------
__device__ __nv_bfloat16 g_qh[MROWS * DD];
__device__ __nv_bfloat16 g_ql[MROWS * DD];
__device__ __nv_bfloat16 g_kh[MROWS * DD];
__device__ __nv_bfloat16 g_kl[MROWS * DD];
__device__ __nv_bfloat16 g_vh[MROWS * DD];
__device__ __nv_bfloat16 g_vl[MROWS * DD];

__device__ __nv_bfloat16 g_xa_h[MROWS * DD];   // activation hi (reused for attn out)
__device__ __nv_bfloat16 g_xa_l[MROWS * DD];
__device__ __nv_bfloat16 g_xb_h[MROWS * DD];   // kv activation hi
__device__ __nv_bfloat16 g_xb_l[MROWS * DD];
__device__ __nv_bfloat16 g_wt_h[4 * DD * DD];  // transposed weights hi [n][k]
__device__ __nv_bfloat16 g_wt_l[4 * DD * DD];

// ---------------------------------------------------------------------------
// PTX helpers
// ---------------------------------------------------------------------------
__device__ __forceinline__ uint32_t smem_to_u32(const void* p) {
    uint32_t a;
    asm("{ .reg .u64 t; cvta.to.shared.u64 t, %1; cvt.u32.u64 %0, t; }"
        : "=r"(a) : "l"(p));
    return a;
}
__device__ __forceinline__ void cp_async16(uint32_t sa, const void* g) {
    asm volatile("cp.async.cg.shared.global [%0], [%1], 16;" :: "r"(sa), "l"(g));
}
__device__ __forceinline__ void cp_commit() {
    asm volatile("cp.async.commit_group;");
}
template <int N>
__device__ __forceinline__ void cp_wait() {
    asm volatile("cp.async.wait_group %0;" :: "n"(N));
}
__device__ __forceinline__ void ldsm_x4(uint32_t addr, uint32_t& r0, uint32_t& r1,
                                        uint32_t& r2, uint32_t& r3) {
    asm volatile("ldmatrix.sync.aligned.m8n8.x4.shared.b16 {%0,%1,%2,%3}, [%4];"
                 : "=r"(r0), "=r"(r1), "=r"(r2), "=r"(r3) : "r"(addr));
}
__device__ __forceinline__ void ldsm_x4_t(uint32_t addr, uint32_t& r0, uint32_t& r1,
                                          uint32_t& r2, uint32_t& r3) {
    asm volatile("ldmatrix.sync.aligned.m8n8.x4.trans.shared.b16 {%0,%1,%2,%3}, [%4];"
                 : "=r"(r0), "=r"(r1), "=r"(r2), "=r"(r3) : "r"(addr));
}
__device__ __forceinline__ void mma16816(float* c, const uint32_t* a,
                                         uint32_t b0, uint32_t b1) {
    asm volatile(
        "mma.sync.aligned.m16n8k16.row.col.f32.bf16.bf16.f32 "
        "{%0,%1,%2,%3}, {%4,%5,%6,%7}, {%8,%9}, {%0,%1,%2,%3};"
        : "+f"(c[0]), "+f"(c[1]), "+f"(c[2]), "+f"(c[3])
        : "r"(a[0]), "r"(a[1]), "r"(a[2]), "r"(a[3]), "r"(b0), "r"(b1));
}
__device__ __forceinline__ uint32_t pack_bf16(float x, float y) {
    __nv_bfloat162 v(__float2bfloat16(x), __float2bfloat16(y));
    return *(uint32_t*)&v;
}

// ---------------------------------------------------------------------------
// Activation fp32 -> (hi, lo) bf16 split
// ---------------------------------------------------------------------------
__global__ __launch_bounds__(256)
void aconv_kernel(const float* __restrict__ X, __nv_bfloat16* __restrict__ Xh,
                  __nv_bfloat16* __restrict__ Xl, int n4) {
    int i = blockIdx.x * blockDim.x + threadIdx.x;
    if (i >= n4) return;
    float4 v = ((const float4*)X)[i];
    __nv_bfloat16 h0 = __float2bfloat16(v.x), h1 = __float2bfloat16(v.y);
    __nv_bfloat16 h2 = __float2bfloat16(v.z), h3 = __float2bfloat16(v.w);
    __nv_bfloat16 l0 = __float2bfloat16(v.x - __bfloat162float(h0));
    __nv_bfloat16 l1 = __float2bfloat16(v.y - __bfloat162float(h1));
    __nv_bfloat16 l2 = __float2bfloat16(v.z - __bfloat162float(h2));
    __nv_bfloat16 l3 = __float2bfloat16(v.w - __bfloat162float(h3));
    ((__nv_bfloat162*)Xh)[i * 2 + 0] = __nv_bfloat162(h0, h1);
    ((__nv_bfloat162*)Xh)[i * 2 + 1] = __nv_bfloat162(h2, h3);
    ((__nv_bfloat162*)Xl)[i * 2 + 0] = __nv_bfloat162(l0, l1);
    ((__nv_bfloat162*)Xl)[i * 2 + 1] = __nv_bfloat162(l2, l3);
}

// ---------------------------------------------------------------------------
// Weight transpose + split: W[k][n] fp32 -> Wt[n][k] hi/lo bf16 (1024x1024)
// ---------------------------------------------------------------------------
__global__ __launch_bounds__(256)
void wconv_kernel(const float* __restrict__ W, __nv_bfloat16* __restrict__ Th,
                  __nv_bfloat16* __restrict__ Tl) {
    __shared__ float t[32][33];
    const int tx = threadIdx.x, ty = threadIdx.y;
    const int k0 = blockIdx.y * 32, n0 = blockIdx.x * 32;
    #pragma unroll
    for (int i = 0; i < 4; i++)
        t[ty + 8 * i][tx] = W[(size_t)(k0 + ty + 8 * i) * DD + n0 + tx];
    __syncthreads();
    #pragma unroll
    for (int i = 0; i < 4; i++) {
        float x = t[tx][ty + 8 * i];
        __nv_bfloat16 h = __float2bfloat16(x);
        __nv_bfloat16 l = __float2bfloat16(x - __bfloat162float(h));
        size_t o = (size_t)(n0 + ty + 8 * i) * DD + k0 + tx;
        Th[o] = h; Tl[o] = l;
    }
}

// ---------------------------------------------------------------------------
// bf16x3 GEMM with mma.sync: C = A[M,K] @ W[K,N]; W pre-transposed [N,K].
// Epilogue: if Ch != nullptr write bf16 hi/lo split, else fp32 to C.
// ---------------------------------------------------------------------------
#define KC        32
#define SROW      80
#define MAT_B     (128 * SROW)
#define STAGE_B   (4 * MAT_B)
#define GEMM_SMEM (2 * STAGE_B)           // 81920 B

__global__ __launch_bounds__(256, 1)
void gemm_mma_kernel(const __nv_bfloat16* __restrict__ Ah,
                     const __nv_bfloat16* __restrict__ Al,
                     const __nv_bfloat16* __restrict__ Bh,
                     const __nv_bfloat16* __restrict__ Bl,
                     float* __restrict__ C,
                     __nv_bfloat16* __restrict__ Ch,
                     __nv_bfloat16* __restrict__ Cl,
                     int M, int N, int K) {
    extern __shared__ char smem[];
    const uint32_t sbase = smem_to_u32(smem);
    const int tid = threadIdx.x;
    const int lane = tid & 31;
    const int wid = tid >> 5;
    const int wm = wid >> 1;
    const int wn = wid & 1;
    const int bm = blockIdx.y * 128;
    const int bn = blockIdx.x * 128;

    float acc[2][8][4];
    #pragma unroll
    for (int i = 0; i < 2; i++)
        #pragma unroll
        for (int j = 0; j < 8; j++)
            #pragma unroll
            for (int q = 0; q < 4; q++) acc[i][j][q] = 0.f;

    const int nchunks = K / KC;
    const int lrow_half = (tid >> 2);
    const int lseg = tid & 3;

    auto load_chunk = [&](int c) {
        const int k0 = c * KC;
        const uint32_t st = sbase + (c & 1) * STAGE_B;
        #pragma unroll
        for (int t = 0; t < 8; t++) {
            const int mat = t >> 1;
            const int row = (t & 1) * 64 + lrow_half;
            const __nv_bfloat16* src = (mat == 0) ? Ah : (mat == 1) ? Al
                                      : (mat == 2) ? Bh : Bl;
            const int grow = ((mat < 2) ? bm : bn) + row;
            const void* g = src + (size_t)grow * K + k0 + lseg * 8;
            cp_async16(st + mat * MAT_B + row * SROW + lseg * 16, g);
        }
        cp_commit();
    };

    const int a_row = wm * 32 + (lane & 15);
    const int a_col = (lane >> 4) * 8;
    const int b_row = wn * 64 + ((lane >> 4) & 1) * 8 + (lane & 7);
    const int b_col = ((lane >> 3) & 1) * 8;

    load_chunk(0);

    for (int c = 0; c < nchunks; c++) {
        if (c + 1 < nchunks) { load_chunk(c + 1); cp_wait<1>(); }
        else cp_wait<0>();
        __syncthreads();

        const uint32_t st = sbase + (c & 1) * STAGE_B;
        #pragma unroll
        for (int kstep = 0; kstep < 2; kstep++) {
            uint32_t ah[2][4], al[2][4], bh[4][4], bl[4][4];
            #pragma unroll
            for (int mt = 0; mt < 2; mt++) {
                uint32_t ra = st + 0 * MAT_B +
                    (a_row + mt * 16) * SROW + (a_col + kstep * 16) * 2;
                ldsm_x4(ra, ah[mt][0], ah[mt][1], ah[mt][2], ah[mt][3]);
                uint32_t rl = st + 1 * MAT_B +
                    (a_row + mt * 16) * SROW + (a_col + kstep * 16) * 2;
                ldsm_x4(rl, al[mt][0], al[mt][1], al[mt][2], al[mt][3]);
            }
            #pragma unroll
            for (int p = 0; p < 4; p++) {
                uint32_t rb = st + 2 * MAT_B +
                    (b_row + p * 16) * SROW + (b_col + kstep * 16) * 2;
                ldsm_x4(rb, bh[p][0], bh[p][1], bh[p][2], bh[p][3]);
                uint32_t rl = st + 3 * MAT_B +
                    (b_row + p * 16) * SROW + (b_col + kstep * 16) * 2;
                ldsm_x4(rl, bl[p][0], bl[p][1], bl[p][2], bl[p][3]);
            }
            #pragma unroll
            for (int mt = 0; mt < 2; mt++) {
                #pragma unroll
                for (int p = 0; p < 4; p++) {
                    mma16816(acc[mt][2 * p + 0], ah[mt], bh[p][0], bh[p][1]);
                    mma16816(acc[mt][2 * p + 1], ah[mt], bh[p][2], bh[p][3]);
                    mma16816(acc[mt][2 * p + 0], ah[mt], bl[p][0], bl[p][1]);
                    mma16816(acc[mt][2 * p + 1], ah[mt], bl[p][2], bl[p][3]);
                    mma16816(acc[mt][2 * p + 0], al[mt], bh[p][0], bh[p][1]);
                    mma16816(acc[mt][2 * p + 1], al[mt], bh[p][2], bh[p][3]);
                }
            }
        }
        __syncthreads();
    }

    const int er = lane >> 2;
    const int ec = (lane & 3) * 2;
    #pragma unroll
    for (int mt = 0; mt < 2; mt++) {
        const int row0 = bm + wm * 32 + mt * 16 + er;
        #pragma unroll
        for (int nt = 0; nt < 8; nt++) {
            const int col = bn + wn * 64 + nt * 8 + ec;
            if (Ch) {
                #pragma unroll
                for (int half = 0; half < 2; half++) {
                    const size_t o = (size_t)(row0 + half * 8) * N + col;
                    float x = acc[mt][nt][2 * half], y = acc[mt][nt][2 * half + 1];
                    __nv_bfloat16 hx = __float2bfloat16(x), hy = __float2bfloat16(y);
                    *(__nv_bfloat162*)&Ch[o] = __nv_bfloat162(hx, hy);
                    *(__nv_bfloat162*)&Cl[o] = __nv_bfloat162(
                        __float2bfloat16(x - __bfloat162float(hx)),
                        __float2bfloat16(y - __bfloat162float(hy)));
                }
            } else {
                *(float2*)&C[(size_t)row0 * N + col] =
                    make_float2(acc[mt][nt][0], acc[mt][nt][1]);
                *(float2*)&C[(size_t)(row0 + 8) * N + col] =
                    make_float2(acc[mt][nt][2], acc[mt][nt][3]);
            }
        }
    }
}

// ---------------------------------------------------------------------------
// Flash attention with mma.sync (causal), bf16x3 split on S and PV.
// BQ=128, BKV=64, HD=64. 8 warps, each owns 16 query rows (full row in warp).
// K/V hi/lo double-buffered via cp.async. Outputs bf16 hi/lo.
// ---------------------------------------------------------------------------
#define FSROW  144                         // 64 bf16 = 128B + 16B pad
#define FTILE  (64 * FSROW)                // 9216
#define FSTAGE (4 * FTILE)                 // 36864 (Kh,Kl,Vh,Vl)
#define FLASH_SMEM (2 * FSTAGE)            // 73728

__global__ __launch_bounds__(256, 1)
void flash_mma_kernel(const __nv_bfloat16* __restrict__ Qh_,
                      const __nv_bfloat16* __restrict__ Ql_,
                      const __nv_bfloat16* __restrict__ Kh_,
                      const __nv_bfloat16* __restrict__ Kl_,
                      const __nv_bfloat16* __restrict__ Vh_,
                      const __nv_bfloat16* __restrict__ Vl_,
                      __nv_bfloat16* __restrict__ Oh_,
                      __nv_bfloat16* __restrict__ Ol_) {
    extern __shared__ char smem[];
    const uint32_t sbase = smem_to_u32(smem);
    const int qb = (int)gridDim.x - 1 - (int)blockIdx.x;   // heavy first
    const int bh = blockIdx.y;
    const int b = bh >> 4, h = bh & 15;
    const int tid = threadIdx.x, lane = tid & 31, wid = tid >> 5;
    const int wrow = qb * 128 + wid * 16;

    // ---- Stage Q (hi at 0, lo at 128*FSROW) and build Q fragments
    {
        const size_t gq = ((size_t)(b * TT + qb * 128)) * DD + h * HD;
        #pragma unroll
        for (int t = 0; t < 8; t++) {
            const int mat = t >> 2;
            const int row = (t & 3) * 32 + (tid >> 3);
            const __nv_bfloat16* src = mat ? Ql_ : Qh_;
            cp_async16(sbase + mat * (128 * FSROW) + row * FSROW + (tid & 7) * 16,
                       src + gq + (size_t)row * DD + (tid & 7) * 8);
        }
        cp_commit(); cp_wait<0>();
        __syncthreads();
    }
    uint32_t qh[4][4], ql[4][4];
    {
        const int a_row = wid * 16 + (lane & 15);
        const int a_col = (lane >> 4) * 8;
        #pragma unroll
        for (int ks = 0; ks < 4; ks++) {
            ldsm_x4(sbase + a_row * FSROW + (a_col + ks * 16) * 2,
                    qh[ks][0], qh[ks][1], qh[ks][2], qh[ks][3]);
            ldsm_x4(sbase + 128 * FSROW + a_row * FSROW + (a_col + ks * 16) * 2,
                    ql[ks][0], ql[ks][1], ql[ks][2], ql[ks][3]);
        }
    }
    __syncthreads();

    // ---- KV loader (double buffered)
    const size_t gkv = ((size_t)(b * TT)) * DD + h * HD;
    auto load_kv = [&](int kt) {
        const uint32_t st = sbase + (kt & 1) * FSTAGE;
        const size_t base = gkv + (size_t)(kt * 64) * DD;
        #pragma unroll
        for (int t = 0; t < 8; t++) {
            const int mat = t >> 1;
            const int row = (t & 1) * 32 + (tid >> 3);
            const __nv_bfloat16* src = (mat == 0) ? Kh_ : (mat == 1) ? Kl_
                                      : (mat == 2) ? Vh_ : Vl_;
            cp_async16(st + mat * FTILE + row * FSROW + (tid & 7) * 16,
                       src + base + (size_t)row * DD + (tid & 7) * 8);
        }
        cp_commit();
    };

    float acc[8][4];
    #pragma unroll
    for (int i = 0; i < 8; i++)
        #pragma unroll
        for (int j = 0; j < 4; j++) acc[i][j] = 0.f;
    float m0 = -CUDART_INF_F, m1 = -CUDART_INF_F, l0 = 0.f, l1 = 0.f;

    const int ntiles = 2 * qb + 2;
    const int diag_kt = wrow >> 6;
    const int b_row = ((lane >> 4) & 1) * 8 + (lane & 7);
    const int b_col = ((lane >> 3) & 1) * 8;

    load_kv(0);

    for (int kt = 0; kt < ntiles; kt++) {
        if (kt + 1 < ntiles) { load_kv(kt + 1); cp_wait<1>(); }
        else cp_wait<0>();
        __syncthreads();

        const uint32_t st = sbase + (kt & 1) * FSTAGE;
        if (kt * 64 <= wrow) {
            // ---- S = Q @ K^T (x3 split)
            float s[8][4];
            #pragma unroll
            for (int i = 0; i < 8; i++)
                #pragma unroll
                for (int j = 0; j < 4; j++) s[i][j] = 0.f;

            #pragma unroll
            for (int ks = 0; ks < 4; ks++) {
                #pragma unroll
                for (int p = 0; p < 4; p++) {
                    uint32_t kh[4], kl[4];
                    ldsm_x4(st + 0 * FTILE + (b_row + p * 16) * FSROW + (b_col + ks * 16) * 2,
                            kh[0], kh[1], kh[2], kh[3]);
                    ldsm_x4(st + 1 * FTILE + (b_row + p * 16) * FSROW + (b_col + ks * 16) * 2,
                            kl[0], kl[1], kl[2], kl[3]);
                    mma16816(s[2 * p + 0], qh[ks], kh[0], kh[1]);
                    mma16816(s[2 * p + 1], qh[ks], kh[2], kh[3]);
                    mma16816(s[2 * p + 0], qh[ks], kl[0], kl[1]);
                    mma16816(s[2 * p + 1], qh[ks], kl[2], kl[3]);
                    mma16816(s[2 * p + 0], ql[ks], kh[0], kh[1]);
                    mma16816(s[2 * p + 1], ql[ks], kh[2], kh[3]);
                }
            }

            // ---- scale + causal mask (diagonal tile only)
            #pragma unroll
            for (int nt = 0; nt < 8; nt++)
                #pragma unroll
                for (int e = 0; e < 4; e++) s[nt][e] *= 0.125f;
            if (kt == diag_kt) {
                const int r0g = wrow + (lane >> 2);
                const int r1g = r0g + 8;
                #pragma unroll
                for (int nt = 0; nt < 8; nt++) {
                    #pragma unroll
                    for (int c = 0; c < 2; c++) {
                        const int col = kt * 64 + nt * 8 + (lane & 3) * 2 + c;
                        if (col > r0g) s[nt][c] = -1e30f;
                        if (col > r1g) s[nt][2 + c] = -1e30f;
                    }
                }
            }

            // ---- online softmax (rows fully in-warp; quad shfl reduction)
            float mx0 = -1e30f, mx1 = -1e30f;
            #pragma unroll
            for (int nt = 0; nt < 8; nt++) {
                mx0 = fmaxf(mx0, fmaxf(s[nt][0], s[nt][1]));
                mx1 = fmaxf(mx1, fmaxf(s[nt][2], s[nt][3]));
            }
            mx0 = fmaxf(mx0, __shfl_xor_sync(0xffffffffu, mx0, 1));
            mx0 = fmaxf(mx0, __shfl_xor_sync(0xffffffffu, mx0, 2));
            mx1 = fmaxf(mx1, __shfl_xor_sync(0xffffffffu, mx1, 1));
            mx1 = fmaxf(mx1, __shfl_xor_sync(0xffffffffu, mx1, 2));
            const float m0n = fmaxf(m0, mx0), m1n = fmaxf(m1, mx1);
            const float f0 = __expf(m0 - m0n), f1 = __expf(m1 - m1n);
            m0 = m0n; m1 = m1n;

            float sum0 = 0.f, sum1 = 0.f;
            #pragma unroll
            for (int nt = 0; nt < 8; nt++) {
                s[nt][0] = __expf(s[nt][0] - m0n); sum0 += s[nt][0];
                s[nt][1] = __expf(s[nt][1] - m0n); sum0 += s[nt][1];
                s[nt][2] = __expf(s[nt][2] - m1n); sum1 += s[nt][2];
                s[nt][3] = __expf(s[nt][3] - m1n); sum1 += s[nt][3];
            }
            sum0 += __shfl_xor_sync(0xffffffffu, sum0, 1);
            sum0 += __shfl_xor_sync(0xffffffffu, sum0, 2);
            sum1 += __shfl_xor_sync(0xffffffffu, sum1, 1);
            sum1 += __shfl_xor_sync(0xffffffffu, sum1, 2);
            l0 = f0 * l0 + sum0;
            l1 = f1 * l1 + sum1;

            #pragma unroll
            for (int nt = 0; nt < 8; nt++) {
                acc[nt][0] *= f0; acc[nt][1] *= f0;
                acc[nt][2] *= f1; acc[nt][3] *= f1;
            }

            // ---- P fragments (C m16n8 pairs -> A m16k16), hi/lo split
            uint32_t aph[4][4], apl[4][4];
            #pragma unroll
            for (int kf = 0; kf < 4; kf++) {
                #pragma unroll
                for (int q = 0; q < 4; q++) {
                    const int t = 2 * kf + (q >> 1);
                    const int c = (q & 1) * 2;
                    const float x = s[t][c], y = s[t][c + 1];
                    const __nv_bfloat16 hx = __float2bfloat16(x);
                    const __nv_bfloat16 hy = __float2bfloat16(y);
                    __nv_bfloat162 hp(hx, hy);
                    aph[kf][q] = *(uint32_t*)&hp;
                    apl[kf][q] = pack_bf16(x - __bfloat162float(hx),
                                           y - __bfloat162float(hy));
                }
            }
            // NOTE: A frag order is a0=(r, k0-7), a1=(r+8, k0-7), a2=(r, k8-15), a3=(r+8, k8-15)
            // C frag order is c0,c1=(r), c2,c3=(r+8). Mapping above: q=0 -> (t=2kf, c0c1) = a0;
            // q=1 -> (t=2kf, c2c3) = a1; q=2 -> (t=2kf+1, c0c1) = a2; q=3 -> a3. Correct.

            // ---- O += P @ V (x3 split), V fragments via ldmatrix.trans
            #pragma unroll
            for (int kf = 0; kf < 4; kf++) {
                const int v_row = kf * 16 + ((lane >> 3) & 1) * 8 + (lane & 7);
                const int v_colb = ((lane >> 4) & 1) * 8;
                #pragma unroll
                for (int p = 0; p < 4; p++) {
                    uint32_t vh[4], vl[4];
                    ldsm_x4_t(st + 2 * FTILE + v_row * FSROW + (p * 16 + v_colb) * 2,
                              vh[0], vh[1], vh[2], vh[3]);
                    ldsm_x4_t(st + 3 * FTILE + v_row * FSROW + (p * 16 + v_colb) * 2,
                              vl[0], vl[1], vl[2], vl[3]);
                    mma16816(acc[2 * p + 0], aph[kf], vh[0], vh[1]);
                    mma16816(acc[2 * p + 1], aph[kf], vh[2], vh[3]);
                    mma16816(acc[2 * p + 0], aph[kf], vl[0], vl[1]);
                    mma16816(acc[2 * p + 1], aph[kf], vl[2], vl[3]);
                    mma16816(acc[2 * p + 0], apl[kf], vh[0], vh[1]);
                    mma16816(acc[2 * p + 1], apl[kf], vh[2], vh[3]);
                }
            }
        }
        __syncthreads();
    }

    // ---- epilogue: normalize, split to bf16 hi/lo
    const float inv0 = 1.f / l0, inv1 = 1.f / l1;
    const size_t orow0 = ((size_t)(b * TT + wrow + (lane >> 2))) * DD + h * HD;
    const size_t orow1 = orow0 + (size_t)8 * DD;
    #pragma unroll
    for (int nt = 0; nt < 8; nt++) {
        const int col = nt * 8 + (lane & 3) * 2;
        {
            const float x = acc[nt][0] * inv0, y = acc[nt][1] * inv0;
            const __nv_bfloat16 hx = __float2bfloat16(x), hy = __float2bfloat16(y);
            *(__nv_bfloat162*)&Oh_[orow0 + col] = __nv_bfloat162(hx, hy);
            *(__nv_bfloat162*)&Ol_[orow0 + col] = __nv_bfloat162(
                __float2bfloat16(x - __bfloat162float(hx)),
                __float2bfloat16(y - __bfloat162float(hy)));
        }
        {
            const float x = acc[nt][2] * inv1, y = acc[nt][3] * inv1;
            const __nv_bfloat16 hx = __float2bfloat16(x), hy = __float2bfloat16(y);
            *(__nv_bfloat162*)&Oh_[orow1 + col] = __nv_bfloat162(hx, hy);
            *(__nv_bfloat162*)&Ol_[orow1 + col] = __nv_bfloat162(
                __float2bfloat16(x - __bfloat162float(hx)),
                __float2bfloat16(y - __bfloat162float(hy)));
        }
    }
}

// ---------------------------------------------------------------------------
// Launch
// ---------------------------------------------------------------------------
extern "C" void kernel_launch(void* const* d_in, const int* in_sizes, int n_in,
                              void* d_out, int out_size) {
    const float* xq  = (const float*)d_in[0];
    const float* xkv = (const float*)d_in[1];
    const float* Wq = (const float*)d_in[3];
    const float* Wk = (const float*)d_in[4];
    const float* Wv = (const float*)d_in[5];
    const float* Wo = (const float*)d_in[6];
    float* out = (float*)d_out;

    __nv_bfloat16 *qh, *ql, *kh, *kl, *vh, *vl;
    __nv_bfloat16 *xah, *xal, *xbh, *xbl, *wth, *wtl;
    cudaGetSymbolAddress((void**)&qh, g_qh);
    cudaGetSymbolAddress((void**)&ql, g_ql);
    cudaGetSymbolAddress((void**)&kh, g_kh);
    cudaGetSymbolAddress((void**)&kl, g_kl);
    cudaGetSymbolAddress((void**)&vh, g_vh);
    cudaGetSymbolAddress((void**)&vl, g_vl);
    cudaGetSymbolAddress((void**)&xah, g_xa_h);
    cudaGetSymbolAddress((void**)&xal, g_xa_l);
    cudaGetSymbolAddress((void**)&xbh, g_xb_h);
    cudaGetSymbolAddress((void**)&xbl, g_xb_l);
    cudaGetSymbolAddress((void**)&wth, g_wt_h);
    cudaGetSymbolAddress((void**)&wtl, g_wt_l);

    cudaFuncSetAttribute(gemm_mma_kernel, cudaFuncAttributeMaxDynamicSharedMemorySize,
                         GEMM_SMEM);
    cudaFuncSetAttribute(flash_mma_kernel, cudaFuncAttributeMaxDynamicSharedMemorySize,
                         FLASH_SMEM);

    const int n4 = MROWS * DD / 4;
    aconv_kernel<<<(n4 + 255) / 256, 256>>>(xq,  xah, xal, n4);
    aconv_kernel<<<(n4 + 255) / 256, 256>>>(xkv, xbh, xbl, n4);

    dim3 wg(32, 32), wb(32, 8);
    wconv_kernel<<<wg, wb>>>(Wq, wth + 0 * DD * DD, wtl + 0 * DD * DD);
    wconv_kernel<<<wg, wb>>>(Wk, wth + 1 * DD * DD, wtl + 1 * DD * DD);
    wconv_kernel<<<wg, wb>>>(Wv, wth + 2 * DD * DD, wtl + 2 * DD * DD);
    wconv_kernel<<<wg, wb>>>(Wo, wth + 3 * DD * DD, wtl + 3 * DD * DD);

    dim3 gg(DD / 128, MROWS / 128);  // (8, 32)
    gemm_mma_kernel<<<gg, 256, GEMM_SMEM>>>(xah, xal, wth + 0 * DD * DD, wtl + 0 * DD * DD,
                                            nullptr, qh, ql, MROWS, DD, DD);
    gemm_mma_kernel<<<gg, 256, GEMM_SMEM>>>(xbh, xbl, wth + 1 * DD * DD, wtl + 1 * DD * DD,
                                            nullptr, kh, kl, MROWS, DD, DD);
    gemm_mma_kernel<<<gg, 256, GEMM_SMEM>>>(xbh, xbl, wth + 2 * DD * DD, wtl + 2 * DD * DD,
                                            nullptr, vh, vl, MROWS, DD, DD);

    // flash writes attn output splits into xa buffers (Q-GEMM already consumed them)
    flash_mma_kernel<<<dim3(TT / 128, BB * HH), 256, FLASH_SMEM>>>(
        qh, ql, kh, kl, vh, vl, xah, xal);

    gemm_mma_kernel<<<gg, 256, GEMM_SMEM>>>(xah, xal, wth + 3 * DD * DD, wtl + 3 * DD * DD,
                                            out, nullptr, nullptr, MROWS, DD, DD);
}

// round 7
// speedup vs baseline: 3.9934x; 1.4092x over previous
#include <cuda_runtime.h>
#include <cuda_fp16.h>
#include <math_constants.h>
#include <cstdint>

// Problem constants
#define BB   2
#define TT   2048
#define DD   1024
#define HH   16
#define HD   64
#define MROWS (BB*TT)        // 4096

// ---------------------------------------------------------------------------
// Scratch (device globals; allocation forbidden)
// ---------------------------------------------------------------------------
__device__ __half g_qh[MROWS * DD];
__device__ __half g_ql[MROWS * DD];
__device__ __half g_kh[MROWS * DD];            // hi only (uncompensated in S)
__device__ __half g_vh[MROWS * DD];            // hi only (uncompensated in PV)

__device__ __half g_xa_h[MROWS * DD];          // activation A hi (reused: attn out)
__device__ __half g_xa_l[MROWS * DD];
__device__ __half g_xb_h[MROWS * DD];          // kv activation hi
__device__ __half g_xb_l[MROWS * DD];
__device__ __half g_wt[4 * DD * DD];           // transposed weights hi [n][k]

// ---------------------------------------------------------------------------
// PTX helpers
// ---------------------------------------------------------------------------
__device__ __forceinline__ uint32_t smem_to_u32(const void* p) {
    uint32_t a;
    asm("{ .reg .u64 t; cvta.to.shared.u64 t, %1; cvt.u32.u64 %0, t; }"
        : "=r"(a) : "l"(p));
    return a;
}
__device__ __forceinline__ void cp_async16(uint32_t sa, const void* g) {
    asm volatile("cp.async.cg.shared.global [%0], [%1], 16;" :: "r"(sa), "l"(g));
}
__device__ __forceinline__ void cp_commit() {
    asm volatile("cp.async.commit_group;");
}
template <int N>
__device__ __forceinline__ void cp_wait() {
    asm volatile("cp.async.wait_group %0;" :: "n"(N));
}
__device__ __forceinline__ void ldsm_x4(uint32_t addr, uint32_t& r0, uint32_t& r1,
                                        uint32_t& r2, uint32_t& r3) {
    asm volatile("ldmatrix.sync.aligned.m8n8.x4.shared.b16 {%0,%1,%2,%3}, [%4];"
                 : "=r"(r0), "=r"(r1), "=r"(r2), "=r"(r3) : "r"(addr));
}
__device__ __forceinline__ void ldsm_x4_t(uint32_t addr, uint32_t& r0, uint32_t& r1,
                                          uint32_t& r2, uint32_t& r3) {
    asm volatile("ldmatrix.sync.aligned.m8n8.x4.trans.shared.b16 {%0,%1,%2,%3}, [%4];"
                 : "=r"(r0), "=r"(r1), "=r"(r2), "=r"(r3) : "r"(addr));
}
__device__ __forceinline__ void mma16816(float* c, const uint32_t* a,
                                         uint32_t b0, uint32_t b1) {
    asm volatile(
        "mma.sync.aligned.m16n8k16.row.col.f32.f16.f16.f32 "
        "{%0,%1,%2,%3}, {%4,%5,%6,%7}, {%8,%9}, {%0,%1,%2,%3};"
        : "+f"(c[0]), "+f"(c[1]), "+f"(c[2]), "+f"(c[3])
        : "r"(a[0]), "r"(a[1]), "r"(a[2]), "r"(a[3]), "r"(b0), "r"(b1));
}
__device__ __forceinline__ uint32_t pack_half2(float x, float y) {
    __half2 v(__float2half(x), __float2half(y));
    return *(uint32_t*)&v;
}

// ---------------------------------------------------------------------------
// Activation fp32 -> (hi, lo) fp16 split
// ---------------------------------------------------------------------------
__global__ __launch_bounds__(256)
void aconv_kernel(const float* __restrict__ X, __half* __restrict__ Xh,
                  __half* __restrict__ Xl, int n4) {
    int i = blockIdx.x * blockDim.x + threadIdx.x;
    if (i >= n4) return;
    float4 v = ((const float4*)X)[i];
    __half h0 = __float2half(v.x), h1 = __float2half(v.y);
    __half h2 = __float2half(v.z), h3 = __float2half(v.w);
    __half l0 = __float2half(v.x - __half2float(h0));
    __half l1 = __float2half(v.y - __half2float(h1));
    __half l2 = __float2half(v.z - __half2float(h2));
    __half l3 = __float2half(v.w - __half2float(h3));
    ((__half2*)Xh)[i * 2 + 0] = __half2(h0, h1);
    ((__half2*)Xh)[i * 2 + 1] = __half2(h2, h3);
    ((__half2*)Xl)[i * 2 + 0] = __half2(l0, l1);
    ((__half2*)Xl)[i * 2 + 1] = __half2(l2, l3);
}

// ---------------------------------------------------------------------------
// Weight transpose + fp16 round: W[k][n] fp32 -> Wt[n][k] fp16 hi only.
// grid (32, 32, 4): z selects source weight + destination slot.
// ---------------------------------------------------------------------------
__global__ __launch_bounds__(256)
void wconv_kernel(const float* __restrict__ W0, const float* __restrict__ W1,
                  const float* __restrict__ W2, const float* __restrict__ W3,
                  __half* __restrict__ T) {
    __shared__ float t[32][33];
    const int z = blockIdx.z;
    const float* W = (z == 0) ? W0 : (z == 1) ? W1 : (z == 2) ? W2 : W3;
    __half* Th = T + (size_t)z * DD * DD;
    const int tx = threadIdx.x, ty = threadIdx.y;
    const int k0 = blockIdx.y * 32, n0 = blockIdx.x * 32;
    #pragma unroll
    for (int i = 0; i < 4; i++)
        t[ty + 8 * i][tx] = W[(size_t)(k0 + ty + 8 * i) * DD + n0 + tx];
    __syncthreads();
    #pragma unroll
    for (int i = 0; i < 4; i++) {
        Th[(size_t)(n0 + ty + 8 * i) * DD + k0 + tx] =
            __float2half(t[tx][ty + 8 * i]);
    }
}

// ---------------------------------------------------------------------------
// fp16 2-product GEMM mainloop (shared by QKV + Wo kernels).
// C = (Ah+Al)[M,K] @ Bh[K,N]; Bh pre-transposed [N,K].
// CTA tile 128x128, 8 warps, K-chunk 32, cp.async double buffer, 3 smem mats.
// ---------------------------------------------------------------------------
#define KC        32
#define SROW      80                       // 32 fp16 = 64B + 16B pad
#define MAT_B     (128 * SROW)             // 10240
#define G_STAGE   (3 * MAT_B)              // 30720
#define GEMM_SMEM (2 * G_STAGE)            // 61440

__device__ __forceinline__ void gemm2_mainloop(
    const __half* __restrict__ Ah, const __half* __restrict__ Al,
    const __half* __restrict__ Bh, int bm, int bn, int K,
    uint32_t sbase, int tid, float acc[2][8][4]) {
    const int lane = tid & 31;
    const int wid = tid >> 5;
    const int wm = wid >> 1;
    const int wn = wid & 1;
    const int nchunks = K / KC;

    auto load_chunk = [&](int c) {
        const int k0 = c * KC;
        const uint32_t st = sbase + (c & 1) * G_STAGE;
        #pragma unroll
        for (int t = 0; t < 6; t++) {
            const int mat = t >> 1;
            const int row = (t & 1) * 64 + (tid >> 2);
            const __half* src = (mat == 0) ? Ah : (mat == 1) ? Al : Bh;
            const int grow = ((mat < 2) ? bm : bn) + row;
            cp_async16(st + mat * MAT_B + row * SROW + (tid & 3) * 16,
                       src + (size_t)grow * K + k0 + (tid & 3) * 8);
        }
        cp_commit();
    };

    const int a_row = wm * 32 + (lane & 15);
    const int a_col = (lane >> 4) * 8;
    const int b_row = wn * 64 + ((lane >> 4) & 1) * 8 + (lane & 7);
    const int b_col = ((lane >> 3) & 1) * 8;

    load_chunk(0);

    for (int c = 0; c < nchunks; c++) {
        if (c + 1 < nchunks) { load_chunk(c + 1); cp_wait<1>(); }
        else cp_wait<0>();
        __syncthreads();

        const uint32_t st = sbase + (c & 1) * G_STAGE;
        #pragma unroll
        for (int kstep = 0; kstep < 2; kstep++) {
            uint32_t ah[2][4], al[2][4], bh[4][4];
            #pragma unroll
            for (int mt = 0; mt < 2; mt++) {
                ldsm_x4(st + 0 * MAT_B + (a_row + mt * 16) * SROW + (a_col + kstep * 16) * 2,
                        ah[mt][0], ah[mt][1], ah[mt][2], ah[mt][3]);
                ldsm_x4(st + 1 * MAT_B + (a_row + mt * 16) * SROW + (a_col + kstep * 16) * 2,
                        al[mt][0], al[mt][1], al[mt][2], al[mt][3]);
            }
            #pragma unroll
            for (int p = 0; p < 4; p++) {
                ldsm_x4(st + 2 * MAT_B + (b_row + p * 16) * SROW + (b_col + kstep * 16) * 2,
                        bh[p][0], bh[p][1], bh[p][2], bh[p][3]);
            }
            #pragma unroll
            for (int mt = 0; mt < 2; mt++) {
                #pragma unroll
                for (int p = 0; p < 4; p++) {
                    mma16816(acc[mt][2 * p + 0], ah[mt], bh[p][0], bh[p][1]);
                    mma16816(acc[mt][2 * p + 1], ah[mt], bh[p][2], bh[p][3]);
                    mma16816(acc[mt][2 * p + 0], al[mt], bh[p][0], bh[p][1]);
                    mma16816(acc[mt][2 * p + 1], al[mt], bh[p][2], bh[p][3]);
                }
            }
        }
        __syncthreads();
    }
}

// Fused QKV GEMM: grid (8, 32, 3). z=0: Q (h/l out), z=1: K (h), z=2: V (h).
__global__ __launch_bounds__(256, 1)
void qkv_mma_kernel(const __half* __restrict__ xah, const __half* __restrict__ xal,
                    const __half* __restrict__ xbh, const __half* __restrict__ xbl,
                    const __half* __restrict__ Wt,
                    __half* __restrict__ Qh, __half* __restrict__ Ql,
                    __half* __restrict__ Kh, __half* __restrict__ Vh) {
    extern __shared__ char smem[];
    const uint32_t sbase = smem_to_u32(smem);
    const int tid = threadIdx.x;
    const int z = blockIdx.z;
    const int bm = blockIdx.y * 128;
    const int bn = blockIdx.x * 128;

    const __half* Ah = (z == 0) ? xah : xbh;
    const __half* Al = (z == 0) ? xal : xbl;
    const __half* Bh = Wt + (size_t)z * DD * DD;

    float acc[2][8][4];
    #pragma unroll
    for (int i = 0; i < 2; i++)
        #pragma unroll
        for (int j = 0; j < 8; j++)
            #pragma unroll
            for (int q = 0; q < 4; q++) acc[i][j][q] = 0.f;

    gemm2_mainloop(Ah, Al, Bh, bm, bn, DD, sbase, tid, acc);

    const int lane = tid & 31, wid = tid >> 5;
    const int wm = wid >> 1, wn = wid & 1;
    const int er = lane >> 2, ec = (lane & 3) * 2;
    #pragma unroll
    for (int mt = 0; mt < 2; mt++) {
        const int row0 = bm + wm * 32 + mt * 16 + er;
        #pragma unroll
        for (int nt = 0; nt < 8; nt++) {
            const int col = bn + wn * 64 + nt * 8 + ec;
            #pragma unroll
            for (int half_ = 0; half_ < 2; half_++) {
                const size_t o = (size_t)(row0 + half_ * 8) * DD + col;
                const float x = acc[mt][nt][2 * half_];
                const float y = acc[mt][nt][2 * half_ + 1];
                const __half hx = __float2half(x), hy = __float2half(y);
                if (z == 0) {
                    *(__half2*)&Qh[o] = __half2(hx, hy);
                    *(__half2*)&Ql[o] = __half2(
                        __float2half(x - __half2float(hx)),
                        __float2half(y - __half2float(hy)));
                } else {
                    __half* dst = (z == 1) ? Kh : Vh;
                    *(__half2*)&dst[o] = __half2(hx, hy);
                }
            }
        }
    }
}

// Wo GEMM: fp32 out.
__global__ __launch_bounds__(256, 1)
void wo_mma_kernel(const __half* __restrict__ Ah, const __half* __restrict__ Al,
                   const __half* __restrict__ Bh, float* __restrict__ C) {
    extern __shared__ char smem[];
    const uint32_t sbase = smem_to_u32(smem);
    const int tid = threadIdx.x;
    const int bm = blockIdx.y * 128;
    const int bn = blockIdx.x * 128;

    float acc[2][8][4];
    #pragma unroll
    for (int i = 0; i < 2; i++)
        #pragma unroll
        for (int j = 0; j < 8; j++)
            #pragma unroll
            for (int q = 0; q < 4; q++) acc[i][j][q] = 0.f;

    gemm2_mainloop(Ah, Al, Bh, bm, bn, DD, sbase, tid, acc);

    const int lane = tid & 31, wid = tid >> 5;
    const int wm = wid >> 1, wn = wid & 1;
    const int er = lane >> 2, ec = (lane & 3) * 2;
    #pragma unroll
    for (int mt = 0; mt < 2; mt++) {
        const int row0 = bm + wm * 32 + mt * 16 + er;
        #pragma unroll
        for (int nt = 0; nt < 8; nt++) {
            const int col = bn + wn * 64 + nt * 8 + ec;
            *(float2*)&C[(size_t)row0 * DD + col] =
                make_float2(acc[mt][nt][0], acc[mt][nt][1]);
            *(float2*)&C[(size_t)(row0 + 8) * DD + col] =
                make_float2(acc[mt][nt][2], acc[mt][nt][3]);
        }
    }
}

// ---------------------------------------------------------------------------
// Flash attention with fp16 mma (causal). BQ=128, BKV=64, HD=64.
// S = (Qh+Ql)·Kh^T; PV = (Ph+Pl)·Vh. 8 warps, 16 rows each (stats in-warp).
// ---------------------------------------------------------------------------
#define FSROW  144                          // 64 fp16 = 128B + 16B pad
#define FTILE  (64 * FSROW)                 // 9216
#define FSTAGE (2 * FTILE)                  // 18432 (Kh, Vh)
#define FLASH_SMEM (2 * FSTAGE)             // 36864 (Q stage fits in same space)

__global__ __launch_bounds__(256, 1)
void flash_mma_kernel(const __half* __restrict__ Qh_, const __half* __restrict__ Ql_,
                      const __half* __restrict__ Kh_, const __half* __restrict__ Vh_,
                      __half* __restrict__ Oh_, __half* __restrict__ Ol_) {
    extern __shared__ char smem[];
    const uint32_t sbase = smem_to_u32(smem);
    const int qb = (int)gridDim.x - 1 - (int)blockIdx.x;   // heavy first
    const int bh = blockIdx.y;
    const int b = bh >> 4, h = bh & 15;
    const int tid = threadIdx.x, lane = tid & 31, wid = tid >> 5;
    const int wrow = qb * 128 + wid * 16;

    // ---- Stage Q (hi at 0, lo at 128*FSROW), extract fragments
    {
        const size_t gq = ((size_t)(b * TT + qb * 128)) * DD + h * HD;
        #pragma unroll
        for (int t = 0; t < 8; t++) {
            const int mat = t >> 2;
            const int row = (t & 3) * 32 + (tid >> 3);
            const __half* src = mat ? Ql_ : Qh_;
            cp_async16(sbase + mat * (128 * FSROW) + row * FSROW + (tid & 7) * 16,
                       src + gq + (size_t)row * DD + (tid & 7) * 8);
        }
        cp_commit(); cp_wait<0>();
        __syncthreads();
    }
    uint32_t qh[4][4], ql[4][4];
    {
        const int a_row = wid * 16 + (lane & 15);
        const int a_col = (lane >> 4) * 8;
        #pragma unroll
        for (int ks = 0; ks < 4; ks++) {
            ldsm_x4(sbase + a_row * FSROW + (a_col + ks * 16) * 2,
                    qh[ks][0], qh[ks][1], qh[ks][2], qh[ks][3]);
            ldsm_x4(sbase + 128 * FSROW + a_row * FSROW + (a_col + ks * 16) * 2,
                    ql[ks][0], ql[ks][1], ql[ks][2], ql[ks][3]);
        }
    }
    __syncthreads();

    // ---- KV loader (Kh + Vh only, double buffered)
    const size_t gkv = ((size_t)(b * TT)) * DD + h * HD;
    auto load_kv = [&](int kt) {
        const uint32_t st = sbase + (kt & 1) * FSTAGE;
        const size_t base = gkv + (size_t)(kt * 64) * DD;
        #pragma unroll
        for (int t = 0; t < 4; t++) {
            const int mat = t >> 1;
            const int row = (t & 1) * 32 + (tid >> 3);
            const __half* src = mat ? Vh_ : Kh_;
            cp_async16(st + mat * FTILE + row * FSROW + (tid & 7) * 16,
                       src + base + (size_t)row * DD + (tid & 7) * 8);
        }
        cp_commit();
    };

    float acc[8][4];
    #pragma unroll
    for (int i = 0; i < 8; i++)
        #pragma unroll
        for (int j = 0; j < 4; j++) acc[i][j] = 0.f;
    float m0 = -CUDART_INF_F, m1 = -CUDART_INF_F, l0 = 0.f, l1 = 0.f;

    const int ntiles = 2 * qb + 2;
    const int diag_kt = wrow >> 6;
    const int b_row = ((lane >> 4) & 1) * 8 + (lane & 7);
    const int b_col = ((lane >> 3) & 1) * 8;

    load_kv(0);

    for (int kt = 0; kt < ntiles; kt++) {
        if (kt + 1 < ntiles) { load_kv(kt + 1); cp_wait<1>(); }
        else cp_wait<0>();
        __syncthreads();

        const uint32_t st = sbase + (kt & 1) * FSTAGE;
        if (kt * 64 <= wrow) {
            // ---- S = (Qh+Ql) @ Kh^T
            float s[8][4];
            #pragma unroll
            for (int i = 0; i < 8; i++)
                #pragma unroll
                for (int j = 0; j < 4; j++) s[i][j] = 0.f;

            #pragma unroll
            for (int ks = 0; ks < 4; ks++) {
                #pragma unroll
                for (int p = 0; p < 4; p++) {
                    uint32_t kh[4];
                    ldsm_x4(st + (b_row + p * 16) * FSROW + (b_col + ks * 16) * 2,
                            kh[0], kh[1], kh[2], kh[3]);
                    mma16816(s[2 * p + 0], qh[ks], kh[0], kh[1]);
                    mma16816(s[2 * p + 1], qh[ks], kh[2], kh[3]);
                    mma16816(s[2 * p + 0], ql[ks], kh[0], kh[1]);
                    mma16816(s[2 * p + 1], ql[ks], kh[2], kh[3]);
                }
            }

            // ---- scale + causal mask
            #pragma unroll
            for (int nt = 0; nt < 8; nt++)
                #pragma unroll
                for (int e = 0; e < 4; e++) s[nt][e] *= 0.125f;
            if (kt == diag_kt) {
                const int r0g = wrow + (lane >> 2);
                const int r1g = r0g + 8;
                #pragma unroll
                for (int nt = 0; nt < 8; nt++) {
                    #pragma unroll
                    for (int c = 0; c < 2; c++) {
                        const int col = kt * 64 + nt * 8 + (lane & 3) * 2 + c;
                        if (col > r0g) s[nt][c] = -1e30f;
                        if (col > r1g) s[nt][2 + c] = -1e30f;
                    }
                }
            }

            // ---- online softmax (in-warp quad reduction)
            float mx0 = -1e30f, mx1 = -1e30f;
            #pragma unroll
            for (int nt = 0; nt < 8; nt++) {
                mx0 = fmaxf(mx0, fmaxf(s[nt][0], s[nt][1]));
                mx1 = fmaxf(mx1, fmaxf(s[nt][2], s[nt][3]));
            }
            mx0 = fmaxf(mx0, __shfl_xor_sync(0xffffffffu, mx0, 1));
            mx0 = fmaxf(mx0, __shfl_xor_sync(0xffffffffu, mx0, 2));
            mx1 = fmaxf(mx1, __shfl_xor_sync(0xffffffffu, mx1, 1));
            mx1 = fmaxf(mx1, __shfl_xor_sync(0xffffffffu, mx1, 2));
            const float m0n = fmaxf(m0, mx0), m1n = fmaxf(m1, mx1);
            const float f0 = __expf(m0 - m0n), f1 = __expf(m1 - m1n);
            m0 = m0n; m1 = m1n;

            float sum0 = 0.f, sum1 = 0.f;
            #pragma unroll
            for (int nt = 0; nt < 8; nt++) {
                s[nt][0] = __expf(s[nt][0] - m0n); sum0 += s[nt][0];
                s[nt][1] = __expf(s[nt][1] - m0n); sum0 += s[nt][1];
                s[nt][2] = __expf(s[nt][2] - m1n); sum1 += s[nt][2];
                s[nt][3] = __expf(s[nt][3] - m1n); sum1 += s[nt][3];
            }
            sum0 += __shfl_xor_sync(0xffffffffu, sum0, 1);
            sum0 += __shfl_xor_sync(0xffffffffu, sum0, 2);
            sum1 += __shfl_xor_sync(0xffffffffu, sum1, 1);
            sum1 += __shfl_xor_sync(0xffffffffu, sum1, 2);
            l0 = f0 * l0 + sum0;
            l1 = f1 * l1 + sum1;

            #pragma unroll
            for (int nt = 0; nt < 8; nt++) {
                acc[nt][0] *= f0; acc[nt][1] *= f0;
                acc[nt][2] *= f1; acc[nt][3] *= f1;
            }

            // ---- P fragments: fp16 hi + residual lo (C->A frag remap)
            uint32_t aph[4][4], apl[4][4];
            #pragma unroll
            for (int kf = 0; kf < 4; kf++) {
                #pragma unroll
                for (int q = 0; q < 4; q++) {
                    const int t = 2 * kf + (q >> 1);
                    const int c = (q & 1) * 2;
                    const float x = s[t][c], y = s[t][c + 1];
                    const __half hx = __float2half(x), hy = __float2half(y);
                    __half2 hp(hx, hy);
                    aph[kf][q] = *(uint32_t*)&hp;
                    apl[kf][q] = pack_half2(x - __half2float(hx),
                                            y - __half2float(hy));
                }
            }

            // ---- O += (Ph+Pl) @ Vh (trans ldmatrix)
            #pragma unroll
            for (int kf = 0; kf < 4; kf++) {
                const int v_row = kf * 16 + ((lane >> 3) & 1) * 8 + (lane & 7);
                const int v_colb = ((lane >> 4) & 1) * 8;
                #pragma unroll
                for (int p = 0; p < 4; p++) {
                    uint32_t vh[4];
                    ldsm_x4_t(st + FTILE + v_row * FSROW + (p * 16 + v_colb) * 2,
                              vh[0], vh[1], vh[2], vh[3]);
                    mma16816(acc[2 * p + 0], aph[kf], vh[0], vh[1]);
                    mma16816(acc[2 * p + 1], aph[kf], vh[2], vh[3]);
                    mma16816(acc[2 * p + 0], apl[kf], vh[0], vh[1]);
                    mma16816(acc[2 * p + 1], apl[kf], vh[2], vh[3]);
                }
            }
        }
        __syncthreads();
    }

    // ---- epilogue: normalize, fp16 hi/lo split for Wo GEMM
    const float inv0 = 1.f / l0, inv1 = 1.f / l1;
    const size_t orow0 = ((size_t)(b * TT + wrow + (lane >> 2))) * DD + h * HD;
    const size_t orow1 = orow0 + (size_t)8 * DD;
    #pragma unroll
    for (int nt = 0; nt < 8; nt++) {
        const int col = nt * 8 + (lane & 3) * 2;
        {
            const float x = acc[nt][0] * inv0, y = acc[nt][1] * inv0;
            const __half hx = __float2half(x), hy = __float2half(y);
            *(__half2*)&Oh_[orow0 + col] = __half2(hx, hy);
            *(__half2*)&Ol_[orow0 + col] = __half2(
                __float2half(x - __half2float(hx)),
                __float2half(y - __half2float(hy)));
        }
        {
            const float x = acc[nt][2] * inv1, y = acc[nt][3] * inv1;
            const __half hx = __float2half(x), hy = __float2half(y);
            *(__half2*)&Oh_[orow1 + col] = __half2(hx, hy);
            *(__half2*)&Ol_[orow1 + col] = __half2(
                __float2half(x - __half2float(hx)),
                __float2half(y - __half2float(hy)));
        }
    }
}

// ---------------------------------------------------------------------------
// Launch
// ---------------------------------------------------------------------------
extern "C" void kernel_launch(void* const* d_in, const int* in_sizes, int n_in,
                              void* d_out, int out_size) {
    const float* xq  = (const float*)d_in[0];
    const float* xkv = (const float*)d_in[1];
    const float* Wq = (const float*)d_in[3];
    const float* Wk = (const float*)d_in[4];
    const float* Wv = (const float*)d_in[5];
    const float* Wo = (const float*)d_in[6];
    float* out = (float*)d_out;

    __half *qh, *ql, *kh, *vh, *xah, *xal, *xbh, *xbl, *wt;
    cudaGetSymbolAddress((void**)&qh, g_qh);
    cudaGetSymbolAddress((void**)&ql, g_ql);
    cudaGetSymbolAddress((void**)&kh, g_kh);
    cudaGetSymbolAddress((void**)&vh, g_vh);
    cudaGetSymbolAddress((void**)&xah, g_xa_h);
    cudaGetSymbolAddress((void**)&xal, g_xa_l);
    cudaGetSymbolAddress((void**)&xbh, g_xb_h);
    cudaGetSymbolAddress((void**)&xbl, g_xb_l);
    cudaGetSymbolAddress((void**)&wt, g_wt);

    cudaFuncSetAttribute(qkv_mma_kernel, cudaFuncAttributeMaxDynamicSharedMemorySize,
                         GEMM_SMEM);
    cudaFuncSetAttribute(wo_mma_kernel, cudaFuncAttributeMaxDynamicSharedMemorySize,
                         GEMM_SMEM);
    cudaFuncSetAttribute(flash_mma_kernel, cudaFuncAttributeMaxDynamicSharedMemorySize,
                         FLASH_SMEM);

    const int n4 = MROWS * DD / 4;
    aconv_kernel<<<(n4 + 255) / 256, 256>>>(xq,  xah, xal, n4);
    aconv_kernel<<<(n4 + 255) / 256, 256>>>(xkv, xbh, xbl, n4);
    wconv_kernel<<<dim3(32, 32, 4), dim3(32, 8)>>>(Wq, Wk, Wv, Wo, wt);

    qkv_mma_kernel<<<dim3(DD / 128, MROWS / 128, 3), 256, GEMM_SMEM>>>(
        xah, xal, xbh, xbl, wt, qh, ql, kh, vh);

    flash_mma_kernel<<<dim3(TT / 128, BB * HH), 256, FLASH_SMEM>>>(
        qh, ql, kh, vh, xah, xal);

    wo_mma_kernel<<<dim3(DD / 128, MROWS / 128), 256, GEMM_SMEM>>>(
        xah, xal, wt + (size_t)3 * DD * DD, out);
}

// round 8
// speedup vs baseline: 4.4301x; 1.1094x over previous
#include <cuda_runtime.h>
#include <cuda_fp16.h>
#include <math_constants.h>
#include <cstdint>

// Problem constants
#define BB   2
#define TT   2048
#define DD   1024
#define HH   16
#define HD   64
#define MROWS (BB*TT)        // 4096

// ---------------------------------------------------------------------------
// Scratch (device globals; allocation forbidden)
// ---------------------------------------------------------------------------
__device__ __half g_qh[MROWS * DD];
__device__ __half g_ql[MROWS * DD];
__device__ __half g_kh[MROWS * DD];            // hi only (uncompensated in S)
__device__ __half g_vh[MROWS * DD];            // hi only (uncompensated in PV)

__device__ __half g_xa_h[MROWS * DD];          // activation A hi (reused: attn out)
__device__ __half g_xa_l[MROWS * DD];
__device__ __half g_xb_h[MROWS * DD];          // kv activation hi
__device__ __half g_xb_l[MROWS * DD];
__device__ __half g_wt[4 * DD * DD];           // transposed weights hi [n][k]

// ---------------------------------------------------------------------------
// PTX helpers
// ---------------------------------------------------------------------------
__device__ __forceinline__ uint32_t smem_to_u32(const void* p) {
    uint32_t a;
    asm("{ .reg .u64 t; cvta.to.shared.u64 t, %1; cvt.u32.u64 %0, t; }"
        : "=r"(a) : "l"(p));
    return a;
}
__device__ __forceinline__ void cp_async16(uint32_t sa, const void* g) {
    asm volatile("cp.async.cg.shared.global [%0], [%1], 16;" :: "r"(sa), "l"(g));
}
__device__ __forceinline__ void cp_commit() {
    asm volatile("cp.async.commit_group;");
}
template <int N>
__device__ __forceinline__ void cp_wait() {
    asm volatile("cp.async.wait_group %0;" :: "n"(N));
}
__device__ __forceinline__ void ldsm_x4(uint32_t addr, uint32_t& r0, uint32_t& r1,
                                        uint32_t& r2, uint32_t& r3) {
    asm volatile("ldmatrix.sync.aligned.m8n8.x4.shared.b16 {%0,%1,%2,%3}, [%4];"
                 : "=r"(r0), "=r"(r1), "=r"(r2), "=r"(r3) : "r"(addr));
}
__device__ __forceinline__ void ldsm_x4_t(uint32_t addr, uint32_t& r0, uint32_t& r1,
                                          uint32_t& r2, uint32_t& r3) {
    asm volatile("ldmatrix.sync.aligned.m8n8.x4.trans.shared.b16 {%0,%1,%2,%3}, [%4];"
                 : "=r"(r0), "=r"(r1), "=r"(r2), "=r"(r3) : "r"(addr));
}
__device__ __forceinline__ void mma16816(float* c, const uint32_t* a,
                                         uint32_t b0, uint32_t b1) {
    asm volatile(
        "mma.sync.aligned.m16n8k16.row.col.f32.f16.f16.f32 "
        "{%0,%1,%2,%3}, {%4,%5,%6,%7}, {%8,%9}, {%0,%1,%2,%3};"
        : "+f"(c[0]), "+f"(c[1]), "+f"(c[2]), "+f"(c[3])
        : "r"(a[0]), "r"(a[1]), "r"(a[2]), "r"(a[3]), "r"(b0), "r"(b1));
}
__device__ __forceinline__ uint32_t pack_half2(float x, float y) {
    __half2 v(__float2half(x), __float2half(y));
    return *(uint32_t*)&v;
}

// ---------------------------------------------------------------------------
// Activation fp32 -> (hi, lo) fp16 split
// ---------------------------------------------------------------------------
__global__ __launch_bounds__(256)
void aconv_kernel(const float* __restrict__ X, __half* __restrict__ Xh,
                  __half* __restrict__ Xl, int n4) {
    int i = blockIdx.x * blockDim.x + threadIdx.x;
    if (i >= n4) return;
    float4 v = ((const float4*)X)[i];
    __half h0 = __float2half(v.x), h1 = __float2half(v.y);
    __half h2 = __float2half(v.z), h3 = __float2half(v.w);
    __half l0 = __float2half(v.x - __half2float(h0));
    __half l1 = __float2half(v.y - __half2float(h1));
    __half l2 = __float2half(v.z - __half2float(h2));
    __half l3 = __float2half(v.w - __half2float(h3));
    ((__half2*)Xh)[i * 2 + 0] = __half2(h0, h1);
    ((__half2*)Xh)[i * 2 + 1] = __half2(h2, h3);
    ((__half2*)Xl)[i * 2 + 0] = __half2(l0, l1);
    ((__half2*)Xl)[i * 2 + 1] = __half2(l2, l3);
}

// ---------------------------------------------------------------------------
// Weight transpose + fp16 round: W[k][n] fp32 -> Wt[n][k] fp16 hi only.
// ---------------------------------------------------------------------------
__global__ __launch_bounds__(256)
void wconv_kernel(const float* __restrict__ W0, const float* __restrict__ W1,
                  const float* __restrict__ W2, const float* __restrict__ W3,
                  __half* __restrict__ T) {
    __shared__ float t[32][33];
    const int z = blockIdx.z;
    const float* W = (z == 0) ? W0 : (z == 1) ? W1 : (z == 2) ? W2 : W3;
    __half* Th = T + (size_t)z * DD * DD;
    const int tx = threadIdx.x, ty = threadIdx.y;
    const int k0 = blockIdx.y * 32, n0 = blockIdx.x * 32;
    #pragma unroll
    for (int i = 0; i < 4; i++)
        t[ty + 8 * i][tx] = W[(size_t)(k0 + ty + 8 * i) * DD + n0 + tx];
    __syncthreads();
    #pragma unroll
    for (int i = 0; i < 4; i++) {
        Th[(size_t)(n0 + ty + 8 * i) * DD + k0 + tx] =
            __float2half(t[tx][ty + 8 * i]);
    }
}

// ---------------------------------------------------------------------------
// fp16 2-product GEMM mainloop. C = (Ah+Al)[M,K] @ Bh[K,N]; Bh [N,K].
// CTA tile 128x128, 8 warps. K-chunk 64, 3-stage cp.async, ONE sync/chunk.
// ---------------------------------------------------------------------------
#define KC        64
#define SROW      144                      // 64 fp16 = 128B + 16B pad
#define MAT_B     (128 * SROW)             // 18432
#define G_STAGE   (3 * MAT_B)              // 55296
#define GEMM_SMEM (3 * G_STAGE)            // 165888

__device__ __forceinline__ void gemm2_mainloop(
    const __half* __restrict__ Ah, const __half* __restrict__ Al,
    const __half* __restrict__ Bh, int bm, int bn, int K,
    uint32_t sbase, int tid, float acc[2][8][4]) {
    const int lane = tid & 31;
    const int wid = tid >> 5;
    const int wm = wid >> 1;
    const int wn = wid & 1;
    const int nchunks = K / KC;            // 16

    // 12 x 16B transfers per thread per chunk (3 mats * 128 rows * 128B)
    const int lrow = tid >> 3;             // 0..31 (+32*g)
    const int lseg = tid & 7;              // 16B segment in 128B row

    auto load_chunk = [&](int c) {
        const int k0 = c * KC;
        const uint32_t st = sbase + (c % 3) * G_STAGE;
        #pragma unroll
        for (int t = 0; t < 12; t++) {
            const int mat = t >> 2;
            const int row = (t & 3) * 32 + lrow;
            const __half* src = (mat == 0) ? Ah : (mat == 1) ? Al : Bh;
            const int grow = ((mat < 2) ? bm : bn) + row;
            cp_async16(st + mat * MAT_B + row * SROW + lseg * 16,
                       src + (size_t)grow * K + k0 + lseg * 8);
        }
        cp_commit();
    };

    const int a_row = wm * 32 + (lane & 15);
    const int a_col = (lane >> 4) * 8;
    const int b_row = wn * 64 + ((lane >> 4) & 1) * 8 + (lane & 7);
    const int b_col = ((lane >> 3) & 1) * 8;

    load_chunk(0);
    load_chunk(1);

    for (int c = 0; c < nchunks; c++) {
        if (c + 1 < nchunks) cp_wait<1>();
        else cp_wait<0>();
        __syncthreads();
        // Safe to overwrite stage (c+2)%3: it was consumed at iter c-1,
        // and the barrier above guarantees all warps finished iter c-1.
        if (c + 2 < nchunks) load_chunk(c + 2);

        const uint32_t st = sbase + (c % 3) * G_STAGE;
        #pragma unroll
        for (int kstep = 0; kstep < 4; kstep++) {
            uint32_t ah[2][4], al[2][4], bh[4][4];
            #pragma unroll
            for (int mt = 0; mt < 2; mt++) {
                ldsm_x4(st + 0 * MAT_B + (a_row + mt * 16) * SROW + (a_col + kstep * 16) * 2,
                        ah[mt][0], ah[mt][1], ah[mt][2], ah[mt][3]);
                ldsm_x4(st + 1 * MAT_B + (a_row + mt * 16) * SROW + (a_col + kstep * 16) * 2,
                        al[mt][0], al[mt][1], al[mt][2], al[mt][3]);
            }
            #pragma unroll
            for (int p = 0; p < 4; p++) {
                ldsm_x4(st + 2 * MAT_B + (b_row + p * 16) * SROW + (b_col + kstep * 16) * 2,
                        bh[p][0], bh[p][1], bh[p][2], bh[p][3]);
            }
            #pragma unroll
            for (int mt = 0; mt < 2; mt++) {
                #pragma unroll
                for (int p = 0; p < 4; p++) {
                    mma16816(acc[mt][2 * p + 0], ah[mt], bh[p][0], bh[p][1]);
                    mma16816(acc[mt][2 * p + 1], ah[mt], bh[p][2], bh[p][3]);
                    mma16816(acc[mt][2 * p + 0], al[mt], bh[p][0], bh[p][1]);
                    mma16816(acc[mt][2 * p + 1], al[mt], bh[p][2], bh[p][3]);
                }
            }
        }
    }
}

// Fused QKV GEMM: grid (8, 32, 3). z=0: Q (h/l out), z=1: K (h), z=2: V (h).
__global__ __launch_bounds__(256, 1)
void qkv_mma_kernel(const __half* __restrict__ xah, const __half* __restrict__ xal,
                    const __half* __restrict__ xbh, const __half* __restrict__ xbl,
                    const __half* __restrict__ Wt,
                    __half* __restrict__ Qh, __half* __restrict__ Ql,
                    __half* __restrict__ Kh, __half* __restrict__ Vh) {
    extern __shared__ char smem[];
    const uint32_t sbase = smem_to_u32(smem);
    const int tid = threadIdx.x;
    const int z = blockIdx.z;
    const int bm = blockIdx.y * 128;
    const int bn = blockIdx.x * 128;

    const __half* Ah = (z == 0) ? xah : xbh;
    const __half* Al = (z == 0) ? xal : xbl;
    const __half* Bh = Wt + (size_t)z * DD * DD;

    float acc[2][8][4];
    #pragma unroll
    for (int i = 0; i < 2; i++)
        #pragma unroll
        for (int j = 0; j < 8; j++)
            #pragma unroll
            for (int q = 0; q < 4; q++) acc[i][j][q] = 0.f;

    gemm2_mainloop(Ah, Al, Bh, bm, bn, DD, sbase, tid, acc);

    const int lane = tid & 31, wid = tid >> 5;
    const int wm = wid >> 1, wn = wid & 1;
    const int er = lane >> 2, ec = (lane & 3) * 2;
    #pragma unroll
    for (int mt = 0; mt < 2; mt++) {
        const int row0 = bm + wm * 32 + mt * 16 + er;
        #pragma unroll
        for (int nt = 0; nt < 8; nt++) {
            const int col = bn + wn * 64 + nt * 8 + ec;
            #pragma unroll
            for (int half_ = 0; half_ < 2; half_++) {
                const size_t o = (size_t)(row0 + half_ * 8) * DD + col;
                const float x = acc[mt][nt][2 * half_];
                const float y = acc[mt][nt][2 * half_ + 1];
                const __half hx = __float2half(x), hy = __float2half(y);
                if (z == 0) {
                    *(__half2*)&Qh[o] = __half2(hx, hy);
                    *(__half2*)&Ql[o] = __half2(
                        __float2half(x - __half2float(hx)),
                        __float2half(y - __half2float(hy)));
                } else {
                    __half* dst = (z == 1) ? Kh : Vh;
                    *(__half2*)&dst[o] = __half2(hx, hy);
                }
            }
        }
    }
}

// Wo GEMM: fp32 out.
__global__ __launch_bounds__(256, 1)
void wo_mma_kernel(const __half* __restrict__ Ah, const __half* __restrict__ Al,
                   const __half* __restrict__ Bh, float* __restrict__ C) {
    extern __shared__ char smem[];
    const uint32_t sbase = smem_to_u32(smem);
    const int tid = threadIdx.x;
    const int bm = blockIdx.y * 128;
    const int bn = blockIdx.x * 128;

    float acc[2][8][4];
    #pragma unroll
    for (int i = 0; i < 2; i++)
        #pragma unroll
        for (int j = 0; j < 8; j++)
            #pragma unroll
            for (int q = 0; q < 4; q++) acc[i][j][q] = 0.f;

    gemm2_mainloop(Ah, Al, Bh, bm, bn, DD, sbase, tid, acc);

    const int lane = tid & 31, wid = tid >> 5;
    const int wm = wid >> 1, wn = wid & 1;
    const int er = lane >> 2, ec = (lane & 3) * 2;
    #pragma unroll
    for (int mt = 0; mt < 2; mt++) {
        const int row0 = bm + wm * 32 + mt * 16 + er;
        #pragma unroll
        for (int nt = 0; nt < 8; nt++) {
            const int col = bn + wn * 64 + nt * 8 + ec;
            *(float2*)&C[(size_t)row0 * DD + col] =
                make_float2(acc[mt][nt][0], acc[mt][nt][1]);
            *(float2*)&C[(size_t)(row0 + 8) * DD + col] =
                make_float2(acc[mt][nt][2], acc[mt][nt][3]);
        }
    }
}

// ---------------------------------------------------------------------------
// Flash attention fp16 mma (causal). BQ=128, BKV=64, HD=64.
// S = (Qh+Ql)·Kh^T; PV = (Ph+Pl)·Vh. 3-stage KV pipeline, one sync/tile.
// ---------------------------------------------------------------------------
#define FSROW  144                          // 64 fp16 = 128B + 16B pad
#define FTILE  (64 * FSROW)                 // 9216
#define FSTAGE (2 * FTILE)                  // 18432 (Kh, Vh)
#define FLASH_SMEM (3 * FSTAGE)             // 55296 (Q staging 36864 fits)

__global__ __launch_bounds__(256, 1)
void flash_mma_kernel(const __half* __restrict__ Qh_, const __half* __restrict__ Ql_,
                      const __half* __restrict__ Kh_, const __half* __restrict__ Vh_,
                      __half* __restrict__ Oh_, __half* __restrict__ Ol_) {
    extern __shared__ char smem[];
    const uint32_t sbase = smem_to_u32(smem);
    const int qb = (int)gridDim.x - 1 - (int)blockIdx.x;   // heavy first
    const int bh = blockIdx.y;
    const int b = bh >> 4, h = bh & 15;
    const int tid = threadIdx.x, lane = tid & 31, wid = tid >> 5;
    const int wrow = qb * 128 + wid * 16;

    // ---- Stage Q (hi at 0, lo at 128*FSROW), extract fragments
    {
        const size_t gq = ((size_t)(b * TT + qb * 128)) * DD + h * HD;
        #pragma unroll
        for (int t = 0; t < 8; t++) {
            const int mat = t >> 2;
            const int row = (t & 3) * 32 + (tid >> 3);
            const __half* src = mat ? Ql_ : Qh_;
            cp_async16(sbase + mat * (128 * FSROW) + row * FSROW + (tid & 7) * 16,
                       src + gq + (size_t)row * DD + (tid & 7) * 8);
        }
        cp_commit(); cp_wait<0>();
        __syncthreads();
    }
    uint32_t qh[4][4], ql[4][4];
    {
        const int a_row = wid * 16 + (lane & 15);
        const int a_col = (lane >> 4) * 8;
        #pragma unroll
        for (int ks = 0; ks < 4; ks++) {
            ldsm_x4(sbase + a_row * FSROW + (a_col + ks * 16) * 2,
                    qh[ks][0], qh[ks][1], qh[ks][2], qh[ks][3]);
            ldsm_x4(sbase + 128 * FSROW + a_row * FSROW + (a_col + ks * 16) * 2,
                    ql[ks][0], ql[ks][1], ql[ks][2], ql[ks][3]);
        }
    }
    __syncthreads();   // all warps done reading Q staging before KV loads reuse smem

    // ---- KV loader (Kh + Vh, 3-stage)
    const size_t gkv = ((size_t)(b * TT)) * DD + h * HD;
    auto load_kv = [&](int kt) {
        const uint32_t st = sbase + (kt % 3) * FSTAGE;
        const size_t base = gkv + (size_t)(kt * 64) * DD;
        #pragma unroll
        for (int t = 0; t < 4; t++) {
            const int mat = t >> 1;
            const int row = (t & 1) * 32 + (tid >> 3);
            const __half* src = mat ? Vh_ : Kh_;
            cp_async16(st + mat * FTILE + row * FSROW + (tid & 7) * 16,
                       src + base + (size_t)row * DD + (tid & 7) * 8);
        }
        cp_commit();
    };

    float acc[8][4];
    #pragma unroll
    for (int i = 0; i < 8; i++)
        #pragma unroll
        for (int j = 0; j < 4; j++) acc[i][j] = 0.f;
    float m0 = -CUDART_INF_F, m1 = -CUDART_INF_F, l0 = 0.f, l1 = 0.f;

    const int ntiles = 2 * qb + 2;
    const int diag_kt = wrow >> 6;
    const int b_row = ((lane >> 4) & 1) * 8 + (lane & 7);
    const int b_col = ((lane >> 3) & 1) * 8;

    load_kv(0);
    if (ntiles > 1) load_kv(1);

    for (int kt = 0; kt < ntiles; kt++) {
        if (kt + 1 < ntiles) cp_wait<1>();
        else cp_wait<0>();
        __syncthreads();
        if (kt + 2 < ntiles) load_kv(kt + 2);

        const uint32_t st = sbase + (kt % 3) * FSTAGE;
        if (kt * 64 <= wrow) {
            // ---- S = (Qh+Ql) @ Kh^T
            float s[8][4];
            #pragma unroll
            for (int i = 0; i < 8; i++)
                #pragma unroll
                for (int j = 0; j < 4; j++) s[i][j] = 0.f;

            #pragma unroll
            for (int ks = 0; ks < 4; ks++) {
                #pragma unroll
                for (int p = 0; p < 4; p++) {
                    uint32_t kh[4];
                    ldsm_x4(st + (b_row + p * 16) * FSROW + (b_col + ks * 16) * 2,
                            kh[0], kh[1], kh[2], kh[3]);
                    mma16816(s[2 * p + 0], qh[ks], kh[0], kh[1]);
                    mma16816(s[2 * p + 1], qh[ks], kh[2], kh[3]);
                    mma16816(s[2 * p + 0], ql[ks], kh[0], kh[1]);
                    mma16816(s[2 * p + 1], ql[ks], kh[2], kh[3]);
                }
            }

            // ---- scale + causal mask
            #pragma unroll
            for (int nt = 0; nt < 8; nt++)
                #pragma unroll
                for (int e = 0; e < 4; e++) s[nt][e] *= 0.125f;
            if (kt == diag_kt) {
                const int r0g = wrow + (lane >> 2);
                const int r1g = r0g + 8;
                #pragma unroll
                for (int nt = 0; nt < 8; nt++) {
                    #pragma unroll
                    for (int c = 0; c < 2; c++) {
                        const int col = kt * 64 + nt * 8 + (lane & 3) * 2 + c;
                        if (col > r0g) s[nt][c] = -1e30f;
                        if (col > r1g) s[nt][2 + c] = -1e30f;
                    }
                }
            }

            // ---- online softmax (in-warp quad reduction)
            float mx0 = -1e30f, mx1 = -1e30f;
            #pragma unroll
            for (int nt = 0; nt < 8; nt++) {
                mx0 = fmaxf(mx0, fmaxf(s[nt][0], s[nt][1]));
                mx1 = fmaxf(mx1, fmaxf(s[nt][2], s[nt][3]));
            }
            mx0 = fmaxf(mx0, __shfl_xor_sync(0xffffffffu, mx0, 1));
            mx0 = fmaxf(mx0, __shfl_xor_sync(0xffffffffu, mx0, 2));
            mx1 = fmaxf(mx1, __shfl_xor_sync(0xffffffffu, mx1, 1));
            mx1 = fmaxf(mx1, __shfl_xor_sync(0xffffffffu, mx1, 2));
            const float m0n = fmaxf(m0, mx0), m1n = fmaxf(m1, mx1);
            const float f0 = __expf(m0 - m0n), f1 = __expf(m1 - m1n);
            m0 = m0n; m1 = m1n;

            float sum0 = 0.f, sum1 = 0.f;
            #pragma unroll
            for (int nt = 0; nt < 8; nt++) {
                s[nt][0] = __expf(s[nt][0] - m0n); sum0 += s[nt][0];
                s[nt][1] = __expf(s[nt][1] - m0n); sum0 += s[nt][1];
                s[nt][2] = __expf(s[nt][2] - m1n); sum1 += s[nt][2];
                s[nt][3] = __expf(s[nt][3] - m1n); sum1 += s[nt][3];
            }
            sum0 += __shfl_xor_sync(0xffffffffu, sum0, 1);
            sum0 += __shfl_xor_sync(0xffffffffu, sum0, 2);
            sum1 += __shfl_xor_sync(0xffffffffu, sum1, 1);
            sum1 += __shfl_xor_sync(0xffffffffu, sum1, 2);
            l0 = f0 * l0 + sum0;
            l1 = f1 * l1 + sum1;

            #pragma unroll
            for (int nt = 0; nt < 8; nt++) {
                acc[nt][0] *= f0; acc[nt][1] *= f0;
                acc[nt][2] *= f1; acc[nt][3] *= f1;
            }

            // ---- P fragments: fp16 hi + residual lo (C->A frag remap)
            uint32_t aph[4][4], apl[4][4];
            #pragma unroll
            for (int kf = 0; kf < 4; kf++) {
                #pragma unroll
                for (int q = 0; q < 4; q++) {
                    const int t = 2 * kf + (q >> 1);
                    const int c = (q & 1) * 2;
                    const float x = s[t][c], y = s[t][c + 1];
                    const __half hx = __float2half(x), hy = __float2half(y);
                    __half2 hp(hx, hy);
                    aph[kf][q] = *(uint32_t*)&hp;
                    apl[kf][q] = pack_half2(x - __half2float(hx),
                                            y - __half2float(hy));
                }
            }

            // ---- O += (Ph+Pl) @ Vh (trans ldmatrix)
            #pragma unroll
            for (int kf = 0; kf < 4; kf++) {
                const int v_row = kf * 16 + ((lane >> 3) & 1) * 8 + (lane & 7);
                const int v_colb = ((lane >> 4) & 1) * 8;
                #pragma unroll
                for (int p = 0; p < 4; p++) {
                    uint32_t vh[4];
                    ldsm_x4_t(st + FTILE + v_row * FSROW + (p * 16 + v_colb) * 2,
                              vh[0], vh[1], vh[2], vh[3]);
                    mma16816(acc[2 * p + 0], aph[kf], vh[0], vh[1]);
                    mma16816(acc[2 * p + 1], aph[kf], vh[2], vh[3]);
                    mma16816(acc[2 * p + 0], apl[kf], vh[0], vh[1]);
                    mma16816(acc[2 * p + 1], apl[kf], vh[2], vh[3]);
                }
            }
        }
    }

    // ---- epilogue: normalize, fp16 hi/lo split for Wo GEMM
    const float inv0 = 1.f / l0, inv1 = 1.f / l1;
    const size_t orow0 = ((size_t)(b * TT + wrow + (lane >> 2))) * DD + h * HD;
    const size_t orow1 = orow0 + (size_t)8 * DD;
    #pragma unroll
    for (int nt = 0; nt < 8; nt++) {
        const int col = nt * 8 + (lane & 3) * 2;
        {
            const float x = acc[nt][0] * inv0, y = acc[nt][1] * inv0;
            const __half hx = __float2half(x), hy = __float2half(y);
            *(__half2*)&Oh_[orow0 + col] = __half2(hx, hy);
            *(__half2*)&Ol_[orow0 + col] = __half2(
                __float2half(x - __half2float(hx)),
                __float2half(y - __half2float(hy)));
        }
        {
            const float x = acc[nt][2] * inv1, y = acc[nt][3] * inv1;
            const __half hx = __float2half(x), hy = __float2half(y);
            *(__half2*)&Oh_[orow1 + col] = __half2(hx, hy);
            *(__half2*)&Ol_[orow1 + col] = __half2(
                __float2half(x - __half2float(hx)),
                __float2half(y - __half2float(hy)));
        }
    }
}

// ---------------------------------------------------------------------------
// Launch
// ---------------------------------------------------------------------------
extern "C" void kernel_launch(void* const* d_in, const int* in_sizes, int n_in,
                              void* d_out, int out_size) {
    const float* xq  = (const float*)d_in[0];
    const float* xkv = (const float*)d_in[1];
    const float* Wq = (const float*)d_in[3];
    const float* Wk = (const float*)d_in[4];
    const float* Wv = (const float*)d_in[5];
    const float* Wo = (const float*)d_in[6];
    float* out = (float*)d_out;

    __half *qh, *ql, *kh, *vh, *xah, *xal, *xbh, *xbl, *wt;
    cudaGetSymbolAddress((void**)&qh, g_qh);
    cudaGetSymbolAddress((void**)&ql, g_ql);
    cudaGetSymbolAddress((void**)&kh, g_kh);
    cudaGetSymbolAddress((void**)&vh, g_vh);
    cudaGetSymbolAddress((void**)&xah, g_xa_h);
    cudaGetSymbolAddress((void**)&xal, g_xa_l);
    cudaGetSymbolAddress((void**)&xbh, g_xb_h);
    cudaGetSymbolAddress((void**)&xbl, g_xb_l);
    cudaGetSymbolAddress((void**)&wt, g_wt);

    cudaFuncSetAttribute(qkv_mma_kernel, cudaFuncAttributeMaxDynamicSharedMemorySize,
                         GEMM_SMEM);
    cudaFuncSetAttribute(wo_mma_kernel, cudaFuncAttributeMaxDynamicSharedMemorySize,
                         GEMM_SMEM);
    cudaFuncSetAttribute(flash_mma_kernel, cudaFuncAttributeMaxDynamicSharedMemorySize,
                         FLASH_SMEM);

    const int n4 = MROWS * DD / 4;
    aconv_kernel<<<(n4 + 255) / 256, 256>>>(xq,  xah, xal, n4);
    aconv_kernel<<<(n4 + 255) / 256, 256>>>(xkv, xbh, xbl, n4);
    wconv_kernel<<<dim3(32, 32, 4), dim3(32, 8)>>>(Wq, Wk, Wv, Wo, wt);

    qkv_mma_kernel<<<dim3(DD / 128, MROWS / 128, 3), 256, GEMM_SMEM>>>(
        xah, xal, xbh, xbl, wt, qh, ql, kh, vh);

    flash_mma_kernel<<<dim3(TT / 128, BB * HH), 256, FLASH_SMEM>>>(
        qh, ql, kh, vh, xah, xal);

    wo_mma_kernel<<<dim3(DD / 128, MROWS / 128), 256, GEMM_SMEM>>>(
        xah, xal, wt + (size_t)3 * DD * DD, out);
}

// round 9
// speedup vs baseline: 4.7431x; 1.0707x over previous
#include <cuda_runtime.h>
#include <cuda_fp16.h>
#include <math_constants.h>
#include <cstdint>

// Problem constants
#define BB   2
#define TT   2048
#define DD   1024
#define HH   16
#define HD   64
#define MROWS (BB*TT)        // 4096

// ---------------------------------------------------------------------------
// Scratch (device globals; allocation forbidden)
// ---------------------------------------------------------------------------
__device__ __half g_qh[MROWS * DD];
__device__ __half g_ql[MROWS * DD];
__device__ __half g_kh[MROWS * DD];            // hi only (uncompensated in S)
__device__ __half g_vh[MROWS * DD];            // hi only (uncompensated in PV)

__device__ __half g_xa_h[MROWS * DD];          // activation A hi (reused: attn out)
__device__ __half g_xa_l[MROWS * DD];
__device__ __half g_xb_h[MROWS * DD];          // kv activation hi
__device__ __half g_xb_l[MROWS * DD];
__device__ __half g_wt[4 * DD * DD];           // transposed weights hi [n][k]

// ---------------------------------------------------------------------------
// PTX helpers
// ---------------------------------------------------------------------------
__device__ __forceinline__ uint32_t smem_to_u32(const void* p) {
    uint32_t a;
    asm("{ .reg .u64 t; cvta.to.shared.u64 t, %1; cvt.u32.u64 %0, t; }"
        : "=r"(a) : "l"(p));
    return a;
}
__device__ __forceinline__ void cp_async16(uint32_t sa, const void* g) {
    asm volatile("cp.async.cg.shared.global [%0], [%1], 16;" :: "r"(sa), "l"(g));
}
__device__ __forceinline__ void cp_commit() {
    asm volatile("cp.async.commit_group;");
}
template <int N>
__device__ __forceinline__ void cp_wait() {
    asm volatile("cp.async.wait_group %0;" :: "n"(N));
}
__device__ __forceinline__ void ldsm_x4(uint32_t addr, uint32_t& r0, uint32_t& r1,
                                        uint32_t& r2, uint32_t& r3) {
    asm volatile("ldmatrix.sync.aligned.m8n8.x4.shared.b16 {%0,%1,%2,%3}, [%4];"
                 : "=r"(r0), "=r"(r1), "=r"(r2), "=r"(r3) : "r"(addr));
}
__device__ __forceinline__ void ldsm_x4_t(uint32_t addr, uint32_t& r0, uint32_t& r1,
                                          uint32_t& r2, uint32_t& r3) {
    asm volatile("ldmatrix.sync.aligned.m8n8.x4.trans.shared.b16 {%0,%1,%2,%3}, [%4];"
                 : "=r"(r0), "=r"(r1), "=r"(r2), "=r"(r3) : "r"(addr));
}
__device__ __forceinline__ void mma16816(float* c, const uint32_t* a,
                                         uint32_t b0, uint32_t b1) {
    asm volatile(
        "mma.sync.aligned.m16n8k16.row.col.f32.f16.f16.f32 "
        "{%0,%1,%2,%3}, {%4,%5,%6,%7}, {%8,%9}, {%0,%1,%2,%3};"
        : "+f"(c[0]), "+f"(c[1]), "+f"(c[2]), "+f"(c[3])
        : "r"(a[0]), "r"(a[1]), "r"(a[2]), "r"(a[3]), "r"(b0), "r"(b1));
}
__device__ __forceinline__ uint32_t pack_half2(float x, float y) {
    __half2 v(__float2half(x), __float2half(y));
    return *(uint32_t*)&v;
}

// ---------------------------------------------------------------------------
// Activation fp32 -> (hi, lo) fp16 split
// ---------------------------------------------------------------------------
__global__ __launch_bounds__(256)
void aconv_kernel(const float* __restrict__ X, __half* __restrict__ Xh,
                  __half* __restrict__ Xl, int n4) {
    int i = blockIdx.x * blockDim.x + threadIdx.x;
    if (i >= n4) return;
    float4 v = ((const float4*)X)[i];
    __half h0 = __float2half(v.x), h1 = __float2half(v.y);
    __half h2 = __float2half(v.z), h3 = __float2half(v.w);
    __half l0 = __float2half(v.x - __half2float(h0));
    __half l1 = __float2half(v.y - __half2float(h1));
    __half l2 = __float2half(v.z - __half2float(h2));
    __half l3 = __float2half(v.w - __half2float(h3));
    ((__half2*)Xh)[i * 2 + 0] = __half2(h0, h1);
    ((__half2*)Xh)[i * 2 + 1] = __half2(h2, h3);
    ((__half2*)Xl)[i * 2 + 0] = __half2(l0, l1);
    ((__half2*)Xl)[i * 2 + 1] = __half2(l2, l3);
}

// ---------------------------------------------------------------------------
// Weight transpose + fp16 round: W[k][n] fp32 -> Wt[n][k] fp16 hi only.
// ---------------------------------------------------------------------------
__global__ __launch_bounds__(256)
void wconv_kernel(const float* __restrict__ W0, const float* __restrict__ W1,
                  const float* __restrict__ W2, const float* __restrict__ W3,
                  __half* __restrict__ T) {
    __shared__ float t[32][33];
    const int z = blockIdx.z;
    const float* W = (z == 0) ? W0 : (z == 1) ? W1 : (z == 2) ? W2 : W3;
    __half* Th = T + (size_t)z * DD * DD;
    const int tx = threadIdx.x, ty = threadIdx.y;
    const int k0 = blockIdx.y * 32, n0 = blockIdx.x * 32;
    #pragma unroll
    for (int i = 0; i < 4; i++)
        t[ty + 8 * i][tx] = W[(size_t)(k0 + ty + 8 * i) * DD + n0 + tx];
    __syncthreads();
    #pragma unroll
    for (int i = 0; i < 4; i++) {
        Th[(size_t)(n0 + ty + 8 * i) * DD + k0 + tx] =
            __float2half(t[tx][ty + 8 * i]);
    }
}

// ---------------------------------------------------------------------------
// fp16 2-product GEMM mainloop. C = (Ah+Al)[M,K] @ Bh[K,N]; Bh [N,K].
// CTA tile 128x128, 8 warps, K-chunk 64. 2-stage cp.async, one sync/chunk,
// sized so 2 CTAs fit per SM (smem 110592*2 = 221184 < 228KB; 128 regs cap).
// ---------------------------------------------------------------------------
#define KC        64
#define SROW      144                      // 64 fp16 = 128B + 16B pad
#define MAT_B     (128 * SROW)             // 18432
#define G_STAGE   (3 * MAT_B)              // 55296
#define GEMM_SMEM (2 * G_STAGE)            // 110592

__device__ __forceinline__ void gemm2_mainloop(
    const __half* __restrict__ Ah, const __half* __restrict__ Al,
    const __half* __restrict__ Bh, int bm, int bn, int K,
    uint32_t sbase, int tid, float acc[2][8][4]) {
    const int lane = tid & 31;
    const int wid = tid >> 5;
    const int wm = wid >> 1;
    const int wn = wid & 1;
    const int nchunks = K / KC;            // 16

    const int lrow = tid >> 3;             // 0..31 (+32*g)
    const int lseg = tid & 7;              // 16B segment in 128B row

    auto load_chunk = [&](int c) {
        const int k0 = c * KC;
        const uint32_t st = sbase + (c & 1) * G_STAGE;
        #pragma unroll
        for (int t = 0; t < 12; t++) {
            const int mat = t >> 2;
            const int row = (t & 3) * 32 + lrow;
            const __half* src = (mat == 0) ? Ah : (mat == 1) ? Al : Bh;
            const int grow = ((mat < 2) ? bm : bn) + row;
            cp_async16(st + mat * MAT_B + row * SROW + lseg * 16,
                       src + (size_t)grow * K + k0 + lseg * 8);
        }
        cp_commit();
    };

    const int a_row = wm * 32 + (lane & 15);
    const int a_col = (lane >> 4) * 8;
    const int b_row = wn * 64 + ((lane >> 4) & 1) * 8 + (lane & 7);
    const int b_col = ((lane >> 3) & 1) * 8;

    load_chunk(0);

    for (int c = 0; c < nchunks; c++) {
        cp_wait<0>();          // only chunk c outstanding; issued 1 full chunk ago
        __syncthreads();       // all warps done with stage (c-1) compute
        if (c + 1 < nchunks) load_chunk(c + 1);   // overwrites stage (c+1)&1

        const uint32_t st = sbase + (c & 1) * G_STAGE;
        #pragma unroll
        for (int kstep = 0; kstep < 4; kstep++) {
            uint32_t ah[2][4], al[2][4], bh[4][4];
            #pragma unroll
            for (int mt = 0; mt < 2; mt++) {
                ldsm_x4(st + 0 * MAT_B + (a_row + mt * 16) * SROW + (a_col + kstep * 16) * 2,
                        ah[mt][0], ah[mt][1], ah[mt][2], ah[mt][3]);
                ldsm_x4(st + 1 * MAT_B + (a_row + mt * 16) * SROW + (a_col + kstep * 16) * 2,
                        al[mt][0], al[mt][1], al[mt][2], al[mt][3]);
            }
            #pragma unroll
            for (int p = 0; p < 4; p++) {
                ldsm_x4(st + 2 * MAT_B + (b_row + p * 16) * SROW + (b_col + kstep * 16) * 2,
                        bh[p][0], bh[p][1], bh[p][2], bh[p][3]);
            }
            #pragma unroll
            for (int mt = 0; mt < 2; mt++) {
                #pragma unroll
                for (int p = 0; p < 4; p++) {
                    mma16816(acc[mt][2 * p + 0], ah[mt], bh[p][0], bh[p][1]);
                    mma16816(acc[mt][2 * p + 1], ah[mt], bh[p][2], bh[p][3]);
                    mma16816(acc[mt][2 * p + 0], al[mt], bh[p][0], bh[p][1]);
                    mma16816(acc[mt][2 * p + 1], al[mt], bh[p][2], bh[p][3]);
                }
            }
        }
    }
}

// Fused QKV GEMM: grid (8, 32, 3). z=0: Q (h/l out), z=1: K (h), z=2: V (h).
__global__ __launch_bounds__(256, 2)
void qkv_mma_kernel(const __half* __restrict__ xah, const __half* __restrict__ xal,
                    const __half* __restrict__ xbh, const __half* __restrict__ xbl,
                    const __half* __restrict__ Wt,
                    __half* __restrict__ Qh, __half* __restrict__ Ql,
                    __half* __restrict__ Kh, __half* __restrict__ Vh) {
    extern __shared__ char smem[];
    const uint32_t sbase = smem_to_u32(smem);
    const int tid = threadIdx.x;
    const int z = blockIdx.z;
    const int bm = blockIdx.y * 128;
    const int bn = blockIdx.x * 128;

    const __half* Ah = (z == 0) ? xah : xbh;
    const __half* Al = (z == 0) ? xal : xbl;
    const __half* Bh = Wt + (size_t)z * DD * DD;

    float acc[2][8][4];
    #pragma unroll
    for (int i = 0; i < 2; i++)
        #pragma unroll
        for (int j = 0; j < 8; j++)
            #pragma unroll
            for (int q = 0; q < 4; q++) acc[i][j][q] = 0.f;

    gemm2_mainloop(Ah, Al, Bh, bm, bn, DD, sbase, tid, acc);

    const int lane = tid & 31, wid = tid >> 5;
    const int wm = wid >> 1, wn = wid & 1;
    const int er = lane >> 2, ec = (lane & 3) * 2;
    #pragma unroll
    for (int mt = 0; mt < 2; mt++) {
        const int row0 = bm + wm * 32 + mt * 16 + er;
        #pragma unroll
        for (int nt = 0; nt < 8; nt++) {
            const int col = bn + wn * 64 + nt * 8 + ec;
            #pragma unroll
            for (int half_ = 0; half_ < 2; half_++) {
                const size_t o = (size_t)(row0 + half_ * 8) * DD + col;
                const float x = acc[mt][nt][2 * half_];
                const float y = acc[mt][nt][2 * half_ + 1];
                const __half hx = __float2half(x), hy = __float2half(y);
                if (z == 0) {
                    *(__half2*)&Qh[o] = __half2(hx, hy);
                    *(__half2*)&Ql[o] = __half2(
                        __float2half(x - __half2float(hx)),
                        __float2half(y - __half2float(hy)));
                } else {
                    __half* dst = (z == 1) ? Kh : Vh;
                    *(__half2*)&dst[o] = __half2(hx, hy);
                }
            }
        }
    }
}

// Wo GEMM: fp32 out.
__global__ __launch_bounds__(256, 2)
void wo_mma_kernel(const __half* __restrict__ Ah, const __half* __restrict__ Al,
                   const __half* __restrict__ Bh, float* __restrict__ C) {
    extern __shared__ char smem[];
    const uint32_t sbase = smem_to_u32(smem);
    const int tid = threadIdx.x;
    const int bm = blockIdx.y * 128;
    const int bn = blockIdx.x * 128;

    float acc[2][8][4];
    #pragma unroll
    for (int i = 0; i < 2; i++)
        #pragma unroll
        for (int j = 0; j < 8; j++)
            #pragma unroll
            for (int q = 0; q < 4; q++) acc[i][j][q] = 0.f;

    gemm2_mainloop(Ah, Al, Bh, bm, bn, DD, sbase, tid, acc);

    const int lane = tid & 31, wid = tid >> 5;
    const int wm = wid >> 1, wn = wid & 1;
    const int er = lane >> 2, ec = (lane & 3) * 2;
    #pragma unroll
    for (int mt = 0; mt < 2; mt++) {
        const int row0 = bm + wm * 32 + mt * 16 + er;
        #pragma unroll
        for (int nt = 0; nt < 8; nt++) {
            const int col = bn + wn * 64 + nt * 8 + ec;
            *(float2*)&C[(size_t)row0 * DD + col] =
                make_float2(acc[mt][nt][0], acc[mt][nt][1]);
            *(float2*)&C[(size_t)(row0 + 8) * DD + col] =
                make_float2(acc[mt][nt][2], acc[mt][nt][3]);
        }
    }
}

// ---------------------------------------------------------------------------
// Flash attention fp16 mma (causal). BQ=128, BKV=64, HD=64.
// S = (Qh+Ql)·Kh^T; PV = (Ph+Pl)·Vh. 3-stage KV pipeline, one sync/tile.
// 2 CTAs/SM (smem 55296*2; regs capped 128 — minor spills absorbed by warps).
// ---------------------------------------------------------------------------
#define FSROW  144                          // 64 fp16 = 128B + 16B pad
#define FTILE  (64 * FSROW)                 // 9216
#define FSTAGE (2 * FTILE)                  // 18432 (Kh, Vh)
#define FLASH_SMEM (3 * FSTAGE)             // 55296 (Q staging 36864 fits)

__global__ __launch_bounds__(256, 2)
void flash_mma_kernel(const __half* __restrict__ Qh_, const __half* __restrict__ Ql_,
                      const __half* __restrict__ Kh_, const __half* __restrict__ Vh_,
                      __half* __restrict__ Oh_, __half* __restrict__ Ol_) {
    extern __shared__ char smem[];
    const uint32_t sbase = smem_to_u32(smem);
    const int qb = (int)gridDim.x - 1 - (int)blockIdx.x;   // heavy first
    const int bh = blockIdx.y;
    const int b = bh >> 4, h = bh & 15;
    const int tid = threadIdx.x, lane = tid & 31, wid = tid >> 5;
    const int wrow = qb * 128 + wid * 16;

    // ---- Stage Q (hi at 0, lo at 128*FSROW), extract fragments
    {
        const size_t gq = ((size_t)(b * TT + qb * 128)) * DD + h * HD;
        #pragma unroll
        for (int t = 0; t < 8; t++) {
            const int mat = t >> 2;
            const int row = (t & 3) * 32 + (tid >> 3);
            const __half* src = mat ? Ql_ : Qh_;
            cp_async16(sbase + mat * (128 * FSROW) + row * FSROW + (tid & 7) * 16,
                       src + gq + (size_t)row * DD + (tid & 7) * 8);
        }
        cp_commit(); cp_wait<0>();
        __syncthreads();
    }
    uint32_t qh[4][4], ql[4][4];
    {
        const int a_row = wid * 16 + (lane & 15);
        const int a_col = (lane >> 4) * 8;
        #pragma unroll
        for (int ks = 0; ks < 4; ks++) {
            ldsm_x4(sbase + a_row * FSROW + (a_col + ks * 16) * 2,
                    qh[ks][0], qh[ks][1], qh[ks][2], qh[ks][3]);
            ldsm_x4(sbase + 128 * FSROW + a_row * FSROW + (a_col + ks * 16) * 2,
                    ql[ks][0], ql[ks][1], ql[ks][2], ql[ks][3]);
        }
    }
    __syncthreads();   // all warps done reading Q staging before KV loads reuse smem

    // ---- KV loader (Kh + Vh, 3-stage)
    const size_t gkv = ((size_t)(b * TT)) * DD + h * HD;
    auto load_kv = [&](int kt) {
        const uint32_t st = sbase + (kt % 3) * FSTAGE;
        const size_t base = gkv + (size_t)(kt * 64) * DD;
        #pragma unroll
        for (int t = 0; t < 4; t++) {
            const int mat = t >> 1;
            const int row = (t & 1) * 32 + (tid >> 3);
            const __half* src = mat ? Vh_ : Kh_;
            cp_async16(st + mat * FTILE + row * FSROW + (tid & 7) * 16,
                       src + base + (size_t)row * DD + (tid & 7) * 8);
        }
        cp_commit();
    };

    float acc[8][4];
    #pragma unroll
    for (int i = 0; i < 8; i++)
        #pragma unroll
        for (int j = 0; j < 4; j++) acc[i][j] = 0.f;
    float m0 = -CUDART_INF_F, m1 = -CUDART_INF_F, l0 = 0.f, l1 = 0.f;

    const int ntiles = 2 * qb + 2;
    const int diag_kt = wrow >> 6;
    const int b_row = ((lane >> 4) & 1) * 8 + (lane & 7);
    const int b_col = ((lane >> 3) & 1) * 8;

    load_kv(0);
    if (ntiles > 1) load_kv(1);

    for (int kt = 0; kt < ntiles; kt++) {
        if (kt + 1 < ntiles) cp_wait<1>();
        else cp_wait<0>();
        __syncthreads();
        if (kt + 2 < ntiles) load_kv(kt + 2);

        const uint32_t st = sbase + (kt % 3) * FSTAGE;
        if (kt * 64 <= wrow) {
            // ---- S = (Qh+Ql) @ Kh^T
            float s[8][4];
            #pragma unroll
            for (int i = 0; i < 8; i++)
                #pragma unroll
                for (int j = 0; j < 4; j++) s[i][j] = 0.f;

            #pragma unroll
            for (int ks = 0; ks < 4; ks++) {
                #pragma unroll
                for (int p = 0; p < 4; p++) {
                    uint32_t kh[4];
                    ldsm_x4(st + (b_row + p * 16) * FSROW + (b_col + ks * 16) * 2,
                            kh[0], kh[1], kh[2], kh[3]);
                    mma16816(s[2 * p + 0], qh[ks], kh[0], kh[1]);
                    mma16816(s[2 * p + 1], qh[ks], kh[2], kh[3]);
                    mma16816(s[2 * p + 0], ql[ks], kh[0], kh[1]);
                    mma16816(s[2 * p + 1], ql[ks], kh[2], kh[3]);
                }
            }

            // ---- scale + causal mask
            #pragma unroll
            for (int nt = 0; nt < 8; nt++)
                #pragma unroll
                for (int e = 0; e < 4; e++) s[nt][e] *= 0.125f;
            if (kt == diag_kt) {
                const int r0g = wrow + (lane >> 2);
                const int r1g = r0g + 8;
                #pragma unroll
                for (int nt = 0; nt < 8; nt++) {
                    #pragma unroll
                    for (int c = 0; c < 2; c++) {
                        const int col = kt * 64 + nt * 8 + (lane & 3) * 2 + c;
                        if (col > r0g) s[nt][c] = -1e30f;
                        if (col > r1g) s[nt][2 + c] = -1e30f;
                    }
                }
            }

            // ---- online softmax (in-warp quad reduction)
            float mx0 = -1e30f, mx1 = -1e30f;
            #pragma unroll
            for (int nt = 0; nt < 8; nt++) {
                mx0 = fmaxf(mx0, fmaxf(s[nt][0], s[nt][1]));
                mx1 = fmaxf(mx1, fmaxf(s[nt][2], s[nt][3]));
            }
            mx0 = fmaxf(mx0, __shfl_xor_sync(0xffffffffu, mx0, 1));
            mx0 = fmaxf(mx0, __shfl_xor_sync(0xffffffffu, mx0, 2));
            mx1 = fmaxf(mx1, __shfl_xor_sync(0xffffffffu, mx1, 1));
            mx1 = fmaxf(mx1, __shfl_xor_sync(0xffffffffu, mx1, 2));
            const float m0n = fmaxf(m0, mx0), m1n = fmaxf(m1, mx1);
            const float f0 = __expf(m0 - m0n), f1 = __expf(m1 - m1n);
            m0 = m0n; m1 = m1n;

            float sum0 = 0.f, sum1 = 0.f;
            #pragma unroll
            for (int nt = 0; nt < 8; nt++) {
                s[nt][0] = __expf(s[nt][0] - m0n); sum0 += s[nt][0];
                s[nt][1] = __expf(s[nt][1] - m0n); sum0 += s[nt][1];
                s[nt][2] = __expf(s[nt][2] - m1n); sum1 += s[nt][2];
                s[nt][3] = __expf(s[nt][3] - m1n); sum1 += s[nt][3];
            }
            sum0 += __shfl_xor_sync(0xffffffffu, sum0, 1);
            sum0 += __shfl_xor_sync(0xffffffffu, sum0, 2);
            sum1 += __shfl_xor_sync(0xffffffffu, sum1, 1);
            sum1 += __shfl_xor_sync(0xffffffffu, sum1, 2);
            l0 = f0 * l0 + sum0;
            l1 = f1 * l1 + sum1;

            #pragma unroll
            for (int nt = 0; nt < 8; nt++) {
                acc[nt][0] *= f0; acc[nt][1] *= f0;
                acc[nt][2] *= f1; acc[nt][3] *= f1;
            }

            // ---- P fragments: fp16 hi + residual lo (C->A frag remap)
            uint32_t aph[4][4], apl[4][4];
            #pragma unroll
            for (int kf = 0; kf < 4; kf++) {
                #pragma unroll
                for (int q = 0; q < 4; q++) {
                    const int t = 2 * kf + (q >> 1);
                    const int c = (q & 1) * 2;
                    const float x = s[t][c], y = s[t][c + 1];
                    const __half hx = __float2half(x), hy = __float2half(y);
                    __half2 hp(hx, hy);
                    aph[kf][q] = *(uint32_t*)&hp;
                    apl[kf][q] = pack_half2(x - __half2float(hx),
                                            y - __half2float(hy));
                }
            }

            // ---- O += (Ph+Pl) @ Vh (trans ldmatrix)
            #pragma unroll
            for (int kf = 0; kf < 4; kf++) {
                const int v_row = kf * 16 + ((lane >> 3) & 1) * 8 + (lane & 7);
                const int v_colb = ((lane >> 4) & 1) * 8;
                #pragma unroll
                for (int p = 0; p < 4; p++) {
                    uint32_t vh[4];
                    ldsm_x4_t(st + FTILE + v_row * FSROW + (p * 16 + v_colb) * 2,
                              vh[0], vh[1], vh[2], vh[3]);
                    mma16816(acc[2 * p + 0], aph[kf], vh[0], vh[1]);
                    mma16816(acc[2 * p + 1], aph[kf], vh[2], vh[3]);
                    mma16816(acc[2 * p + 0], apl[kf], vh[0], vh[1]);
                    mma16816(acc[2 * p + 1], apl[kf], vh[2], vh[3]);
                }
            }
        }
    }

    // ---- epilogue: normalize, fp16 hi/lo split for Wo GEMM
    const float inv0 = 1.f / l0, inv1 = 1.f / l1;
    const size_t orow0 = ((size_t)(b * TT + wrow + (lane >> 2))) * DD + h * HD;
    const size_t orow1 = orow0 + (size_t)8 * DD;
    #pragma unroll
    for (int nt = 0; nt < 8; nt++) {
        const int col = nt * 8 + (lane & 3) * 2;
        {
            const float x = acc[nt][0] * inv0, y = acc[nt][1] * inv0;
            const __half hx = __float2half(x), hy = __float2half(y);
            *(__half2*)&Oh_[orow0 + col] = __half2(hx, hy);
            *(__half2*)&Ol_[orow0 + col] = __half2(
                __float2half(x - __half2float(hx)),
                __float2half(y - __half2float(hy)));
        }
        {
            const float x = acc[nt][2] * inv1, y = acc[nt][3] * inv1;
            const __half hx = __float2half(x), hy = __float2half(y);
            *(__half2*)&Oh_[orow1 + col] = __half2(hx, hy);
            *(__half2*)&Ol_[orow1 + col] = __half2(
                __float2half(x - __half2float(hx)),
                __float2half(y - __half2float(hy)));
        }
    }
}

// ---------------------------------------------------------------------------
// Launch
// ---------------------------------------------------------------------------
extern "C" void kernel_launch(void* const* d_in, const int* in_sizes, int n_in,
                              void* d_out, int out_size) {
    const float* xq  = (const float*)d_in[0];
    const float* xkv = (const float*)d_in[1];
    const float* Wq = (const float*)d_in[3];
    const float* Wk = (const float*)d_in[4];
    const float* Wv = (const float*)d_in[5];
    const float* Wo = (const float*)d_in[6];
    float* out = (float*)d_out;

    __half *qh, *ql, *kh, *vh, *xah, *xal, *xbh, *xbl, *wt;
    cudaGetSymbolAddress((void**)&qh, g_qh);
    cudaGetSymbolAddress((void**)&ql, g_ql);
    cudaGetSymbolAddress((void**)&kh, g_kh);
    cudaGetSymbolAddress((void**)&vh, g_vh);
    cudaGetSymbolAddress((void**)&xah, g_xa_h);
    cudaGetSymbolAddress((void**)&xal, g_xa_l);
    cudaGetSymbolAddress((void**)&xbh, g_xb_h);
    cudaGetSymbolAddress((void**)&xbl, g_xb_l);
    cudaGetSymbolAddress((void**)&wt, g_wt);

    cudaFuncSetAttribute(qkv_mma_kernel, cudaFuncAttributeMaxDynamicSharedMemorySize,
                         GEMM_SMEM);
    cudaFuncSetAttribute(wo_mma_kernel, cudaFuncAttributeMaxDynamicSharedMemorySize,
                         GEMM_SMEM);
    cudaFuncSetAttribute(flash_mma_kernel, cudaFuncAttributeMaxDynamicSharedMemorySize,
                         FLASH_SMEM);

    const int n4 = MROWS * DD / 4;
    aconv_kernel<<<(n4 + 255) / 256, 256>>>(xq,  xah, xal, n4);
    aconv_kernel<<<(n4 + 255) / 256, 256>>>(xkv, xbh, xbl, n4);
    wconv_kernel<<<dim3(32, 32, 4), dim3(32, 8)>>>(Wq, Wk, Wv, Wo, wt);

    qkv_mma_kernel<<<dim3(DD / 128, MROWS / 128, 3), 256, GEMM_SMEM>>>(
        xah, xal, xbh, xbl, wt, qh, ql, kh, vh);

    flash_mma_kernel<<<dim3(TT / 128, BB * HH), 256, FLASH_SMEM>>>(
        qh, ql, kh, vh, xah, xal);

    wo_mma_kernel<<<dim3(DD / 128, MROWS / 128), 256, GEMM_SMEM>>>(
        xah, xal, wt + (size_t)3 * DD * DD, out);
}

// round 12
// speedup vs baseline: 5.3499x; 1.1279x over previous
#include <cuda_runtime.h>
#include <cuda_fp16.h>
#include <math_constants.h>
#include <cstdint>

// Problem constants
#define BB   2
#define TT   2048
#define DD   1024
#define HH   16
#define HD   64
#define MROWS (BB*TT)        // 4096

// ---------------------------------------------------------------------------
// Scratch (device globals; allocation forbidden)
// ---------------------------------------------------------------------------
__device__ __half g_qh[MROWS * DD];
__device__ __half g_ql[MROWS * DD];
__device__ __half g_kh[MROWS * DD];            // hi only
__device__ __half g_vh[MROWS * DD];            // hi only

__device__ __half g_xa_h[MROWS * DD];          // xq hi (reused: attn out hi)
__device__ __half g_xa_l[MROWS * DD];          // xq lo
__device__ __half g_xb_h[MROWS * DD];          // xkv hi (K/V GEMMs uncompensated)
__device__ __half g_wt[4 * DD * DD];           // transposed weights hi [n][k]

// ---------------------------------------------------------------------------
// PTX helpers
// ---------------------------------------------------------------------------
__device__ __forceinline__ uint32_t smem_to_u32(const void* p) {
    uint32_t a;
    asm("{ .reg .u64 t; cvta.to.shared.u64 t, %1; cvt.u32.u64 %0, t; }"
        : "=r"(a) : "l"(p));
    return a;
}
__device__ __forceinline__ void cp_async16(uint32_t sa, const void* g) {
    asm volatile("cp.async.cg.shared.global [%0], [%1], 16;" :: "r"(sa), "l"(g));
}
__device__ __forceinline__ void cp_commit() {
    asm volatile("cp.async.commit_group;");
}
template <int N>
__device__ __forceinline__ void cp_wait() {
    asm volatile("cp.async.wait_group %0;" :: "n"(N));
}
__device__ __forceinline__ void ldsm_x4(uint32_t addr, uint32_t& r0, uint32_t& r1,
                                        uint32_t& r2, uint32_t& r3) {
    asm volatile("ldmatrix.sync.aligned.m8n8.x4.shared.b16 {%0,%1,%2,%3}, [%4];"
                 : "=r"(r0), "=r"(r1), "=r"(r2), "=r"(r3) : "r"(addr));
}
__device__ __forceinline__ void ldsm_x4_t(uint32_t addr, uint32_t& r0, uint32_t& r1,
                                          uint32_t& r2, uint32_t& r3) {
    asm volatile("ldmatrix.sync.aligned.m8n8.x4.trans.shared.b16 {%0,%1,%2,%3}, [%4];"
                 : "=r"(r0), "=r"(r1), "=r"(r2), "=r"(r3) : "r"(addr));
}
__device__ __forceinline__ void mma16816(float* c, const uint32_t* a,
                                         uint32_t b0, uint32_t b1) {
    asm volatile(
        "mma.sync.aligned.m16n8k16.row.col.f32.f16.f16.f32 "
        "{%0,%1,%2,%3}, {%4,%5,%6,%7}, {%8,%9}, {%0,%1,%2,%3};"
        : "+f"(c[0]), "+f"(c[1]), "+f"(c[2]), "+f"(c[3])
        : "r"(a[0]), "r"(a[1]), "r"(a[2]), "r"(a[3]), "r"(b0), "r"(b1));
}
__device__ __forceinline__ uint32_t pack_half2(float x, float y) {
    __half2 v(__float2half(x), __float2half(y));
    return *(uint32_t*)&v;
}
__device__ __forceinline__ float ex2(float x) {
    float r;
    asm("ex2.approx.ftz.f32 %0, %1;" : "=f"(r) : "f"(x));
    return r;
}

// ---------------------------------------------------------------------------
// Activation fp32 -> (hi, lo) fp16 split  /  hi-only variant
// ---------------------------------------------------------------------------
__global__ __launch_bounds__(256)
void aconv_kernel(const float* __restrict__ X, __half* __restrict__ Xh,
                  __half* __restrict__ Xl, int n4) {
    int i = blockIdx.x * blockDim.x + threadIdx.x;
    if (i >= n4) return;
    float4 v = ((const float4*)X)[i];
    __half h0 = __float2half(v.x), h1 = __float2half(v.y);
    __half h2 = __float2half(v.z), h3 = __float2half(v.w);
    __half l0 = __float2half(v.x - __half2float(h0));
    __half l1 = __float2half(v.y - __half2float(h1));
    __half l2 = __float2half(v.z - __half2float(h2));
    __half l3 = __float2half(v.w - __half2float(h3));
    ((__half2*)Xh)[i * 2 + 0] = __half2(h0, h1);
    ((__half2*)Xh)[i * 2 + 1] = __half2(h2, h3);
    ((__half2*)Xl)[i * 2 + 0] = __half2(l0, l1);
    ((__half2*)Xl)[i * 2 + 1] = __half2(l2, l3);
}

__global__ __launch_bounds__(256)
void aconv_h_kernel(const float* __restrict__ X, __half* __restrict__ Xh, int n4) {
    int i = blockIdx.x * blockDim.x + threadIdx.x;
    if (i >= n4) return;
    float4 v = ((const float4*)X)[i];
    ((__half2*)Xh)[i * 2 + 0] = __half2(__float2half(v.x), __float2half(v.y));
    ((__half2*)Xh)[i * 2 + 1] = __half2(__float2half(v.z), __float2half(v.w));
}

// ---------------------------------------------------------------------------
// Weight transpose + fp16 round: W[k][n] fp32 -> Wt[n][k] fp16 hi only.
// ---------------------------------------------------------------------------
__global__ __launch_bounds__(256)
void wconv_kernel(const float* __restrict__ W0, const float* __restrict__ W1,
                  const float* __restrict__ W2, const float* __restrict__ W3,
                  __half* __restrict__ T) {
    __shared__ float t[32][33];
    const int z = blockIdx.z;
    const float* W = (z == 0) ? W0 : (z == 1) ? W1 : (z == 2) ? W2 : W3;
    __half* Th = T + (size_t)z * DD * DD;
    const int tx = threadIdx.x, ty = threadIdx.y;
    const int k0 = blockIdx.y * 32, n0 = blockIdx.x * 32;
    #pragma unroll
    for (int i = 0; i < 4; i++)
        t[ty + 8 * i][tx] = W[(size_t)(k0 + ty + 8 * i) * DD + n0 + tx];
    __syncthreads();
    #pragma unroll
    for (int i = 0; i < 4; i++) {
        Th[(size_t)(n0 + ty + 8 * i) * DD + k0 + tx] =
            __float2half(t[tx][ty + 8 * i]);
    }
}

// ---------------------------------------------------------------------------
// fp16 GEMM mainloop. C = (Ah [+ Al]) @ Bh; Bh pre-transposed [N,K].
// with_al selects 2-product (compensated A) or 1-product.
// CTA tile 128x128, 8 warps, K-chunk 64, 2-stage cp.async, one sync/chunk.
// 2 CTAs/SM (smem 110592*2 = 221184; 128 regs).
// ---------------------------------------------------------------------------
#define KC        64
#define SROW      144                      // 64 fp16 = 128B + 16B pad
#define MAT_B     (128 * SROW)             // 18432
#define G_STAGE   (3 * MAT_B)              // 55296
#define GEMM_SMEM (2 * G_STAGE)            // 110592

__device__ __forceinline__ void gemm_mainloop(
    const __half* __restrict__ Ah, const __half* __restrict__ Al,
    const __half* __restrict__ Bh, int bm, int bn, int K,
    uint32_t sbase, int tid, bool with_al, float acc[2][8][4]) {
    const int lane = tid & 31;
    const int wid = tid >> 5;
    const int wm = wid >> 1;
    const int wn = wid & 1;
    const int nchunks = K / KC;            // 16

    const int lrow = tid >> 3;             // 0..31 (+32*g)
    const int lseg = tid & 7;              // 16B segment in 128B row

    auto load_chunk = [&](int c) {
        const int k0 = c * KC;
        const uint32_t st = sbase + (c & 1) * G_STAGE;
        #pragma unroll
        for (int t = 0; t < 12; t++) {
            const int mat = t >> 2;
            if (mat == 1 && !with_al) continue;
            const int row = (t & 3) * 32 + lrow;
            const __half* src = (mat == 0) ? Ah : (mat == 1) ? Al : Bh;
            const int grow = ((mat < 2) ? bm : bn) + row;
            cp_async16(st + mat * MAT_B + row * SROW + lseg * 16,
                       src + (size_t)grow * K + k0 + lseg * 8);
        }
        cp_commit();
    };

    const int a_row = wm * 32 + (lane & 15);
    const int a_col = (lane >> 4) * 8;
    const int b_row = wn * 64 + ((lane >> 4) & 1) * 8 + (lane & 7);
    const int b_col = ((lane >> 3) & 1) * 8;

    load_chunk(0);

    for (int c = 0; c < nchunks; c++) {
        cp_wait<0>();
        __syncthreads();
        if (c + 1 < nchunks) load_chunk(c + 1);

        const uint32_t st = sbase + (c & 1) * G_STAGE;
        #pragma unroll
        for (int kstep = 0; kstep < 4; kstep++) {
            uint32_t ah[2][4], al[2][4], bh[4][4];
            #pragma unroll
            for (int mt = 0; mt < 2; mt++) {
                ldsm_x4(st + 0 * MAT_B + (a_row + mt * 16) * SROW + (a_col + kstep * 16) * 2,
                        ah[mt][0], ah[mt][1], ah[mt][2], ah[mt][3]);
                if (with_al)
                    ldsm_x4(st + 1 * MAT_B + (a_row + mt * 16) * SROW + (a_col + kstep * 16) * 2,
                            al[mt][0], al[mt][1], al[mt][2], al[mt][3]);
            }
            #pragma unroll
            for (int p = 0; p < 4; p++) {
                ldsm_x4(st + 2 * MAT_B + (b_row + p * 16) * SROW + (b_col + kstep * 16) * 2,
                        bh[p][0], bh[p][1], bh[p][2], bh[p][3]);
            }
            #pragma unroll
            for (int mt = 0; mt < 2; mt++) {
                #pragma unroll
                for (int p = 0; p < 4; p++) {
                    mma16816(acc[mt][2 * p + 0], ah[mt], bh[p][0], bh[p][1]);
                    mma16816(acc[mt][2 * p + 1], ah[mt], bh[p][2], bh[p][3]);
                    if (with_al) {
                        mma16816(acc[mt][2 * p + 0], al[mt], bh[p][0], bh[p][1]);
                        mma16816(acc[mt][2 * p + 1], al[mt], bh[p][2], bh[p][3]);
                    }
                }
            }
        }
    }
}

// Fused QKV GEMM: grid (8, 32, 3). z=0: Q (2-product, h/l out);
// z=1: K (1-product, h); z=2: V (1-product, h).
__global__ __launch_bounds__(256, 2)
void qkv_mma_kernel(const __half* __restrict__ xah, const __half* __restrict__ xal,
                    const __half* __restrict__ xbh,
                    const __half* __restrict__ Wt,
                    __half* __restrict__ Qh, __half* __restrict__ Ql,
                    __half* __restrict__ Kh, __half* __restrict__ Vh) {
    extern __shared__ char smem[];
    const uint32_t sbase = smem_to_u32(smem);
    const int tid = threadIdx.x;
    const int z = blockIdx.z;
    const int bm = blockIdx.y * 128;
    const int bn = blockIdx.x * 128;

    const __half* Ah = (z == 0) ? xah : xbh;
    const __half* Al = (z == 0) ? xal : xbh;   // dummy for z>=1 (unused)
    const __half* Bh = Wt + (size_t)z * DD * DD;

    float acc[2][8][4];
    #pragma unroll
    for (int i = 0; i < 2; i++)
        #pragma unroll
        for (int j = 0; j < 8; j++)
            #pragma unroll
            for (int q = 0; q < 4; q++) acc[i][j][q] = 0.f;

    gemm_mainloop(Ah, Al, Bh, bm, bn, DD, sbase, tid, (z == 0), acc);

    const int lane = tid & 31, wid = tid >> 5;
    const int wm = wid >> 1, wn = wid & 1;
    const int er = lane >> 2, ec = (lane & 3) * 2;
    #pragma unroll
    for (int mt = 0; mt < 2; mt++) {
        const int row0 = bm + wm * 32 + mt * 16 + er;
        #pragma unroll
        for (int nt = 0; nt < 8; nt++) {
            const int col = bn + wn * 64 + nt * 8 + ec;
            #pragma unroll
            for (int half_ = 0; half_ < 2; half_++) {
                const size_t o = (size_t)(row0 + half_ * 8) * DD + col;
                const float x = acc[mt][nt][2 * half_];
                const float y = acc[mt][nt][2 * half_ + 1];
                const __half hx = __float2half(x), hy = __float2half(y);
                if (z == 0) {
                    *(__half2*)&Qh[o] = __half2(hx, hy);
                    *(__half2*)&Ql[o] = __half2(
                        __float2half(x - __half2float(hx)),
                        __float2half(y - __half2float(hy)));
                } else {
                    __half* dst = (z == 1) ? Kh : Vh;
                    *(__half2*)&dst[o] = __half2(hx, hy);
                }
            }
        }
    }
}

// Wo GEMM: 1-product (attn-out hi only), fp32 out.
__global__ __launch_bounds__(256, 2)
void wo_mma_kernel(const __half* __restrict__ Ah,
                   const __half* __restrict__ Bh, float* __restrict__ C) {
    extern __shared__ char smem[];
    const uint32_t sbase = smem_to_u32(smem);
    const int tid = threadIdx.x;
    const int bm = blockIdx.y * 128;
    const int bn = blockIdx.x * 128;

    float acc[2][8][4];
    #pragma unroll
    for (int i = 0; i < 2; i++)
        #pragma unroll
        for (int j = 0; j < 8; j++)
            #pragma unroll
            for (int q = 0; q < 4; q++) acc[i][j][q] = 0.f;

    gemm_mainloop(Ah, Ah, Bh, bm, bn, DD, sbase, tid, false, acc);

    const int lane = tid & 31, wid = tid >> 5;
    const int wm = wid >> 1, wn = wid & 1;
    const int er = lane >> 2, ec = (lane & 3) * 2;
    #pragma unroll
    for (int mt = 0; mt < 2; mt++) {
        const int row0 = bm + wm * 32 + mt * 16 + er;
        #pragma unroll
        for (int nt = 0; nt < 8; nt++) {
            const int col = bn + wn * 64 + nt * 8 + ec;
            *(float2*)&C[(size_t)row0 * DD + col] =
                make_float2(acc[mt][nt][0], acc[mt][nt][1]);
            *(float2*)&C[(size_t)(row0 + 8) * DD + col] =
                make_float2(acc[mt][nt][2], acc[mt][nt][3]);
        }
    }
}

// ---------------------------------------------------------------------------
// Flash attention fp16 mma (causal). BQ=128, BKV=64, HD=64.
// S = (Qh+Ql)·Kh^T; PV = (Ph+Pl)·Vh. Base-2 softmax (ex2.approx).
// 3-stage KV pipeline, one sync/tile, 2 CTAs/SM. Output: hi only.
// ---------------------------------------------------------------------------
#define FSROW  144                          // 64 fp16 = 128B + 16B pad
#define FTILE  (64 * FSROW)                 // 9216
#define FSTAGE (2 * FTILE)                  // 18432 (Kh, Vh)
#define FLASH_SMEM (3 * FSTAGE)             // 55296 (Q staging 36864 fits)

__global__ __launch_bounds__(256, 2)
void flash_mma_kernel(const __half* __restrict__ Qh_, const __half* __restrict__ Ql_,
                      const __half* __restrict__ Kh_, const __half* __restrict__ Vh_,
                      __half* __restrict__ Oh_) {
    extern __shared__ char smem[];
    const uint32_t sbase = smem_to_u32(smem);
    const int qb = (int)gridDim.x - 1 - (int)blockIdx.x;   // heavy first
    const int bh = blockIdx.y;
    const int b = bh >> 4, h = bh & 15;
    const int tid = threadIdx.x, lane = tid & 31, wid = tid >> 5;
    const int wrow = qb * 128 + wid * 16;

    // ---- Stage Q (hi at 0, lo at 128*FSROW), extract fragments
    {
        const size_t gq = ((size_t)(b * TT + qb * 128)) * DD + h * HD;
        #pragma unroll
        for (int t = 0; t < 8; t++) {
            const int mat = t >> 2;
            const int row = (t & 3) * 32 + (tid >> 3);
            const __half* src = mat ? Ql_ : Qh_;
            cp_async16(sbase + mat * (128 * FSROW) + row * FSROW + (tid & 7) * 16,
                       src + gq + (size_t)row * DD + (tid & 7) * 8);
        }
        cp_commit(); cp_wait<0>();
        __syncthreads();
    }
    uint32_t qh[4][4], ql[4][4];
    {
        const int a_row = wid * 16 + (lane & 15);
        const int a_col = (lane >> 4) * 8;
        #pragma unroll
        for (int ks = 0; ks < 4; ks++) {
            ldsm_x4(sbase + a_row * FSROW + (a_col + ks * 16) * 2,
                    qh[ks][0], qh[ks][1], qh[ks][2], qh[ks][3]);
            ldsm_x4(sbase + 128 * FSROW + a_row * FSROW + (a_col + ks * 16) * 2,
                    ql[ks][0], ql[ks][1], ql[ks][2], ql[ks][3]);
        }
    }
    __syncthreads();   // all warps done reading Q staging before KV loads reuse smem

    // ---- KV loader (Kh + Vh, 3-stage)
    const size_t gkv = ((size_t)(b * TT)) * DD + h * HD;
    auto load_kv = [&](int kt) {
        const uint32_t st = sbase + (kt % 3) * FSTAGE;
        const size_t base = gkv + (size_t)(kt * 64) * DD;
        #pragma unroll
        for (int t = 0; t < 4; t++) {
            const int mat = t >> 1;
            const int row = (t & 1) * 32 + (tid >> 3);
            const __half* src = mat ? Vh_ : Kh_;
            cp_async16(st + mat * FTILE + row * FSROW + (tid & 7) * 16,
                       src + base + (size_t)row * DD + (tid & 7) * 8);
        }
        cp_commit();
    };

    float acc[8][4];
    #pragma unroll
    for (int i = 0; i < 8; i++)
        #pragma unroll
        for (int j = 0; j < 4; j++) acc[i][j] = 0.f;
    float m0 = -CUDART_INF_F, m1 = -CUDART_INF_F, l0 = 0.f, l1 = 0.f;

    const int ntiles = 2 * qb + 2;
    const int diag_kt = wrow >> 6;
    const int b_row = ((lane >> 4) & 1) * 8 + (lane & 7);
    const int b_col = ((lane >> 3) & 1) * 8;
    // scale folded into log2 domain: S2 = S_raw * (1/8) * log2(e)
    const float SCALE2 = 0.125f * 1.4426950408889634f;

    load_kv(0);
    if (ntiles > 1) load_kv(1);

    for (int kt = 0; kt < ntiles; kt++) {
        if (kt + 1 < ntiles) cp_wait<1>();
        else cp_wait<0>();
        __syncthreads();
        if (kt + 2 < ntiles) load_kv(kt + 2);

        const uint32_t st = sbase + (kt % 3) * FSTAGE;
        if (kt * 64 <= wrow) {
            // ---- S = (Qh+Ql) @ Kh^T
            float s[8][4];
            #pragma unroll
            for (int i = 0; i < 8; i++)
                #pragma unroll
                for (int j = 0; j < 4; j++) s[i][j] = 0.f;

            #pragma unroll
            for (int ks = 0; ks < 4; ks++) {
                #pragma unroll
                for (int p = 0; p < 4; p++) {
                    uint32_t kh[4];
                    ldsm_x4(st + (b_row + p * 16) * FSROW + (b_col + ks * 16) * 2,
                            kh[0], kh[1], kh[2], kh[3]);
                    mma16816(s[2 * p + 0], qh[ks], kh[0], kh[1]);
                    mma16816(s[2 * p + 1], qh[ks], kh[2], kh[3]);
                    mma16816(s[2 * p + 0], ql[ks], kh[0], kh[1]);
                    mma16816(s[2 * p + 1], ql[ks], kh[2], kh[3]);
                }
            }

            // ---- scale (log2 domain) + causal mask
            #pragma unroll
            for (int nt = 0; nt < 8; nt++)
                #pragma unroll
                for (int e = 0; e < 4; e++) s[nt][e] *= SCALE2;
            if (kt == diag_kt) {
                const int r0g = wrow + (lane >> 2);
                const int r1g = r0g + 8;
                #pragma unroll
                for (int nt = 0; nt < 8; nt++) {
                    #pragma unroll
                    for (int c = 0; c < 2; c++) {
                        const int col = kt * 64 + nt * 8 + (lane & 3) * 2 + c;
                        if (col > r0g) s[nt][c] = -1e30f;
                        if (col > r1g) s[nt][2 + c] = -1e30f;
                    }
                }
            }

            // ---- online softmax (base 2, in-warp quad reduction)
            float mx0 = -1e30f, mx1 = -1e30f;
            #pragma unroll
            for (int nt = 0; nt < 8; nt++) {
                mx0 = fmaxf(mx0, fmaxf(s[nt][0], s[nt][1]));
                mx1 = fmaxf(mx1, fmaxf(s[nt][2], s[nt][3]));
            }
            mx0 = fmaxf(mx0, __shfl_xor_sync(0xffffffffu, mx0, 1));
            mx0 = fmaxf(mx0, __shfl_xor_sync(0xffffffffu, mx0, 2));
            mx1 = fmaxf(mx1, __shfl_xor_sync(0xffffffffu, mx1, 1));
            mx1 = fmaxf(mx1, __shfl_xor_sync(0xffffffffu, mx1, 2));
            const float m0n = fmaxf(m0, mx0), m1n = fmaxf(m1, mx1);
            const float f0 = ex2(m0 - m0n), f1 = ex2(m1 - m1n);
            m0 = m0n; m1 = m1n;

            float sum0 = 0.f, sum1 = 0.f;
            #pragma unroll
            for (int nt = 0; nt < 8; nt++) {
                s[nt][0] = ex2(s[nt][0] - m0n); sum0 += s[nt][0];
                s[nt][1] = ex2(s[nt][1] - m0n); sum0 += s[nt][1];
                s[nt][2] = ex2(s[nt][2] - m1n); sum1 += s[nt][2];
                s[nt][3] = ex2(s[nt][3] - m1n); sum1 += s[nt][3];
            }
            sum0 += __shfl_xor_sync(0xffffffffu, sum0, 1);
            sum0 += __shfl_xor_sync(0xffffffffu, sum0, 2);
            sum1 += __shfl_xor_sync(0xffffffffu, sum1, 1);
            sum1 += __shfl_xor_sync(0xffffffffu, sum1, 2);
            l0 = f0 * l0 + sum0;
            l1 = f1 * l1 + sum1;

            #pragma unroll
            for (int nt = 0; nt < 8; nt++) {
                acc[nt][0] *= f0; acc[nt][1] *= f0;
                acc[nt][2] *= f1; acc[nt][3] *= f1;
            }

            // ---- P fragments: fp16 hi + residual lo (C->A frag remap)
            uint32_t aph[4][4], apl[4][4];
            #pragma unroll
            for (int kf = 0; kf < 4; kf++) {
                #pragma unroll
                for (int q = 0; q < 4; q++) {
                    const int t = 2 * kf + (q >> 1);
                    const int c = (q & 1) * 2;
                    const float x = s[t][c], y = s[t][c + 1];
                    const __half hx = __float2half(x), hy = __float2half(y);
                    __half2 hp(hx, hy);
                    aph[kf][q] = *(uint32_t*)&hp;
                    apl[kf][q] = pack_half2(x - __half2float(hx),
                                            y - __half2float(hy));
                }
            }

            // ---- O += (Ph+Pl) @ Vh (trans ldmatrix)
            #pragma unroll
            for (int kf = 0; kf < 4; kf++) {
                const int v_row = kf * 16 + ((lane >> 3) & 1) * 8 + (lane & 7);
                const int v_colb = ((lane >> 4) & 1) * 8;
                #pragma unroll
                for (int p = 0; p < 4; p++) {
                    uint32_t vh[4];
                    ldsm_x4_t(st + FTILE + v_row * FSROW + (p * 16 + v_colb) * 2,
                              vh[0], vh[1], vh[2], vh[3]);
                    mma16816(acc[2 * p + 0], aph[kf], vh[0], vh[1]);
                    mma16816(acc[2 * p + 1], aph[kf], vh[2], vh[3]);
                    mma16816(acc[2 * p + 0], apl[kf], vh[0], vh[1]);
                    mma16816(acc[2 * p + 1], apl[kf], vh[2], vh[3]);
                }
            }
        }
    }

    // ---- epilogue: normalize, fp16 hi only (Wo GEMM is 1-product)
    const float inv0 = 1.f / l0, inv1 = 1.f / l1;
    const size_t orow0 = ((size_t)(b * TT + wrow + (lane >> 2))) * DD + h * HD;
    const size_t orow1 = orow0 + (size_t)8 * DD;
    #pragma unroll
    for (int nt = 0; nt < 8; nt++) {
        const int col = nt * 8 + (lane & 3) * 2;
        *(__half2*)&Oh_[orow0 + col] =
            __half2(__float2half(acc[nt][0] * inv0), __float2half(acc[nt][1] * inv0));
        *(__half2*)&Oh_[orow1 + col] =
            __half2(__float2half(acc[nt][2] * inv1), __float2half(acc[nt][3] * inv1));
    }
}

// ---------------------------------------------------------------------------
// Launch
// ---------------------------------------------------------------------------
extern "C" void kernel_launch(void* const* d_in, const int* in_sizes, int n_in,
                              void* d_out, int out_size) {
    const float* xq  = (const float*)d_in[0];
    const float* xkv = (const float*)d_in[1];
    const float* Wq = (const float*)d_in[3];
    const float* Wk = (const float*)d_in[4];
    const float* Wv = (const float*)d_in[5];
    const float* Wo = (const float*)d_in[6];
    float* out = (float*)d_out;

    __half *qh, *ql, *kh, *vh, *xah, *xal, *xbh, *wt;
    cudaGetSymbolAddress((void**)&qh, g_qh);
    cudaGetSymbolAddress((void**)&ql, g_ql);
    cudaGetSymbolAddress((void**)&kh, g_kh);
    cudaGetSymbolAddress((void**)&vh, g_vh);
    cudaGetSymbolAddress((void**)&xah, g_xa_h);
    cudaGetSymbolAddress((void**)&xal, g_xa_l);
    cudaGetSymbolAddress((void**)&xbh, g_xb_h);
    cudaGetSymbolAddress((void**)&wt, g_wt);

    cudaFuncSetAttribute(qkv_mma_kernel, cudaFuncAttributeMaxDynamicSharedMemorySize,
                         GEMM_SMEM);
    cudaFuncSetAttribute(wo_mma_kernel, cudaFuncAttributeMaxDynamicSharedMemorySize,
                         GEMM_SMEM);
    cudaFuncSetAttribute(flash_mma_kernel, cudaFuncAttributeMaxDynamicSharedMemorySize,
                         FLASH_SMEM);

    const int n4 = MROWS * DD / 4;
    aconv_kernel<<<(n4 + 255) / 256, 256>>>(xq, xah, xal, n4);
    aconv_h_kernel<<<(n4 + 255) / 256, 256>>>(xkv, xbh, n4);
    wconv_kernel<<<dim3(32, 32, 4), dim3(32, 8)>>>(Wq, Wk, Wv, Wo, wt);

    qkv_mma_kernel<<<dim3(DD / 128, MROWS / 128, 3), 256, GEMM_SMEM>>>(
        xah, xal, xbh, wt, qh, ql, kh, vh);

    // flash writes attn output hi into xah (Q-GEMM already consumed it)
    flash_mma_kernel<<<dim3(TT / 128, BB * HH), 256, FLASH_SMEM>>>(
        qh, ql, kh, vh, xah);

    wo_mma_kernel<<<dim3(DD / 128, MROWS / 128), 256, GEMM_SMEM>>>(
        xah, wt + (size_t)3 * DD * DD, out);
}

// round 15
// speedup vs baseline: 6.2900x; 1.1757x over previous
#include <cuda_runtime.h>
#include <cuda_fp16.h>
#include <math_constants.h>
#include <cstdint>

// Problem constants
#define BB   2
#define TT   2048
#define DD   1024
#define HH   16
#define HD   64
#define MROWS (BB*TT)        // 4096

// ---------------------------------------------------------------------------
// Scratch (device globals; allocation forbidden)
// ---------------------------------------------------------------------------
__device__ __half g_qh[MROWS * DD];
__device__ __half g_ql[MROWS * DD];            // residual of Q output rounding
__device__ __half g_kh[MROWS * DD];            // hi only
__device__ __half g_vh[MROWS * DD];            // hi only

__device__ __half g_xa_h[MROWS * DD];          // xq hi (reused: attn out hi)
__device__ __half g_xb_h[MROWS * DD];          // xkv hi
__device__ __half g_wt[4 * DD * DD];           // transposed weights hi [n][k]

// ---------------------------------------------------------------------------
// PTX helpers
// ---------------------------------------------------------------------------
__device__ __forceinline__ uint32_t smem_to_u32(const void* p) {
    uint32_t a;
    asm("{ .reg .u64 t; cvta.to.shared.u64 t, %1; cvt.u32.u64 %0, t; }"
        : "=r"(a) : "l"(p));
    return a;
}
__device__ __forceinline__ void cp_async16(uint32_t sa, const void* g) {
    asm volatile("cp.async.cg.shared.global [%0], [%1], 16;" :: "r"(sa), "l"(g));
}
__device__ __forceinline__ void cp_commit() {
    asm volatile("cp.async.commit_group;");
}
template <int N>
__device__ __forceinline__ void cp_wait() {
    asm volatile("cp.async.wait_group %0;" :: "n"(N));
}
__device__ __forceinline__ void ldsm_x4(uint32_t addr, uint32_t& r0, uint32_t& r1,
                                        uint32_t& r2, uint32_t& r3) {
    asm volatile("ldmatrix.sync.aligned.m8n8.x4.shared.b16 {%0,%1,%2,%3}, [%4];"
                 : "=r"(r0), "=r"(r1), "=r"(r2), "=r"(r3) : "r"(addr));
}
__device__ __forceinline__ void ldsm_x4_t(uint32_t addr, uint32_t& r0, uint32_t& r1,
                                          uint32_t& r2, uint32_t& r3) {
    asm volatile("ldmatrix.sync.aligned.m8n8.x4.trans.shared.b16 {%0,%1,%2,%3}, [%4];"
                 : "=r"(r0), "=r"(r1), "=r"(r2), "=r"(r3) : "r"(addr));
}
__device__ __forceinline__ void mma16816(float* c, const uint32_t* a,
                                         uint32_t b0, uint32_t b1) {
    asm volatile(
        "mma.sync.aligned.m16n8k16.row.col.f32.f16.f16.f32 "
        "{%0,%1,%2,%3}, {%4,%5,%6,%7}, {%8,%9}, {%0,%1,%2,%3};"
        : "+f"(c[0]), "+f"(c[1]), "+f"(c[2]), "+f"(c[3])
        : "r"(a[0]), "r"(a[1]), "r"(a[2]), "r"(a[3]), "r"(b0), "r"(b1));
}
__device__ __forceinline__ uint32_t pack_half2(float x, float y) {
    __half2 v(__float2half(x), __float2half(y));
    return *(uint32_t*)&v;
}
__device__ __forceinline__ float ex2(float x) {
    float r;
    asm("ex2.approx.ftz.f32 %0, %1;" : "=f"(r) : "f"(x));
    return r;
}

// ---------------------------------------------------------------------------
// Activation fp32 -> fp16 (hi only)
// ---------------------------------------------------------------------------
__global__ __launch_bounds__(256)
void aconv_h_kernel(const float* __restrict__ X, __half* __restrict__ Xh, int n4) {
    int i = blockIdx.x * blockDim.x + threadIdx.x;
    if (i >= n4) return;
    float4 v = ((const float4*)X)[i];
    ((__half2*)Xh)[i * 2 + 0] = __half2(__float2half(v.x), __float2half(v.y));
    ((__half2*)Xh)[i * 2 + 1] = __half2(__float2half(v.z), __float2half(v.w));
}

// ---------------------------------------------------------------------------
// Weight transpose + fp16 round: W[k][n] fp32 -> Wt[n][k] fp16 hi only.
// ---------------------------------------------------------------------------
__global__ __launch_bounds__(256)
void wconv_kernel(const float* __restrict__ W0, const float* __restrict__ W1,
                  const float* __restrict__ W2, const float* __restrict__ W3,
                  __half* __restrict__ T) {
    __shared__ float t[32][33];
    const int z = blockIdx.z;
    const float* W = (z == 0) ? W0 : (z == 1) ? W1 : (z == 2) ? W2 : W3;
    __half* Th = T + (size_t)z * DD * DD;
    const int tx = threadIdx.x, ty = threadIdx.y;
    const int k0 = blockIdx.y * 32, n0 = blockIdx.x * 32;
    #pragma unroll
    for (int i = 0; i < 4; i++)
        t[ty + 8 * i][tx] = W[(size_t)(k0 + ty + 8 * i) * DD + n0 + tx];
    __syncthreads();
    #pragma unroll
    for (int i = 0; i < 4; i++) {
        Th[(size_t)(n0 + ty + 8 * i) * DD + k0 + tx] =
            __float2half(t[tx][ty + 8 * i]);
    }
}

// ---------------------------------------------------------------------------
// fp16 1-product GEMM mainloop. C = Ah[M,K] @ Bh; Bh pre-transposed [N,K].
// CTA tile 128x128, 8 warps, K-chunk 64. 3-stage cp.async, one sync/chunk,
// wait<1> keeps one chunk in flight. 2 CTAs/SM (smem 110592*2; 128 regs).
// ---------------------------------------------------------------------------
#define KC        64
#define SROW      144                      // 64 fp16 = 128B + 16B pad
#define MAT_B     (128 * SROW)             // 18432
#define G_STAGE   (2 * MAT_B)              // 36864 (A, B)
#define GEMM_SMEM (3 * G_STAGE)            // 110592

__device__ __forceinline__ void gemm_mainloop(
    const __half* __restrict__ Ah, const __half* __restrict__ Bh,
    int bm, int bn, int K, uint32_t sbase, int tid, float acc[2][8][4]) {
    const int lane = tid & 31;
    const int wid = tid >> 5;
    const int wm = wid >> 1;
    const int wn = wid & 1;
    const int nchunks = K / KC;            // 16

    const int lrow = tid >> 3;             // 0..31 (+32*g)
    const int lseg = tid & 7;              // 16B segment in 128B row

    auto load_chunk = [&](int c) {
        const int k0 = c * KC;
        const uint32_t st = sbase + (c % 3) * G_STAGE;
        #pragma unroll
        for (int t = 0; t < 8; t++) {
            const int mat = t >> 2;                  // 0=A, 1=B
            const int row = (t & 3) * 32 + lrow;
            const __half* src = mat ? Bh : Ah;
            const int grow = (mat ? bn : bm) + row;
            cp_async16(st + mat * MAT_B + row * SROW + lseg * 16,
                       src + (size_t)grow * K + k0 + lseg * 8);
        }
        cp_commit();
    };

    const int a_row = wm * 32 + (lane & 15);
    const int a_col = (lane >> 4) * 8;
    const int b_row = wn * 64 + ((lane >> 4) & 1) * 8 + (lane & 7);
    const int b_col = ((lane >> 3) & 1) * 8;

    load_chunk(0);
    load_chunk(1);

    for (int c = 0; c < nchunks; c++) {
        if (c + 1 < nchunks) cp_wait<1>();
        else cp_wait<0>();
        __syncthreads();
        // Stage (c+2)%3 was consumed at iteration c-1; barrier above makes
        // reuse safe for all warps.
        if (c + 2 < nchunks) load_chunk(c + 2);

        const uint32_t st = sbase + (c % 3) * G_STAGE;
        #pragma unroll
        for (int kstep = 0; kstep < 4; kstep++) {
            uint32_t ah[2][4], bh[4][4];
            #pragma unroll
            for (int mt = 0; mt < 2; mt++) {
                ldsm_x4(st + (a_row + mt * 16) * SROW + (a_col + kstep * 16) * 2,
                        ah[mt][0], ah[mt][1], ah[mt][2], ah[mt][3]);
            }
            #pragma unroll
            for (int p = 0; p < 4; p++) {
                ldsm_x4(st + MAT_B + (b_row + p * 16) * SROW + (b_col + kstep * 16) * 2,
                        bh[p][0], bh[p][1], bh[p][2], bh[p][3]);
            }
            #pragma unroll
            for (int mt = 0; mt < 2; mt++) {
                #pragma unroll
                for (int p = 0; p < 4; p++) {
                    mma16816(acc[mt][2 * p + 0], ah[mt], bh[p][0], bh[p][1]);
                    mma16816(acc[mt][2 * p + 1], ah[mt], bh[p][2], bh[p][3]);
                }
            }
        }
    }
}

// Fused QKV GEMM: grid (8, 32, 3). z=0: Q (writes hi + residual-lo);
// z=1: K (hi); z=2: V (hi). All 1-product.
__global__ __launch_bounds__(256, 2)
void qkv_mma_kernel(const __half* __restrict__ xah, const __half* __restrict__ xbh,
                    const __half* __restrict__ Wt,
                    __half* __restrict__ Qh, __half* __restrict__ Ql,
                    __half* __restrict__ Kh, __half* __restrict__ Vh) {
    extern __shared__ char smem[];
    const uint32_t sbase = smem_to_u32(smem);
    const int tid = threadIdx.x;
    const int z = blockIdx.z;
    const int bm = blockIdx.y * 128;
    const int bn = blockIdx.x * 128;

    const __half* Ah = (z == 0) ? xah : xbh;
    const __half* Bh = Wt + (size_t)z * DD * DD;

    float acc[2][8][4];
    #pragma unroll
    for (int i = 0; i < 2; i++)
        #pragma unroll
        for (int j = 0; j < 8; j++)
            #pragma unroll
            for (int q = 0; q < 4; q++) acc[i][j][q] = 0.f;

    gemm_mainloop(Ah, Bh, bm, bn, DD, sbase, tid, acc);

    const int lane = tid & 31, wid = tid >> 5;
    const int wm = wid >> 1, wn = wid & 1;
    const int er = lane >> 2, ec = (lane & 3) * 2;
    #pragma unroll
    for (int mt = 0; mt < 2; mt++) {
        const int row0 = bm + wm * 32 + mt * 16 + er;
        #pragma unroll
        for (int nt = 0; nt < 8; nt++) {
            const int col = bn + wn * 64 + nt * 8 + ec;
            #pragma unroll
            for (int half_ = 0; half_ < 2; half_++) {
                const size_t o = (size_t)(row0 + half_ * 8) * DD + col;
                const float x = acc[mt][nt][2 * half_];
                const float y = acc[mt][nt][2 * half_ + 1];
                const __half hx = __float2half(x), hy = __float2half(y);
                if (z == 0) {
                    *(__half2*)&Qh[o] = __half2(hx, hy);
                    *(__half2*)&Ql[o] = __half2(
                        __float2half(x - __half2float(hx)),
                        __float2half(y - __half2float(hy)));
                } else {
                    __half* dst = (z == 1) ? Kh : Vh;
                    *(__half2*)&dst[o] = __half2(hx, hy);
                }
            }
        }
    }
}

// Wo GEMM: 1-product, fp32 out.
__global__ __launch_bounds__(256, 2)
void wo_mma_kernel(const __half* __restrict__ Ah,
                   const __half* __restrict__ Bh, float* __restrict__ C) {
    extern __shared__ char smem[];
    const uint32_t sbase = smem_to_u32(smem);
    const int tid = threadIdx.x;
    const int bm = blockIdx.y * 128;
    const int bn = blockIdx.x * 128;

    float acc[2][8][4];
    #pragma unroll
    for (int i = 0; i < 2; i++)
        #pragma unroll
        for (int j = 0; j < 8; j++)
            #pragma unroll
            for (int q = 0; q < 4; q++) acc[i][j][q] = 0.f;

    gemm_mainloop(Ah, Bh, bm, bn, DD, sbase, tid, acc);

    const int lane = tid & 31, wid = tid >> 5;
    const int wm = wid >> 1, wn = wid & 1;
    const int er = lane >> 2, ec = (lane & 3) * 2;
    #pragma unroll
    for (int mt = 0; mt < 2; mt++) {
        const int row0 = bm + wm * 32 + mt * 16 + er;
        #pragma unroll
        for (int nt = 0; nt < 8; nt++) {
            const int col = bn + wn * 64 + nt * 8 + ec;
            *(float2*)&C[(size_t)row0 * DD + col] =
                make_float2(acc[mt][nt][0], acc[mt][nt][1]);
            *(float2*)&C[(size_t)(row0 + 8) * DD + col] =
                make_float2(acc[mt][nt][2], acc[mt][nt][3]);
        }
    }
}

// ---------------------------------------------------------------------------
// Flash attention fp16 mma (causal). BQ=128, BKV=64, HD=64.
// S = (Qh+Ql)·Kh^T; PV = (Ph+Pl)·Vh. Base-2 softmax (ex2.approx).
// 3-stage KV pipeline, one sync/tile, 2 CTAs/SM. Output: hi only.
// ---------------------------------------------------------------------------
#define FSROW  144                          // 64 fp16 = 128B + 16B pad
#define FTILE  (64 * FSROW)                 // 9216
#define FSTAGE (2 * FTILE)                  // 18432 (Kh, Vh)
#define FLASH_SMEM (3 * FSTAGE)             // 55296 (Q staging 36864 fits)

__global__ __launch_bounds__(256, 2)
void flash_mma_kernel(const __half* __restrict__ Qh_, const __half* __restrict__ Ql_,
                      const __half* __restrict__ Kh_, const __half* __restrict__ Vh_,
                      __half* __restrict__ Oh_) {
    extern __shared__ char smem[];
    const uint32_t sbase = smem_to_u32(smem);
    const int qb = (int)gridDim.x - 1 - (int)blockIdx.x;   // heavy first
    const int bh = blockIdx.y;
    const int b = bh >> 4, h = bh & 15;
    const int tid = threadIdx.x, lane = tid & 31, wid = tid >> 5;
    const int wrow = qb * 128 + wid * 16;

    // ---- Stage Q (hi at 0, lo at 128*FSROW), extract fragments
    {
        const size_t gq = ((size_t)(b * TT + qb * 128)) * DD + h * HD;
        #pragma unroll
        for (int t = 0; t < 8; t++) {
            const int mat = t >> 2;
            const int row = (t & 3) * 32 + (tid >> 3);
            const __half* src = mat ? Ql_ : Qh_;
            cp_async16(sbase + mat * (128 * FSROW) + row * FSROW + (tid & 7) * 16,
                       src + gq + (size_t)row * DD + (tid & 7) * 8);
        }
        cp_commit(); cp_wait<0>();
        __syncthreads();
    }
    uint32_t qh[4][4], ql[4][4];
    {
        const int a_row = wid * 16 + (lane & 15);
        const int a_col = (lane >> 4) * 8;
        #pragma unroll
        for (int ks = 0; ks < 4; ks++) {
            ldsm_x4(sbase + a_row * FSROW + (a_col + ks * 16) * 2,
                    qh[ks][0], qh[ks][1], qh[ks][2], qh[ks][3]);
            ldsm_x4(sbase + 128 * FSROW + a_row * FSROW + (a_col + ks * 16) * 2,
                    ql[ks][0], ql[ks][1], ql[ks][2], ql[ks][3]);
        }
    }
    __syncthreads();   // all warps done reading Q staging before KV loads reuse smem

    // ---- KV loader (Kh + Vh, 3-stage)
    const size_t gkv = ((size_t)(b * TT)) * DD + h * HD;
    auto load_kv = [&](int kt) {
        const uint32_t st = sbase + (kt % 3) * FSTAGE;
        const size_t base = gkv + (size_t)(kt * 64) * DD;
        #pragma unroll
        for (int t = 0; t < 4; t++) {
            const int mat = t >> 1;
            const int row = (t & 1) * 32 + (tid >> 3);
            const __half* src = mat ? Vh_ : Kh_;
            cp_async16(st + mat * FTILE + row * FSROW + (tid & 7) * 16,
                       src + base + (size_t)row * DD + (tid & 7) * 8);
        }
        cp_commit();
    };

    float acc[8][4];
    #pragma unroll
    for (int i = 0; i < 8; i++)
        #pragma unroll
        for (int j = 0; j < 4; j++) acc[i][j] = 0.f;
    float m0 = -CUDART_INF_F, m1 = -CUDART_INF_F, l0 = 0.f, l1 = 0.f;

    const int ntiles = 2 * qb + 2;
    const int diag_kt = wrow >> 6;
    const int b_row = ((lane >> 4) & 1) * 8 + (lane & 7);
    const int b_col = ((lane >> 3) & 1) * 8;
    const float SCALE2 = 0.125f * 1.4426950408889634f;

    load_kv(0);
    if (ntiles > 1) load_kv(1);

    for (int kt = 0; kt < ntiles; kt++) {
        if (kt + 1 < ntiles) cp_wait<1>();
        else cp_wait<0>();
        __syncthreads();
        if (kt + 2 < ntiles) load_kv(kt + 2);

        const uint32_t st = sbase + (kt % 3) * FSTAGE;
        if (kt * 64 <= wrow) {
            // ---- S = (Qh+Ql) @ Kh^T
            float s[8][4];
            #pragma unroll
            for (int i = 0; i < 8; i++)
                #pragma unroll
                for (int j = 0; j < 4; j++) s[i][j] = 0.f;

            #pragma unroll
            for (int ks = 0; ks < 4; ks++) {
                #pragma unroll
                for (int p = 0; p < 4; p++) {
                    uint32_t kh[4];
                    ldsm_x4(st + (b_row + p * 16) * FSROW + (b_col + ks * 16) * 2,
                            kh[0], kh[1], kh[2], kh[3]);
                    mma16816(s[2 * p + 0], qh[ks], kh[0], kh[1]);
                    mma16816(s[2 * p + 1], qh[ks], kh[2], kh[3]);
                    mma16816(s[2 * p + 0], ql[ks], kh[0], kh[1]);
                    mma16816(s[2 * p + 1], ql[ks], kh[2], kh[3]);
                }
            }

            // ---- scale (log2 domain) + causal mask
            #pragma unroll
            for (int nt = 0; nt < 8; nt++)
                #pragma unroll
                for (int e = 0; e < 4; e++) s[nt][e] *= SCALE2;
            if (kt == diag_kt) {
                const int r0g = wrow + (lane >> 2);
                const int r1g = r0g + 8;
                #pragma unroll
                for (int nt = 0; nt < 8; nt++) {
                    #pragma unroll
                    for (int c = 0; c < 2; c++) {
                        const int col = kt * 64 + nt * 8 + (lane & 3) * 2 + c;
                        if (col > r0g) s[nt][c] = -1e30f;
                        if (col > r1g) s[nt][2 + c] = -1e30f;
                    }
                }
            }

            // ---- online softmax (base 2, in-warp quad reduction)
            float mx0 = -1e30f, mx1 = -1e30f;
            #pragma unroll
            for (int nt = 0; nt < 8; nt++) {
                mx0 = fmaxf(mx0, fmaxf(s[nt][0], s[nt][1]));
                mx1 = fmaxf(mx1, fmaxf(s[nt][2], s[nt][3]));
            }
            mx0 = fmaxf(mx0, __shfl_xor_sync(0xffffffffu, mx0, 1));
            mx0 = fmaxf(mx0, __shfl_xor_sync(0xffffffffu, mx0, 2));
            mx1 = fmaxf(mx1, __shfl_xor_sync(0xffffffffu, mx1, 1));
            mx1 = fmaxf(mx1, __shfl_xor_sync(0xffffffffu, mx1, 2));
            const float m0n = fmaxf(m0, mx0), m1n = fmaxf(m1, mx1);
            const float f0 = ex2(m0 - m0n), f1 = ex2(m1 - m1n);
            m0 = m0n; m1 = m1n;

            float sum0 = 0.f, sum1 = 0.f;
            #pragma unroll
            for (int nt = 0; nt < 8; nt++) {
                s[nt][0] = ex2(s[nt][0] - m0n); sum0 += s[nt][0];
                s[nt][1] = ex2(s[nt][1] - m0n); sum0 += s[nt][1];
                s[nt][2] = ex2(s[nt][2] - m1n); sum1 += s[nt][2];
                s[nt][3] = ex2(s[nt][3] - m1n); sum1 += s[nt][3];
            }
            sum0 += __shfl_xor_sync(0xffffffffu, sum0, 1);
            sum0 += __shfl_xor_sync(0xffffffffu, sum0, 2);
            sum1 += __shfl_xor_sync(0xffffffffu, sum1, 1);
            sum1 += __shfl_xor_sync(0xffffffffu, sum1, 2);
            l0 = f0 * l0 + sum0;
            l1 = f1 * l1 + sum1;

            #pragma unroll
            for (int nt = 0; nt < 8; nt++) {
                acc[nt][0] *= f0; acc[nt][1] *= f0;
                acc[nt][2] *= f1; acc[nt][3] *= f1;
            }

            // ---- P fragments: fp16 hi + residual lo (C->A frag remap)
            uint32_t aph[4][4], apl[4][4];
            #pragma unroll
            for (int kf = 0; kf < 4; kf++) {
                #pragma unroll
                for (int q = 0; q < 4; q++) {
                    const int t = 2 * kf + (q >> 1);
                    const int c = (q & 1) * 2;
                    const float x = s[t][c], y = s[t][c + 1];
                    const __half hx = __float2half(x), hy = __float2half(y);
                    __half2 hp(hx, hy);
                    aph[kf][q] = *(uint32_t*)&hp;
                    apl[kf][q] = pack_half2(x - __half2float(hx),
                                            y - __half2float(hy));
                }
            }

            // ---- O += (Ph+Pl) @ Vh (trans ldmatrix)
            #pragma unroll
            for (int kf = 0; kf < 4; kf++) {
                const int v_row = kf * 16 + ((lane >> 3) & 1) * 8 + (lane & 7);
                const int v_colb = ((lane >> 4) & 1) * 8;
                #pragma unroll
                for (int p = 0; p < 4; p++) {
                    uint32_t vh[4];
                    ldsm_x4_t(st + FTILE + v_row * FSROW + (p * 16 + v_colb) * 2,
                              vh[0], vh[1], vh[2], vh[3]);
                    mma16816(acc[2 * p + 0], aph[kf], vh[0], vh[1]);
                    mma16816(acc[2 * p + 1], aph[kf], vh[2], vh[3]);
                    mma16816(acc[2 * p + 0], apl[kf], vh[0], vh[1]);
                    mma16816(acc[2 * p + 1], apl[kf], vh[2], vh[3]);
                }
            }
        }
    }

    // ---- epilogue: normalize, fp16 hi only (Wo GEMM is 1-product)
    const float inv0 = 1.f / l0, inv1 = 1.f / l1;
    const size_t orow0 = ((size_t)(b * TT + wrow + (lane >> 2))) * DD + h * HD;
    const size_t orow1 = orow0 + (size_t)8 * DD;
    #pragma unroll
    for (int nt = 0; nt < 8; nt++) {
        const int col = nt * 8 + (lane & 3) * 2;
        *(__half2*)&Oh_[orow0 + col] =
            __half2(__float2half(acc[nt][0] * inv0), __float2half(acc[nt][1] * inv0));
        *(__half2*)&Oh_[orow1 + col] =
            __half2(__float2half(acc[nt][2] * inv1), __float2half(acc[nt][3] * inv1));
    }
}

// ---------------------------------------------------------------------------
// Launch
// ---------------------------------------------------------------------------
extern "C" void kernel_launch(void* const* d_in, const int* in_sizes, int n_in,
                              void* d_out, int out_size) {
    const float* xq  = (const float*)d_in[0];
    const float* xkv = (const float*)d_in[1];
    const float* Wq = (const float*)d_in[3];
    const float* Wk = (const float*)d_in[4];
    const float* Wv = (const float*)d_in[5];
    const float* Wo = (const float*)d_in[6];
    float* out = (float*)d_out;

    __half *qh, *ql, *kh, *vh, *xah, *xbh, *wt;
    cudaGetSymbolAddress((void**)&qh, g_qh);
    cudaGetSymbolAddress((void**)&ql, g_ql);
    cudaGetSymbolAddress((void**)&kh, g_kh);
    cudaGetSymbolAddress((void**)&vh, g_vh);
    cudaGetSymbolAddress((void**)&xah, g_xa_h);
    cudaGetSymbolAddress((void**)&xbh, g_xb_h);
    cudaGetSymbolAddress((void**)&wt, g_wt);

    cudaFuncSetAttribute(qkv_mma_kernel, cudaFuncAttributeMaxDynamicSharedMemorySize,
                         GEMM_SMEM);
    cudaFuncSetAttribute(wo_mma_kernel, cudaFuncAttributeMaxDynamicSharedMemorySize,
                         GEMM_SMEM);
    cudaFuncSetAttribute(flash_mma_kernel, cudaFuncAttributeMaxDynamicSharedMemorySize,
                         FLASH_SMEM);

    const int n4 = MROWS * DD / 4;
    aconv_h_kernel<<<(n4 + 255) / 256, 256>>>(xq,  xah, n4);
    aconv_h_kernel<<<(n4 + 255) / 256, 256>>>(xkv, xbh, n4);
    wconv_kernel<<<dim3(32, 32, 4), dim3(32, 8)>>>(Wq, Wk, Wv, Wo, wt);

    qkv_mma_kernel<<<dim3(DD / 128, MROWS / 128, 3), 256, GEMM_SMEM>>>(
        xah, xbh, wt, qh, ql, kh, vh);

    // flash writes attn output hi into xah (Q-GEMM already consumed it)
    flash_mma_kernel<<<dim3(TT / 128, BB * HH), 256, FLASH_SMEM>>>(
        qh, ql, kh, vh, xah);

    wo_mma_kernel<<<dim3(DD / 128, MROWS / 128), 256, GEMM_SMEM>>>(
        xah, wt + (size_t)3 * DD * DD, out);
}

// round 16
// speedup vs baseline: 6.9138x; 1.0992x over previous
#include <cuda_runtime.h>
#include <cuda_fp16.h>
#include <math_constants.h>
#include <cstdint>

// Problem constants
#define BB   2
#define TT   2048
#define DD   1024
#define HH   16
#define HD   64
#define MROWS (BB*TT)        // 4096

// ---------------------------------------------------------------------------
// Scratch (device globals; allocation forbidden)
// ---------------------------------------------------------------------------
__device__ __half g_qh[MROWS * DD];            // hi only (S uncompensated both sides)
__device__ __half g_kh[MROWS * DD];            // hi only
__device__ __half g_vh[MROWS * DD];            // hi only

__device__ __half g_xa_h[MROWS * DD];          // xq hi (reused: attn out hi)
__device__ __half g_xb_h[MROWS * DD];          // xkv hi
__device__ __half g_wt[4 * DD * DD];           // transposed weights hi [n][k]

// ---------------------------------------------------------------------------
// PTX helpers
// ---------------------------------------------------------------------------
__device__ __forceinline__ uint32_t smem_to_u32(const void* p) {
    uint32_t a;
    asm("{ .reg .u64 t; cvta.to.shared.u64 t, %1; cvt.u32.u64 %0, t; }"
        : "=r"(a) : "l"(p));
    return a;
}
__device__ __forceinline__ void cp_async16(uint32_t sa, const void* g) {
    asm volatile("cp.async.cg.shared.global [%0], [%1], 16;" :: "r"(sa), "l"(g));
}
__device__ __forceinline__ void cp_commit() {
    asm volatile("cp.async.commit_group;");
}
template <int N>
__device__ __forceinline__ void cp_wait() {
    asm volatile("cp.async.wait_group %0;" :: "n"(N));
}
__device__ __forceinline__ void ldsm_x4(uint32_t addr, uint32_t& r0, uint32_t& r1,
                                        uint32_t& r2, uint32_t& r3) {
    asm volatile("ldmatrix.sync.aligned.m8n8.x4.shared.b16 {%0,%1,%2,%3}, [%4];"
                 : "=r"(r0), "=r"(r1), "=r"(r2), "=r"(r3) : "r"(addr));
}
__device__ __forceinline__ void ldsm_x4_t(uint32_t addr, uint32_t& r0, uint32_t& r1,
                                          uint32_t& r2, uint32_t& r3) {
    asm volatile("ldmatrix.sync.aligned.m8n8.x4.trans.shared.b16 {%0,%1,%2,%3}, [%4];"
                 : "=r"(r0), "=r"(r1), "=r"(r2), "=r"(r3) : "r"(addr));
}
__device__ __forceinline__ void mma16816(float* c, const uint32_t* a,
                                         uint32_t b0, uint32_t b1) {
    asm volatile(
        "mma.sync.aligned.m16n8k16.row.col.f32.f16.f16.f32 "
        "{%0,%1,%2,%3}, {%4,%5,%6,%7}, {%8,%9}, {%0,%1,%2,%3};"
        : "+f"(c[0]), "+f"(c[1]), "+f"(c[2]), "+f"(c[3])
        : "r"(a[0]), "r"(a[1]), "r"(a[2]), "r"(a[3]), "r"(b0), "r"(b1));
}
__device__ __forceinline__ uint32_t pack_half2(float x, float y) {
    __half2 v(__float2half(x), __float2half(y));
    return *(uint32_t*)&v;
}
__device__ __forceinline__ float ex2(float x) {
    float r;
    asm("ex2.approx.ftz.f32 %0, %1;" : "=f"(r) : "f"(x));
    return r;
}

// ---------------------------------------------------------------------------
// Activation fp32 -> fp16 (hi only)
// ---------------------------------------------------------------------------
__global__ __launch_bounds__(256)
void aconv_h_kernel(const float* __restrict__ X, __half* __restrict__ Xh, int n4) {
    int i = blockIdx.x * blockDim.x + threadIdx.x;
    if (i >= n4) return;
    float4 v = ((const float4*)X)[i];
    ((__half2*)Xh)[i * 2 + 0] = __half2(__float2half(v.x), __float2half(v.y));
    ((__half2*)Xh)[i * 2 + 1] = __half2(__float2half(v.z), __float2half(v.w));
}

// ---------------------------------------------------------------------------
// Weight transpose + fp16 round: W[k][n] fp32 -> Wt[n][k] fp16 hi only.
// ---------------------------------------------------------------------------
__global__ __launch_bounds__(256)
void wconv_kernel(const float* __restrict__ W0, const float* __restrict__ W1,
                  const float* __restrict__ W2, const float* __restrict__ W3,
                  __half* __restrict__ T) {
    __shared__ float t[32][33];
    const int z = blockIdx.z;
    const float* W = (z == 0) ? W0 : (z == 1) ? W1 : (z == 2) ? W2 : W3;
    __half* Th = T + (size_t)z * DD * DD;
    const int tx = threadIdx.x, ty = threadIdx.y;
    const int k0 = blockIdx.y * 32, n0 = blockIdx.x * 32;
    #pragma unroll
    for (int i = 0; i < 4; i++)
        t[ty + 8 * i][tx] = W[(size_t)(k0 + ty + 8 * i) * DD + n0 + tx];
    __syncthreads();
    #pragma unroll
    for (int i = 0; i < 4; i++) {
        Th[(size_t)(n0 + ty + 8 * i) * DD + k0 + tx] =
            __float2half(t[tx][ty + 8 * i]);
    }
}

// ---------------------------------------------------------------------------
// fp16 1-product GEMM mainloop. C = Ah[M,K] @ Bh; Bh pre-transposed [N,K].
// CTA tile 128x128, 8 warps, K-chunk 64. 3-stage cp.async, one sync/chunk,
// wait<1> keeps one chunk in flight. 2 CTAs/SM. B-ldsm interleaved with MMAs.
// ---------------------------------------------------------------------------
#define KC        64
#define SROW      144                      // 64 fp16 = 128B + 16B pad
#define MAT_B     (128 * SROW)             // 18432
#define G_STAGE   (2 * MAT_B)              // 36864 (A, B)
#define GEMM_SMEM (3 * G_STAGE)            // 110592

__device__ __forceinline__ void gemm_mainloop(
    const __half* __restrict__ Ah, const __half* __restrict__ Bh,
    int bm, int bn, int K, uint32_t sbase, int tid, float acc[2][8][4]) {
    const int lane = tid & 31;
    const int wid = tid >> 5;
    const int wm = wid >> 1;
    const int wn = wid & 1;
    const int nchunks = K / KC;            // 16

    const int lrow = tid >> 3;             // 0..31 (+32*g)
    const int lseg = tid & 7;              // 16B segment in 128B row

    auto load_chunk = [&](int c) {
        const int k0 = c * KC;
        const uint32_t st = sbase + (c % 3) * G_STAGE;
        #pragma unroll
        for (int t = 0; t < 8; t++) {
            const int mat = t >> 2;                  // 0=A, 1=B
            const int row = (t & 3) * 32 + lrow;
            const __half* src = mat ? Bh : Ah;
            const int grow = (mat ? bn : bm) + row;
            cp_async16(st + mat * MAT_B + row * SROW + lseg * 16,
                       src + (size_t)grow * K + k0 + lseg * 8);
        }
        cp_commit();
    };

    const int a_row = wm * 32 + (lane & 15);
    const int a_col = (lane >> 4) * 8;
    const int b_row = wn * 64 + ((lane >> 4) & 1) * 8 + (lane & 7);
    const int b_col = ((lane >> 3) & 1) * 8;

    load_chunk(0);
    load_chunk(1);

    for (int c = 0; c < nchunks; c++) {
        if (c + 1 < nchunks) cp_wait<1>();
        else cp_wait<0>();
        __syncthreads();
        // Stage (c+2)%3 was consumed at iteration c-1; barrier above makes
        // reuse safe for all warps.
        if (c + 2 < nchunks) load_chunk(c + 2);

        const uint32_t st = sbase + (c % 3) * G_STAGE;
        #pragma unroll
        for (int kstep = 0; kstep < 4; kstep++) {
            uint32_t ah[2][4];
            #pragma unroll
            for (int mt = 0; mt < 2; mt++) {
                ldsm_x4(st + (a_row + mt * 16) * SROW + (a_col + kstep * 16) * 2,
                        ah[mt][0], ah[mt][1], ah[mt][2], ah[mt][3]);
            }
            // interleave: each B ldsm immediately followed by its 4 MMAs
            #pragma unroll
            for (int p = 0; p < 4; p++) {
                uint32_t bh[4];
                ldsm_x4(st + MAT_B + (b_row + p * 16) * SROW + (b_col + kstep * 16) * 2,
                        bh[0], bh[1], bh[2], bh[3]);
                #pragma unroll
                for (int mt = 0; mt < 2; mt++) {
                    mma16816(acc[mt][2 * p + 0], ah[mt], bh[0], bh[1]);
                    mma16816(acc[mt][2 * p + 1], ah[mt], bh[2], bh[3]);
                }
            }
        }
    }
}

// Fused QKV GEMM: grid (8, 32, 3). z selects Q/K/V; all 1-product, hi-only out.
__global__ __launch_bounds__(256, 2)
void qkv_mma_kernel(const __half* __restrict__ xah, const __half* __restrict__ xbh,
                    const __half* __restrict__ Wt,
                    __half* __restrict__ Qh, __half* __restrict__ Kh,
                    __half* __restrict__ Vh) {
    extern __shared__ char smem[];
    const uint32_t sbase = smem_to_u32(smem);
    const int tid = threadIdx.x;
    const int z = blockIdx.z;
    const int bm = blockIdx.y * 128;
    const int bn = blockIdx.x * 128;

    const __half* Ah = (z == 0) ? xah : xbh;
    const __half* Bh = Wt + (size_t)z * DD * DD;
    __half* dst = (z == 0) ? Qh : (z == 1) ? Kh : Vh;

    float acc[2][8][4];
    #pragma unroll
    for (int i = 0; i < 2; i++)
        #pragma unroll
        for (int j = 0; j < 8; j++)
            #pragma unroll
            for (int q = 0; q < 4; q++) acc[i][j][q] = 0.f;

    gemm_mainloop(Ah, Bh, bm, bn, DD, sbase, tid, acc);

    const int lane = tid & 31, wid = tid >> 5;
    const int wm = wid >> 1, wn = wid & 1;
    const int er = lane >> 2, ec = (lane & 3) * 2;
    #pragma unroll
    for (int mt = 0; mt < 2; mt++) {
        const int row0 = bm + wm * 32 + mt * 16 + er;
        #pragma unroll
        for (int nt = 0; nt < 8; nt++) {
            const int col = bn + wn * 64 + nt * 8 + ec;
            #pragma unroll
            for (int half_ = 0; half_ < 2; half_++) {
                const size_t o = (size_t)(row0 + half_ * 8) * DD + col;
                *(__half2*)&dst[o] =
                    __half2(__float2half(acc[mt][nt][2 * half_]),
                            __float2half(acc[mt][nt][2 * half_ + 1]));
            }
        }
    }
}

// Wo GEMM: 1-product, fp32 out.
__global__ __launch_bounds__(256, 2)
void wo_mma_kernel(const __half* __restrict__ Ah,
                   const __half* __restrict__ Bh, float* __restrict__ C) {
    extern __shared__ char smem[];
    const uint32_t sbase = smem_to_u32(smem);
    const int tid = threadIdx.x;
    const int bm = blockIdx.y * 128;
    const int bn = blockIdx.x * 128;

    float acc[2][8][4];
    #pragma unroll
    for (int i = 0; i < 2; i++)
        #pragma unroll
        for (int j = 0; j < 8; j++)
            #pragma unroll
            for (int q = 0; q < 4; q++) acc[i][j][q] = 0.f;

    gemm_mainloop(Ah, Bh, bm, bn, DD, sbase, tid, acc);

    const int lane = tid & 31, wid = tid >> 5;
    const int wm = wid >> 1, wn = wid & 1;
    const int er = lane >> 2, ec = (lane & 3) * 2;
    #pragma unroll
    for (int mt = 0; mt < 2; mt++) {
        const int row0 = bm + wm * 32 + mt * 16 + er;
        #pragma unroll
        for (int nt = 0; nt < 8; nt++) {
            const int col = bn + wn * 64 + nt * 8 + ec;
            *(float2*)&C[(size_t)row0 * DD + col] =
                make_float2(acc[mt][nt][0], acc[mt][nt][1]);
            *(float2*)&C[(size_t)(row0 + 8) * DD + col] =
                make_float2(acc[mt][nt][2], acc[mt][nt][3]);
        }
    }
}

// ---------------------------------------------------------------------------
// Flash attention fp16 mma (causal). BQ=128, BKV=64, HD=64.
// S = Qh·Kh^T (uncompensated); PV = (Ph+Pl)·Vh. Base-2 softmax (ex2.approx).
// 3-stage KV pipeline, one sync/tile, 2 CTAs/SM. Output: hi only.
// ---------------------------------------------------------------------------
#define FSROW  144                          // 64 fp16 = 128B + 16B pad
#define FTILE  (64 * FSROW)                 // 9216
#define FSTAGE (2 * FTILE)                  // 18432 (Kh, Vh)
#define FLASH_SMEM (3 * FSTAGE)             // 55296 (Q staging 18432 fits)

__global__ __launch_bounds__(256, 2)
void flash_mma_kernel(const __half* __restrict__ Qh_,
                      const __half* __restrict__ Kh_, const __half* __restrict__ Vh_,
                      __half* __restrict__ Oh_) {
    extern __shared__ char smem[];
    const uint32_t sbase = smem_to_u32(smem);
    const int qb = (int)gridDim.x - 1 - (int)blockIdx.x;   // heavy first
    const int bh = blockIdx.y;
    const int b = bh >> 4, h = bh & 15;
    const int tid = threadIdx.x, lane = tid & 31, wid = tid >> 5;
    const int wrow = qb * 128 + wid * 16;

    // ---- Stage Qh (128 rows x 128B), extract fragments
    {
        const size_t gq = ((size_t)(b * TT + qb * 128)) * DD + h * HD;
        #pragma unroll
        for (int t = 0; t < 4; t++) {
            const int row = t * 32 + (tid >> 3);
            cp_async16(sbase + row * FSROW + (tid & 7) * 16,
                       Qh_ + gq + (size_t)row * DD + (tid & 7) * 8);
        }
        cp_commit(); cp_wait<0>();
        __syncthreads();
    }
    uint32_t qh[4][4];
    {
        const int a_row = wid * 16 + (lane & 15);
        const int a_col = (lane >> 4) * 8;
        #pragma unroll
        for (int ks = 0; ks < 4; ks++) {
            ldsm_x4(sbase + a_row * FSROW + (a_col + ks * 16) * 2,
                    qh[ks][0], qh[ks][1], qh[ks][2], qh[ks][3]);
        }
    }
    __syncthreads();   // all warps done reading Q staging before KV loads reuse smem

    // ---- KV loader (Kh + Vh, 3-stage)
    const size_t gkv = ((size_t)(b * TT)) * DD + h * HD;
    auto load_kv = [&](int kt) {
        const uint32_t st = sbase + (kt % 3) * FSTAGE;
        const size_t base = gkv + (size_t)(kt * 64) * DD;
        #pragma unroll
        for (int t = 0; t < 4; t++) {
            const int mat = t >> 1;
            const int row = (t & 1) * 32 + (tid >> 3);
            const __half* src = mat ? Vh_ : Kh_;
            cp_async16(st + mat * FTILE + row * FSROW + (tid & 7) * 16,
                       src + base + (size_t)row * DD + (tid & 7) * 8);
        }
        cp_commit();
    };

    float acc[8][4];
    #pragma unroll
    for (int i = 0; i < 8; i++)
        #pragma unroll
        for (int j = 0; j < 4; j++) acc[i][j] = 0.f;
    float m0 = -CUDART_INF_F, m1 = -CUDART_INF_F, l0 = 0.f, l1 = 0.f;

    const int ntiles = 2 * qb + 2;
    const int diag_kt = wrow >> 6;
    const int b_row = ((lane >> 4) & 1) * 8 + (lane & 7);
    const int b_col = ((lane >> 3) & 1) * 8;
    const float SCALE2 = 0.125f * 1.4426950408889634f;

    load_kv(0);
    if (ntiles > 1) load_kv(1);

    for (int kt = 0; kt < ntiles; kt++) {
        if (kt + 1 < ntiles) cp_wait<1>();
        else cp_wait<0>();
        __syncthreads();
        if (kt + 2 < ntiles) load_kv(kt + 2);

        const uint32_t st = sbase + (kt % 3) * FSTAGE;
        if (kt * 64 <= wrow) {
            // ---- S = Qh @ Kh^T (1-product)
            float s[8][4];
            #pragma unroll
            for (int i = 0; i < 8; i++)
                #pragma unroll
                for (int j = 0; j < 4; j++) s[i][j] = 0.f;

            #pragma unroll
            for (int ks = 0; ks < 4; ks++) {
                #pragma unroll
                for (int p = 0; p < 4; p++) {
                    uint32_t kh[4];
                    ldsm_x4(st + (b_row + p * 16) * FSROW + (b_col + ks * 16) * 2,
                            kh[0], kh[1], kh[2], kh[3]);
                    mma16816(s[2 * p + 0], qh[ks], kh[0], kh[1]);
                    mma16816(s[2 * p + 1], qh[ks], kh[2], kh[3]);
                }
            }

            // ---- scale (log2 domain) + causal mask
            #pragma unroll
            for (int nt = 0; nt < 8; nt++)
                #pragma unroll
                for (int e = 0; e < 4; e++) s[nt][e] *= SCALE2;
            if (kt == diag_kt) {
                const int r0g = wrow + (lane >> 2);
                const int r1g = r0g + 8;
                #pragma unroll
                for (int nt = 0; nt < 8; nt++) {
                    #pragma unroll
                    for (int c = 0; c < 2; c++) {
                        const int col = kt * 64 + nt * 8 + (lane & 3) * 2 + c;
                        if (col > r0g) s[nt][c] = -1e30f;
                        if (col > r1g) s[nt][2 + c] = -1e30f;
                    }
                }
            }

            // ---- online softmax (base 2, in-warp quad reduction)
            float mx0 = -1e30f, mx1 = -1e30f;
            #pragma unroll
            for (int nt = 0; nt < 8; nt++) {
                mx0 = fmaxf(mx0, fmaxf(s[nt][0], s[nt][1]));
                mx1 = fmaxf(mx1, fmaxf(s[nt][2], s[nt][3]));
            }
            mx0 = fmaxf(mx0, __shfl_xor_sync(0xffffffffu, mx0, 1));
            mx0 = fmaxf(mx0, __shfl_xor_sync(0xffffffffu, mx0, 2));
            mx1 = fmaxf(mx1, __shfl_xor_sync(0xffffffffu, mx1, 1));
            mx1 = fmaxf(mx1, __shfl_xor_sync(0xffffffffu, mx1, 2));
            const float m0n = fmaxf(m0, mx0), m1n = fmaxf(m1, mx1);
            const float f0 = ex2(m0 - m0n), f1 = ex2(m1 - m1n);
            m0 = m0n; m1 = m1n;

            float sum0 = 0.f, sum1 = 0.f;
            #pragma unroll
            for (int nt = 0; nt < 8; nt++) {
                s[nt][0] = ex2(s[nt][0] - m0n); sum0 += s[nt][0];
                s[nt][1] = ex2(s[nt][1] - m0n); sum0 += s[nt][1];
                s[nt][2] = ex2(s[nt][2] - m1n); sum1 += s[nt][2];
                s[nt][3] = ex2(s[nt][3] - m1n); sum1 += s[nt][3];
            }
            sum0 += __shfl_xor_sync(0xffffffffu, sum0, 1);
            sum0 += __shfl_xor_sync(0xffffffffu, sum0, 2);
            sum1 += __shfl_xor_sync(0xffffffffu, sum1, 1);
            sum1 += __shfl_xor_sync(0xffffffffu, sum1, 2);
            l0 = f0 * l0 + sum0;
            l1 = f1 * l1 + sum1;

            #pragma unroll
            for (int nt = 0; nt < 8; nt++) {
                acc[nt][0] *= f0; acc[nt][1] *= f0;
                acc[nt][2] *= f1; acc[nt][3] *= f1;
            }

            // ---- P fragments: fp16 hi + residual lo (C->A frag remap)
            uint32_t aph[4][4], apl[4][4];
            #pragma unroll
            for (int kf = 0; kf < 4; kf++) {
                #pragma unroll
                for (int q = 0; q < 4; q++) {
                    const int t = 2 * kf + (q >> 1);
                    const int c = (q & 1) * 2;
                    const float x = s[t][c], y = s[t][c + 1];
                    const __half hx = __float2half(x), hy = __float2half(y);
                    __half2 hp(hx, hy);
                    aph[kf][q] = *(uint32_t*)&hp;
                    apl[kf][q] = pack_half2(x - __half2float(hx),
                                            y - __half2float(hy));
                }
            }

            // ---- O += (Ph+Pl) @ Vh (trans ldmatrix)
            #pragma unroll
            for (int kf = 0; kf < 4; kf++) {
                const int v_row = kf * 16 + ((lane >> 3) & 1) * 8 + (lane & 7);
                const int v_colb = ((lane >> 4) & 1) * 8;
                #pragma unroll
                for (int p = 0; p < 4; p++) {
                    uint32_t vh[4];
                    ldsm_x4_t(st + FTILE + v_row * FSROW + (p * 16 + v_colb) * 2,
                              vh[0], vh[1], vh[2], vh[3]);
                    mma16816(acc[2 * p + 0], aph[kf], vh[0], vh[1]);
                    mma16816(acc[2 * p + 1], aph[kf], vh[2], vh[3]);
                    mma16816(acc[2 * p + 0], apl[kf], vh[0], vh[1]);
                    mma16816(acc[2 * p + 1], apl[kf], vh[2], vh[3]);
                }
            }
        }
    }

    // ---- epilogue: normalize, fp16 hi only (Wo GEMM is 1-product)
    const float inv0 = 1.f / l0, inv1 = 1.f / l1;
    const size_t orow0 = ((size_t)(b * TT + wrow + (lane >> 2))) * DD + h * HD;
    const size_t orow1 = orow0 + (size_t)8 * DD;
    #pragma unroll
    for (int nt = 0; nt < 8; nt++) {
        const int col = nt * 8 + (lane & 3) * 2;
        *(__half2*)&Oh_[orow0 + col] =
            __half2(__float2half(acc[nt][0] * inv0), __float2half(acc[nt][1] * inv0));
        *(__half2*)&Oh_[orow1 + col] =
            __half2(__float2half(acc[nt][2] * inv1), __float2half(acc[nt][3] * inv1));
    }
}

// ---------------------------------------------------------------------------
// Launch
// ---------------------------------------------------------------------------
extern "C" void kernel_launch(void* const* d_in, const int* in_sizes, int n_in,
                              void* d_out, int out_size) {
    const float* xq  = (const float*)d_in[0];
    const float* xkv = (const float*)d_in[1];
    const float* Wq = (const float*)d_in[3];
    const float* Wk = (const float*)d_in[4];
    const float* Wv = (const float*)d_in[5];
    const float* Wo = (const float*)d_in[6];
    float* out = (float*)d_out;

    __half *qh, *kh, *vh, *xah, *xbh, *wt;
    cudaGetSymbolAddress((void**)&qh, g_qh);
    cudaGetSymbolAddress((void**)&kh, g_kh);
    cudaGetSymbolAddress((void**)&vh, g_vh);
    cudaGetSymbolAddress((void**)&xah, g_xa_h);
    cudaGetSymbolAddress((void**)&xbh, g_xb_h);
    cudaGetSymbolAddress((void**)&wt, g_wt);

    cudaFuncSetAttribute(qkv_mma_kernel, cudaFuncAttributeMaxDynamicSharedMemorySize,
                         GEMM_SMEM);
    cudaFuncSetAttribute(wo_mma_kernel, cudaFuncAttributeMaxDynamicSharedMemorySize,
                         GEMM_SMEM);
    cudaFuncSetAttribute(flash_mma_kernel, cudaFuncAttributeMaxDynamicSharedMemorySize,
                         FLASH_SMEM);

    const int n4 = MROWS * DD / 4;
    aconv_h_kernel<<<(n4 + 255) / 256, 256>>>(xq,  xah, n4);
    aconv_h_kernel<<<(n4 + 255) / 256, 256>>>(xkv, xbh, n4);
    wconv_kernel<<<dim3(32, 32, 4), dim3(32, 8)>>>(Wq, Wk, Wv, Wo, wt);

    qkv_mma_kernel<<<dim3(DD / 128, MROWS / 128, 3), 256, GEMM_SMEM>>>(
        xah, xbh, wt, qh, kh, vh);

    // flash writes attn output hi into xah (Q-GEMM already consumed it)
    flash_mma_kernel<<<dim3(TT / 128, BB * HH), 256, FLASH_SMEM>>>(
        qh, kh, vh, xah);

    wo_mma_kernel<<<dim3(DD / 128, MROWS / 128), 256, GEMM_SMEM>>>(
        xah, wt + (size_t)3 * DD * DD, out);
}

// round 17
// speedup vs baseline: 7.7338x; 1.1186x over previous
#include <cuda_runtime.h>
#include <cuda_fp16.h>
#include <math_constants.h>
#include <cstdint>

// Problem constants
#define BB   2
#define TT   2048
#define DD   1024
#define HH   16
#define HD   64
#define MROWS (BB*TT)        // 4096

// ---------------------------------------------------------------------------
// Scratch (device globals; allocation forbidden)
// ---------------------------------------------------------------------------
__device__ __half g_qh[MROWS * DD];            // hi only
__device__ __half g_kh[MROWS * DD];            // hi only
__device__ __half g_vh[MROWS * DD];            // hi only

__device__ __half g_xa_h[MROWS * DD];          // xq hi (reused: attn out hi)
__device__ __half g_xb_h[MROWS * DD];          // xkv hi
__device__ __half g_wt[4 * DD * DD];           // transposed weights hi [n][k]

// ---------------------------------------------------------------------------
// PTX helpers
// ---------------------------------------------------------------------------
__device__ __forceinline__ uint32_t smem_to_u32(const void* p) {
    uint32_t a;
    asm("{ .reg .u64 t; cvta.to.shared.u64 t, %1; cvt.u32.u64 %0, t; }"
        : "=r"(a) : "l"(p));
    return a;
}
__device__ __forceinline__ void cp_async16(uint32_t sa, const void* g) {
    asm volatile("cp.async.cg.shared.global [%0], [%1], 16;" :: "r"(sa), "l"(g));
}
__device__ __forceinline__ void cp_commit() {
    asm volatile("cp.async.commit_group;");
}
template <int N>
__device__ __forceinline__ void cp_wait() {
    asm volatile("cp.async.wait_group %0;" :: "n"(N));
}
__device__ __forceinline__ void ldsm_x4(uint32_t addr, uint32_t& r0, uint32_t& r1,
                                        uint32_t& r2, uint32_t& r3) {
    asm volatile("ldmatrix.sync.aligned.m8n8.x4.shared.b16 {%0,%1,%2,%3}, [%4];"
                 : "=r"(r0), "=r"(r1), "=r"(r2), "=r"(r3) : "r"(addr));
}
__device__ __forceinline__ void ldsm_x4_t(uint32_t addr, uint32_t& r0, uint32_t& r1,
                                          uint32_t& r2, uint32_t& r3) {
    asm volatile("ldmatrix.sync.aligned.m8n8.x4.trans.shared.b16 {%0,%1,%2,%3}, [%4];"
                 : "=r"(r0), "=r"(r1), "=r"(r2), "=r"(r3) : "r"(addr));
}
__device__ __forceinline__ void mma16816(float* c, const uint32_t* a,
                                         uint32_t b0, uint32_t b1) {
    asm volatile(
        "mma.sync.aligned.m16n8k16.row.col.f32.f16.f16.f32 "
        "{%0,%1,%2,%3}, {%4,%5,%6,%7}, {%8,%9}, {%0,%1,%2,%3};"
        : "+f"(c[0]), "+f"(c[1]), "+f"(c[2]), "+f"(c[3])
        : "r"(a[0]), "r"(a[1]), "r"(a[2]), "r"(a[3]), "r"(b0), "r"(b1));
}
__device__ __forceinline__ float ex2(float x) {
    float r;
    asm("ex2.approx.ftz.f32 %0, %1;" : "=f"(r) : "f"(x));
    return r;
}

// ---------------------------------------------------------------------------
// Activation fp32 -> fp16 (hi only)
// ---------------------------------------------------------------------------
__global__ __launch_bounds__(256)
void aconv_h_kernel(const float* __restrict__ X, __half* __restrict__ Xh, int n4) {
    int i = blockIdx.x * blockDim.x + threadIdx.x;
    if (i >= n4) return;
    float4 v = ((const float4*)X)[i];
    ((__half2*)Xh)[i * 2 + 0] = __half2(__float2half(v.x), __float2half(v.y));
    ((__half2*)Xh)[i * 2 + 1] = __half2(__float2half(v.z), __float2half(v.w));
}

// ---------------------------------------------------------------------------
// Weight transpose + fp16 round: W[k][n] fp32 -> Wt[n][k] fp16 hi only.
// ---------------------------------------------------------------------------
__global__ __launch_bounds__(256)
void wconv_kernel(const float* __restrict__ W0, const float* __restrict__ W1,
                  const float* __restrict__ W2, const float* __restrict__ W3,
                  __half* __restrict__ T) {
    __shared__ float t[32][33];
    const int z = blockIdx.z;
    const float* W = (z == 0) ? W0 : (z == 1) ? W1 : (z == 2) ? W2 : W3;
    __half* Th = T + (size_t)z * DD * DD;
    const int tx = threadIdx.x, ty = threadIdx.y;
    const int k0 = blockIdx.y * 32, n0 = blockIdx.x * 32;
    #pragma unroll
    for (int i = 0; i < 4; i++)
        t[ty + 8 * i][tx] = W[(size_t)(k0 + ty + 8 * i) * DD + n0 + tx];
    __syncthreads();
    #pragma unroll
    for (int i = 0; i < 4; i++) {
        Th[(size_t)(n0 + ty + 8 * i) * DD + k0 + tx] =
            __float2half(t[tx][ty + 8 * i]);
    }
}

// ---------------------------------------------------------------------------
// fp16 1-product GEMM mainloop. C = Ah[M,K] @ Bh; Bh pre-transposed [N,K].
// CTA tile 128x128, 8 warps, K-chunk 64. 3-stage cp.async, one sync/chunk,
// wait<1> keeps one chunk in flight. 2 CTAs/SM.
// ---------------------------------------------------------------------------
#define KC        64
#define SROW      144                      // 64 fp16 = 128B + 16B pad
#define MAT_B     (128 * SROW)             // 18432
#define G_STAGE   (2 * MAT_B)              // 36864 (A, B)
#define GEMM_SMEM (3 * G_STAGE)            // 110592

__device__ __forceinline__ void gemm_mainloop(
    const __half* __restrict__ Ah, const __half* __restrict__ Bh,
    int bm, int bn, int K, uint32_t sbase, int tid, float acc[2][8][4]) {
    const int lane = tid & 31;
    const int wid = tid >> 5;
    const int wm = wid >> 1;
    const int wn = wid & 1;
    const int nchunks = K / KC;            // 16

    const int lrow = tid >> 3;             // 0..31 (+32*g)
    const int lseg = tid & 7;              // 16B segment in 128B row

    auto load_chunk = [&](int c) {
        const int k0 = c * KC;
        const uint32_t st = sbase + (c % 3) * G_STAGE;
        #pragma unroll
        for (int t = 0; t < 8; t++) {
            const int mat = t >> 2;                  // 0=A, 1=B
            const int row = (t & 3) * 32 + lrow;
            const __half* src = mat ? Bh : Ah;
            const int grow = (mat ? bn : bm) + row;
            cp_async16(st + mat * MAT_B + row * SROW + lseg * 16,
                       src + (size_t)grow * K + k0 + lseg * 8);
        }
        cp_commit();
    };

    const int a_row = wm * 32 + (lane & 15);
    const int a_col = (lane >> 4) * 8;
    const int b_row = wn * 64 + ((lane >> 4) & 1) * 8 + (lane & 7);
    const int b_col = ((lane >> 3) & 1) * 8;

    load_chunk(0);
    load_chunk(1);

    for (int c = 0; c < nchunks; c++) {
        if (c + 1 < nchunks) cp_wait<1>();
        else cp_wait<0>();
        __syncthreads();
        // Stage (c+2)%3 was consumed at iteration c-1; barrier above makes
        // reuse safe for all warps.
        if (c + 2 < nchunks) load_chunk(c + 2);

        const uint32_t st = sbase + (c % 3) * G_STAGE;
        #pragma unroll
        for (int kstep = 0; kstep < 4; kstep++) {
            uint32_t ah[2][4];
            #pragma unroll
            for (int mt = 0; mt < 2; mt++) {
                ldsm_x4(st + (a_row + mt * 16) * SROW + (a_col + kstep * 16) * 2,
                        ah[mt][0], ah[mt][1], ah[mt][2], ah[mt][3]);
            }
            #pragma unroll
            for (int p = 0; p < 4; p++) {
                uint32_t bh[4];
                ldsm_x4(st + MAT_B + (b_row + p * 16) * SROW + (b_col + kstep * 16) * 2,
                        bh[0], bh[1], bh[2], bh[3]);
                #pragma unroll
                for (int mt = 0; mt < 2; mt++) {
                    mma16816(acc[mt][2 * p + 0], ah[mt], bh[0], bh[1]);
                    mma16816(acc[mt][2 * p + 1], ah[mt], bh[2], bh[3]);
                }
            }
        }
    }
}

// Fused QKV GEMM: grid (8, 32, 3). z selects Q/K/V; all 1-product, hi-only out.
__global__ __launch_bounds__(256, 2)
void qkv_mma_kernel(const __half* __restrict__ xah, const __half* __restrict__ xbh,
                    const __half* __restrict__ Wt,
                    __half* __restrict__ Qh, __half* __restrict__ Kh,
                    __half* __restrict__ Vh) {
    extern __shared__ char smem[];
    const uint32_t sbase = smem_to_u32(smem);
    const int tid = threadIdx.x;
    const int z = blockIdx.z;
    const int bm = blockIdx.y * 128;
    const int bn = blockIdx.x * 128;

    const __half* Ah = (z == 0) ? xah : xbh;
    const __half* Bh = Wt + (size_t)z * DD * DD;
    __half* dst = (z == 0) ? Qh : (z == 1) ? Kh : Vh;

    float acc[2][8][4];
    #pragma unroll
    for (int i = 0; i < 2; i++)
        #pragma unroll
        for (int j = 0; j < 8; j++)
            #pragma unroll
            for (int q = 0; q < 4; q++) acc[i][j][q] = 0.f;

    gemm_mainloop(Ah, Bh, bm, bn, DD, sbase, tid, acc);

    const int lane = tid & 31, wid = tid >> 5;
    const int wm = wid >> 1, wn = wid & 1;
    const int er = lane >> 2, ec = (lane & 3) * 2;
    #pragma unroll
    for (int mt = 0; mt < 2; mt++) {
        const int row0 = bm + wm * 32 + mt * 16 + er;
        #pragma unroll
        for (int nt = 0; nt < 8; nt++) {
            const int col = bn + wn * 64 + nt * 8 + ec;
            #pragma unroll
            for (int half_ = 0; half_ < 2; half_++) {
                const size_t o = (size_t)(row0 + half_ * 8) * DD + col;
                *(__half2*)&dst[o] =
                    __half2(__float2half(acc[mt][nt][2 * half_]),
                            __float2half(acc[mt][nt][2 * half_ + 1]));
            }
        }
    }
}

// Wo GEMM: 1-product, fp32 out.
__global__ __launch_bounds__(256, 2)
void wo_mma_kernel(const __half* __restrict__ Ah,
                   const __half* __restrict__ Bh, float* __restrict__ C) {
    extern __shared__ char smem[];
    const uint32_t sbase = smem_to_u32(smem);
    const int tid = threadIdx.x;
    const int bm = blockIdx.y * 128;
    const int bn = blockIdx.x * 128;

    float acc[2][8][4];
    #pragma unroll
    for (int i = 0; i < 2; i++)
        #pragma unroll
        for (int j = 0; j < 8; j++)
            #pragma unroll
            for (int q = 0; q < 4; q++) acc[i][j][q] = 0.f;

    gemm_mainloop(Ah, Bh, bm, bn, DD, sbase, tid, acc);

    const int lane = tid & 31, wid = tid >> 5;
    const int wm = wid >> 1, wn = wid & 1;
    const int er = lane >> 2, ec = (lane & 3) * 2;
    #pragma unroll
    for (int mt = 0; mt < 2; mt++) {
        const int row0 = bm + wm * 32 + mt * 16 + er;
        #pragma unroll
        for (int nt = 0; nt < 8; nt++) {
            const int col = bn + wn * 64 + nt * 8 + ec;
            *(float2*)&C[(size_t)row0 * DD + col] =
                make_float2(acc[mt][nt][0], acc[mt][nt][1]);
            *(float2*)&C[(size_t)(row0 + 8) * DD + col] =
                make_float2(acc[mt][nt][2], acc[mt][nt][3]);
        }
    }
}

// ---------------------------------------------------------------------------
// Flash attention fp16 mma (causal). BQ=128, BKV=64, HD=64.
// S = Qh·Kh^T; PV = Ph·Vh (both 1-product). Base-2 softmax (ex2.approx).
// 3-stage KV pipeline, one sync/tile, 2 CTAs/SM. Output: hi only.
// ---------------------------------------------------------------------------
#define FSROW  144                          // 64 fp16 = 128B + 16B pad
#define FTILE  (64 * FSROW)                 // 9216
#define FSTAGE (2 * FTILE)                  // 18432 (Kh, Vh)
#define FLASH_SMEM (3 * FSTAGE)             // 55296 (Q staging 18432 fits)

__global__ __launch_bounds__(256, 2)
void flash_mma_kernel(const __half* __restrict__ Qh_,
                      const __half* __restrict__ Kh_, const __half* __restrict__ Vh_,
                      __half* __restrict__ Oh_) {
    extern __shared__ char smem[];
    const uint32_t sbase = smem_to_u32(smem);
    const int qb = (int)gridDim.x - 1 - (int)blockIdx.x;   // heavy first
    const int bh = blockIdx.y;
    const int b = bh >> 4, h = bh & 15;
    const int tid = threadIdx.x, lane = tid & 31, wid = tid >> 5;
    const int wrow = qb * 128 + wid * 16;

    // ---- Stage Qh (128 rows x 128B), extract fragments
    {
        const size_t gq = ((size_t)(b * TT + qb * 128)) * DD + h * HD;
        #pragma unroll
        for (int t = 0; t < 4; t++) {
            const int row = t * 32 + (tid >> 3);
            cp_async16(sbase + row * FSROW + (tid & 7) * 16,
                       Qh_ + gq + (size_t)row * DD + (tid & 7) * 8);
        }
        cp_commit(); cp_wait<0>();
        __syncthreads();
    }
    uint32_t qh[4][4];
    {
        const int a_row = wid * 16 + (lane & 15);
        const int a_col = (lane >> 4) * 8;
        #pragma unroll
        for (int ks = 0; ks < 4; ks++) {
            ldsm_x4(sbase + a_row * FSROW + (a_col + ks * 16) * 2,
                    qh[ks][0], qh[ks][1], qh[ks][2], qh[ks][3]);
        }
    }
    __syncthreads();   // all warps done reading Q staging before KV loads reuse smem

    // ---- KV loader (Kh + Vh, 3-stage)
    const size_t gkv = ((size_t)(b * TT)) * DD + h * HD;
    auto load_kv = [&](int kt) {
        const uint32_t st = sbase + (kt % 3) * FSTAGE;
        const size_t base = gkv + (size_t)(kt * 64) * DD;
        #pragma unroll
        for (int t = 0; t < 4; t++) {
            const int mat = t >> 1;
            const int row = (t & 1) * 32 + (tid >> 3);
            const __half* src = mat ? Vh_ : Kh_;
            cp_async16(st + mat * FTILE + row * FSROW + (tid & 7) * 16,
                       src + base + (size_t)row * DD + (tid & 7) * 8);
        }
        cp_commit();
    };

    float acc[8][4];
    #pragma unroll
    for (int i = 0; i < 8; i++)
        #pragma unroll
        for (int j = 0; j < 4; j++) acc[i][j] = 0.f;
    float m0 = -CUDART_INF_F, m1 = -CUDART_INF_F, l0 = 0.f, l1 = 0.f;

    const int ntiles = 2 * qb + 2;
    const int diag_kt = wrow >> 6;
    const int b_row = ((lane >> 4) & 1) * 8 + (lane & 7);
    const int b_col = ((lane >> 3) & 1) * 8;
    const float SCALE2 = 0.125f * 1.4426950408889634f;

    load_kv(0);
    if (ntiles > 1) load_kv(1);

    for (int kt = 0; kt < ntiles; kt++) {
        if (kt + 1 < ntiles) cp_wait<1>();
        else cp_wait<0>();
        __syncthreads();
        if (kt + 2 < ntiles) load_kv(kt + 2);

        const uint32_t st = sbase + (kt % 3) * FSTAGE;
        if (kt * 64 <= wrow) {
            // ---- S = Qh @ Kh^T (1-product)
            float s[8][4];
            #pragma unroll
            for (int i = 0; i < 8; i++)
                #pragma unroll
                for (int j = 0; j < 4; j++) s[i][j] = 0.f;

            #pragma unroll
            for (int ks = 0; ks < 4; ks++) {
                #pragma unroll
                for (int p = 0; p < 4; p++) {
                    uint32_t kh[4];
                    ldsm_x4(st + (b_row + p * 16) * FSROW + (b_col + ks * 16) * 2,
                            kh[0], kh[1], kh[2], kh[3]);
                    mma16816(s[2 * p + 0], qh[ks], kh[0], kh[1]);
                    mma16816(s[2 * p + 1], qh[ks], kh[2], kh[3]);
                }
            }

            // ---- scale (log2 domain) + causal mask
            #pragma unroll
            for (int nt = 0; nt < 8; nt++)
                #pragma unroll
                for (int e = 0; e < 4; e++) s[nt][e] *= SCALE2;
            if (kt == diag_kt) {
                const int r0g = wrow + (lane >> 2);
                const int r1g = r0g + 8;
                #pragma unroll
                for (int nt = 0; nt < 8; nt++) {
                    #pragma unroll
                    for (int c = 0; c < 2; c++) {
                        const int col = kt * 64 + nt * 8 + (lane & 3) * 2 + c;
                        if (col > r0g) s[nt][c] = -1e30f;
                        if (col > r1g) s[nt][2 + c] = -1e30f;
                    }
                }
            }

            // ---- online softmax (base 2, in-warp quad reduction)
            float mx0 = -1e30f, mx1 = -1e30f;
            #pragma unroll
            for (int nt = 0; nt < 8; nt++) {
                mx0 = fmaxf(mx0, fmaxf(s[nt][0], s[nt][1]));
                mx1 = fmaxf(mx1, fmaxf(s[nt][2], s[nt][3]));
            }
            mx0 = fmaxf(mx0, __shfl_xor_sync(0xffffffffu, mx0, 1));
            mx0 = fmaxf(mx0, __shfl_xor_sync(0xffffffffu, mx0, 2));
            mx1 = fmaxf(mx1, __shfl_xor_sync(0xffffffffu, mx1, 1));
            mx1 = fmaxf(mx1, __shfl_xor_sync(0xffffffffu, mx1, 2));
            const float m0n = fmaxf(m0, mx0), m1n = fmaxf(m1, mx1);
            const float f0 = ex2(m0 - m0n), f1 = ex2(m1 - m1n);
            m0 = m0n; m1 = m1n;

            float sum0 = 0.f, sum1 = 0.f;
            #pragma unroll
            for (int nt = 0; nt < 8; nt++) {
                s[nt][0] = ex2(s[nt][0] - m0n); sum0 += s[nt][0];
                s[nt][1] = ex2(s[nt][1] - m0n); sum0 += s[nt][1];
                s[nt][2] = ex2(s[nt][2] - m1n); sum1 += s[nt][2];
                s[nt][3] = ex2(s[nt][3] - m1n); sum1 += s[nt][3];
            }
            sum0 += __shfl_xor_sync(0xffffffffu, sum0, 1);
            sum0 += __shfl_xor_sync(0xffffffffu, sum0, 2);
            sum1 += __shfl_xor_sync(0xffffffffu, sum1, 1);
            sum1 += __shfl_xor_sync(0xffffffffu, sum1, 2);
            l0 = f0 * l0 + sum0;
            l1 = f1 * l1 + sum1;

            #pragma unroll
            for (int nt = 0; nt < 8; nt++) {
                acc[nt][0] *= f0; acc[nt][1] *= f0;
                acc[nt][2] *= f1; acc[nt][3] *= f1;
            }

            // ---- P fragments: fp16 (C->A frag remap), 1-product PV
            uint32_t aph[4][4];
            #pragma unroll
            for (int kf = 0; kf < 4; kf++) {
                #pragma unroll
                for (int q = 0; q < 4; q++) {
                    const int t = 2 * kf + (q >> 1);
                    const int c = (q & 1) * 2;
                    __half2 hp(__float2half(s[t][c]), __float2half(s[t][c + 1]));
                    aph[kf][q] = *(uint32_t*)&hp;
                }
            }

            // ---- O += Ph @ Vh (trans ldmatrix)
            #pragma unroll
            for (int kf = 0; kf < 4; kf++) {
                const int v_row = kf * 16 + ((lane >> 3) & 1) * 8 + (lane & 7);
                const int v_colb = ((lane >> 4) & 1) * 8;
                #pragma unroll
                for (int p = 0; p < 4; p++) {
                    uint32_t vh[4];
                    ldsm_x4_t(st + FTILE + v_row * FSROW + (p * 16 + v_colb) * 2,
                              vh[0], vh[1], vh[2], vh[3]);
                    mma16816(acc[2 * p + 0], aph[kf], vh[0], vh[1]);
                    mma16816(acc[2 * p + 1], aph[kf], vh[2], vh[3]);
                }
            }
        }
    }

    // ---- epilogue: normalize, fp16 hi only (Wo GEMM is 1-product)
    const float inv0 = 1.f / l0, inv1 = 1.f / l1;
    const size_t orow0 = ((size_t)(b * TT + wrow + (lane >> 2))) * DD + h * HD;
    const size_t orow1 = orow0 + (size_t)8 * DD;
    #pragma unroll
    for (int nt = 0; nt < 8; nt++) {
        const int col = nt * 8 + (lane & 3) * 2;
        *(__half2*)&Oh_[orow0 + col] =
            __half2(__float2half(acc[nt][0] * inv0), __float2half(acc[nt][1] * inv0));
        *(__half2*)&Oh_[orow1 + col] =
            __half2(__float2half(acc[nt][2] * inv1), __float2half(acc[nt][3] * inv1));
    }
}

// ---------------------------------------------------------------------------
// Launch
// ---------------------------------------------------------------------------
extern "C" void kernel_launch(void* const* d_in, const int* in_sizes, int n_in,
                              void* d_out, int out_size) {
    const float* xq  = (const float*)d_in[0];
    const float* xkv = (const float*)d_in[1];
    const float* Wq = (const float*)d_in[3];
    const float* Wk = (const float*)d_in[4];
    const float* Wv = (const float*)d_in[5];
    const float* Wo = (const float*)d_in[6];
    float* out = (float*)d_out;

    __half *qh, *kh, *vh, *xah, *xbh, *wt;
    cudaGetSymbolAddress((void**)&qh, g_qh);
    cudaGetSymbolAddress((void**)&kh, g_kh);
    cudaGetSymbolAddress((void**)&vh, g_vh);
    cudaGetSymbolAddress((void**)&xah, g_xa_h);
    cudaGetSymbolAddress((void**)&xbh, g_xb_h);
    cudaGetSymbolAddress((void**)&wt, g_wt);

    cudaFuncSetAttribute(qkv_mma_kernel, cudaFuncAttributeMaxDynamicSharedMemorySize,
                         GEMM_SMEM);
    cudaFuncSetAttribute(wo_mma_kernel, cudaFuncAttributeMaxDynamicSharedMemorySize,
                         GEMM_SMEM);
    cudaFuncSetAttribute(flash_mma_kernel, cudaFuncAttributeMaxDynamicSharedMemorySize,
                         FLASH_SMEM);

    const int n4 = MROWS * DD / 4;
    aconv_h_kernel<<<(n4 + 255) / 256, 256>>>(xq,  xah, n4);
    aconv_h_kernel<<<(n4 + 255) / 256, 256>>>(xkv, xbh, n4);
    wconv_kernel<<<dim3(32, 32, 4), dim3(32, 8)>>>(Wq, Wk, Wv, Wo, wt);

    qkv_mma_kernel<<<dim3(DD / 128, MROWS / 128, 3), 256, GEMM_SMEM>>>(
        xah, xbh, wt, qh, kh, vh);

    // flash writes attn output hi into xah (Q-GEMM already consumed it)
    flash_mma_kernel<<<dim3(TT / 128, BB * HH), 256, FLASH_SMEM>>>(
        qh, kh, vh, xah);

    wo_mma_kernel<<<dim3(DD / 128, MROWS / 128), 256, GEMM_SMEM>>>(
        xah, wt + (size_t)3 * DD * DD, out);
}